// round 1
// baseline (speedup 1.0000x reference)
#include <cuda_runtime.h>
#include <math.h>

// Problem constants (shapes fixed by setup_inputs)
#define NNZ   4096     // B*S tokens
#define HIDN  4096
#define NHEAD 32
#define NKVH  8
#define HDIM  128
#define SEQ   1024
#define NBATCH 4
#define QKVC  6144     // 4096 (Q) + 1024 (K) + 1024 (V)
#define KOFF  4096
#define VOFF  5120

// Scratch (device globals — no allocation allowed)
__device__ float g_qkv[(size_t)NNZ * QKVC];   // ~100 MB
__device__ float g_attn[(size_t)NNZ * HIDN];  // ~64 MB

// ---------------------------------------------------------------------------
// SGEMM: C[i,j] = sum_k A[i,k] * B[j,k]   (A row-major [M,K], B row-major [N,K])
// 128x128 tile, BK=8, 256 threads, 8x8 per-thread micro-tile.
// M, N multiples of 128; K multiple of 8. Grid: (N/128, M/128).
// ---------------------------------------------------------------------------
__global__ void __launch_bounds__(256) sgemm_abt(
    const float* __restrict__ A, const float* __restrict__ B,
    float* __restrict__ C, int K, int ldc)
{
    __shared__ float As[8][128];
    __shared__ float Bs[8][128];
    const int bm = blockIdx.y * 128;
    const int bn = blockIdx.x * 128;
    const int tid = threadIdx.x;
    const int tx = tid & 15;         // 0..15 -> 8 output cols each
    const int ty = tid >> 4;         // 0..15 -> 8 output rows each
    const int lrow = tid >> 1;       // 0..127
    const int lcol = (tid & 1) * 4;  // 0 or 4

    const float* Ap = A + (size_t)(bm + lrow) * K + lcol;
    const float* Bp = B + (size_t)(bn + lrow) * K + lcol;

    float acc[8][8];
#pragma unroll
    for (int i = 0; i < 8; i++)
#pragma unroll
        for (int j = 0; j < 8; j++) acc[i][j] = 0.0f;

    for (int k0 = 0; k0 < K; k0 += 8) {
        float4 a4 = *(const float4*)(Ap + k0);
        float4 b4 = *(const float4*)(Bp + k0);
        As[lcol + 0][lrow] = a4.x; As[lcol + 1][lrow] = a4.y;
        As[lcol + 2][lrow] = a4.z; As[lcol + 3][lrow] = a4.w;
        Bs[lcol + 0][lrow] = b4.x; Bs[lcol + 1][lrow] = b4.y;
        Bs[lcol + 2][lrow] = b4.z; Bs[lcol + 3][lrow] = b4.w;
        __syncthreads();
#pragma unroll
        for (int k = 0; k < 8; k++) {
            float ra[8], rb[8];
#pragma unroll
            for (int i = 0; i < 8; i++) ra[i] = As[k][ty * 8 + i];
#pragma unroll
            for (int j = 0; j < 8; j++) rb[j] = Bs[k][tx * 8 + j];
#pragma unroll
            for (int i = 0; i < 8; i++)
#pragma unroll
                for (int j = 0; j < 8; j++) acc[i][j] += ra[i] * rb[j];
        }
        __syncthreads();
    }

#pragma unroll
    for (int i = 0; i < 8; i++) {
        float* crow = C + (size_t)(bm + ty * 8 + i) * ldc + bn + tx * 8;
#pragma unroll
        for (int j = 0; j < 8; j += 4) {
            float4 v = make_float4(acc[i][j], acc[i][j + 1], acc[i][j + 2], acc[i][j + 3]);
            *(float4*)(crow + j) = v;
        }
    }
}

// ---------------------------------------------------------------------------
// Llama-3.1 RoPE, in-place on Q heads (cols 0..4095) and K heads (4096..5119).
// Grid: (NNZ, 40), block 64. Head h: Q heads 0..31, K heads 32..39;
// column base = h*128 works for both since 32*128 == KOFF.
// ---------------------------------------------------------------------------
__global__ void rope_kernel(float* __restrict__ qkv, const int* __restrict__ pos)
{
    const int tok = blockIdx.x;
    const int h   = blockIdx.y;     // 0..39
    const int d   = threadIdx.x;    // 0..63

    float* base = qkv + (size_t)tok * QKVC + h * HDIM;
    const int p = pos[tok];

    // freq = theta^(-2d/128), theta = 5e5
    float freq = powf(500000.0f, -(float)d / 64.0f);
    const float wl = 6.283185307179586f / freq;
    float f;
    if (wl < 2048.0f) {
        f = freq;                   // wavelen < high_wl
    } else if (wl > 8192.0f) {
        f = freq * 0.125f;          // wavelen > low_wl -> freq/scale
    } else {
        float smooth = (8192.0f / wl - 1.0f) * (1.0f / 3.0f);
        f = (1.0f - smooth) * freq * 0.125f + smooth * freq;
    }
    const float ang = (float)p * f;
    const float c = cosf(ang), s = sinf(ang);
    const float x1 = base[d], x2 = base[d + 64];
    base[d]      = x1 * c - x2 * s;
    base[d + 64] = x2 * c + x1 * s;
}

// ---------------------------------------------------------------------------
// Flash attention (causal, GQA g=4). One block per (q-tile of 64, head, batch).
// 256 threads. fp32 throughout. Online softmax state held in registers
// (replicated across the 16 threads of each row group -> no shared races).
//
// Shared (dynamic, 120832 B):
//   Qts[128][68]  transposed Q tile (d-major), pre-scaled by 1/sqrt(128)
//   Kts[128][68]  transposed K tile (d-major)
//   Vs [64][132]  V tile row-major (key-major)
//   Ps [64][68]   probability tile
// ---------------------------------------------------------------------------
#define ATT_SMEM_FLOATS (128*68 + 128*68 + 64*132 + 64*68)
#define ATT_SMEM_BYTES  (ATT_SMEM_FLOATS * 4)

__global__ void __launch_bounds__(256) attn_kernel(
    const float* __restrict__ qkv, float* __restrict__ out)
{
    extern __shared__ float sh[];
    float* Qts = sh;                    // 128*68
    float* Kts = Qts + 128 * 68;        // 128*68
    float* Vs  = Kts + 128 * 68;        // 64*132
    float* Ps  = Vs + 64 * 132;         // 64*68

    const int qt  = blockIdx.x;         // 0..15
    const int h   = blockIdx.y;         // 0..31
    const int b   = blockIdx.z;         // 0..3
    const int kvh = h >> 2;
    const int tid = threadIdx.x;
    const int tx  = tid & 15;           // score col group / O col group
    const int ty  = tid >> 4;           // row group (4 rows)
    const int lane = tid & 31;
    const int qr0 = qt * 64;

    // --- load Q tile transposed, pre-scaled ---
    {
        const int lr = tid >> 5;        // 0..7
        const int lc = lane * 4;        // 0..124
        const float scale = 0.08838834764831845f; // 1/sqrt(128)
        for (int r = lr; r < 64; r += 8) {
            float4 v = *(const float4*)(qkv + (size_t)(b * SEQ + qr0 + r) * QKVC + h * HDIM + lc);
            Qts[(lc + 0) * 68 + r] = v.x * scale;
            Qts[(lc + 1) * 68 + r] = v.y * scale;
            Qts[(lc + 2) * 68 + r] = v.z * scale;
            Qts[(lc + 3) * 68 + r] = v.w * scale;
        }
    }

    float m_i[4], l_i[4];
    float acc[4][2][4];                 // [row i][half jj][u]; cols = tx*4+u + 64*jj
#pragma unroll
    for (int i = 0; i < 4; i++) {
        m_i[i] = -1e30f;
        l_i[i] = 0.0f;
#pragma unroll
        for (int jj = 0; jj < 2; jj++)
#pragma unroll
            for (int u = 0; u < 4; u++) acc[i][jj][u] = 0.0f;
    }

    for (int kt = 0; kt <= qt; kt++) {
        __syncthreads();  // prior tile's Kts/Vs/Ps consumption complete

        // --- load K (transposed) and V (row-major) tiles ---
        {
            const int lr = tid >> 5;
            const int lc = lane * 4;
            const int kr0 = kt * 64;
            for (int r = lr; r < 64; r += 8) {
                const size_t krow = (size_t)(b * SEQ + kr0 + r) * QKVC;
                float4 kv = *(const float4*)(qkv + krow + KOFF + kvh * HDIM + lc);
                Kts[(lc + 0) * 68 + r] = kv.x;
                Kts[(lc + 1) * 68 + r] = kv.y;
                Kts[(lc + 2) * 68 + r] = kv.z;
                Kts[(lc + 3) * 68 + r] = kv.w;
                float4 vv = *(const float4*)(qkv + krow + VOFF + kvh * HDIM + lc);
                *(float4*)&Vs[r * 132 + lc] = vv;
            }
        }
        __syncthreads();

        // --- scores: rows ty*4+i, cols tx*4+j, reduce over d=0..127 ---
        float sc[4][4];
#pragma unroll
        for (int i = 0; i < 4; i++)
#pragma unroll
            for (int j = 0; j < 4; j++) sc[i][j] = 0.0f;

#pragma unroll 4
        for (int d = 0; d < 128; d++) {
            float4 ra = *(const float4*)&Qts[d * 68 + ty * 4];
            float4 rb = *(const float4*)&Kts[d * 68 + tx * 4];
            const float raa[4] = {ra.x, ra.y, ra.z, ra.w};
            const float rbb[4] = {rb.x, rb.y, rb.z, rb.w};
#pragma unroll
            for (int i = 0; i < 4; i++)
#pragma unroll
                for (int j = 0; j < 4; j++) sc[i][j] += raa[i] * rbb[j];
        }

        // --- causal mask (only diagonal tile) ---
        if (kt == qt) {
#pragma unroll
            for (int i = 0; i < 4; i++)
#pragma unroll
                for (int j = 0; j < 4; j++)
                    if (tx * 4 + j > ty * 4 + i) sc[i][j] = -1e30f;
        }

        // --- online softmax: row max/sum reduced over the 16-thread row group ---
        float rmax[4], fac[4], rsum[4];
#pragma unroll
        for (int i = 0; i < 4; i++) {
            float m = sc[i][0];
            m = fmaxf(m, sc[i][1]); m = fmaxf(m, sc[i][2]); m = fmaxf(m, sc[i][3]);
            rmax[i] = m;
        }
#pragma unroll
        for (int off = 8; off >= 1; off >>= 1)
#pragma unroll
            for (int i = 0; i < 4; i++)
                rmax[i] = fmaxf(rmax[i], __shfl_xor_sync(0xffffffffu, rmax[i], off));

#pragma unroll
        for (int i = 0; i < 4; i++) {
            float mnew = fmaxf(m_i[i], rmax[i]);
            fac[i] = expf(m_i[i] - mnew);
            m_i[i] = mnew;
            rsum[i] = 0.0f;
        }

#pragma unroll
        for (int i = 0; i < 4; i++) {
#pragma unroll
            for (int j = 0; j < 4; j++) {
                float p = expf(sc[i][j] - m_i[i]);
                Ps[(ty * 4 + i) * 68 + tx * 4 + j] = p;
                rsum[i] += p;
            }
        }
#pragma unroll
        for (int off = 8; off >= 1; off >>= 1)
#pragma unroll
            for (int i = 0; i < 4; i++)
                rsum[i] += __shfl_xor_sync(0xffffffffu, rsum[i], off);

#pragma unroll
        for (int i = 0; i < 4; i++) {
            l_i[i] = l_i[i] * fac[i] + rsum[i];
#pragma unroll
            for (int jj = 0; jj < 2; jj++)
#pragma unroll
                for (int u = 0; u < 4; u++) acc[i][jj][u] *= fac[i];
        }

        __syncthreads();  // Ps visible to all

        // --- O += P @ V : rows ty*4+i, cols tx*4+u (+64) ---
        for (int c0 = 0; c0 < 64; c0 += 4) {
            float pr[4][4];
#pragma unroll
            for (int i = 0; i < 4; i++) {
                float4 p4 = *(const float4*)&Ps[(ty * 4 + i) * 68 + c0];
                pr[i][0] = p4.x; pr[i][1] = p4.y; pr[i][2] = p4.z; pr[i][3] = p4.w;
            }
#pragma unroll
            for (int cc = 0; cc < 4; cc++) {
                float4 v0 = *(const float4*)&Vs[(c0 + cc) * 132 + tx * 4];
                float4 v1 = *(const float4*)&Vs[(c0 + cc) * 132 + 64 + tx * 4];
                const float v0a[4] = {v0.x, v0.y, v0.z, v0.w};
                const float v1a[4] = {v1.x, v1.y, v1.z, v1.w};
#pragma unroll
                for (int i = 0; i < 4; i++) {
                    const float p = pr[i][cc];
#pragma unroll
                    for (int u = 0; u < 4; u++) {
                        acc[i][0][u] += p * v0a[u];
                        acc[i][1][u] += p * v1a[u];
                    }
                }
            }
        }
    }

    // --- normalize and write out ---
#pragma unroll
    for (int i = 0; i < 4; i++) {
        const float inv = 1.0f / l_i[i];
        const int row = b * SEQ + qr0 + ty * 4 + i;
        float* orow = out + (size_t)row * HIDN + h * HDIM;
        float4 o0 = make_float4(acc[i][0][0] * inv, acc[i][0][1] * inv,
                                acc[i][0][2] * inv, acc[i][0][3] * inv);
        float4 o1 = make_float4(acc[i][1][0] * inv, acc[i][1][1] * inv,
                                acc[i][1][2] * inv, acc[i][1][3] * inv);
        *(float4*)(orow + tx * 4) = o0;
        *(float4*)(orow + 64 + tx * 4) = o1;
    }
}

// ---------------------------------------------------------------------------
// Launch: QKV GEMMs -> RoPE -> flash attention -> output GEMM
// ---------------------------------------------------------------------------
extern "C" void kernel_launch(void* const* d_in, const int* in_sizes, int n_in,
                              void* d_out, int out_size)
{
    const float* hidden = (const float*)d_in[0];
    const float* wq     = (const float*)d_in[1];
    const float* wk     = (const float*)d_in[2];
    const float* wv     = (const float*)d_in[3];
    const float* wo     = (const float*)d_in[4];
    const int*   pos    = (const int*)d_in[6];
    float*       outp   = (float*)d_out;

    float* qkv;  cudaGetSymbolAddress((void**)&qkv,  g_qkv);
    float* attn; cudaGetSymbolAddress((void**)&attn, g_attn);

    cudaFuncSetAttribute(attn_kernel, cudaFuncAttributeMaxDynamicSharedMemorySize,
                         ATT_SMEM_BYTES);

    // Q/K/V projections: out = hidden @ W^T
    sgemm_abt<<<dim3(32, 32), 256>>>(hidden, wq, qkv,        HIDN, QKVC);
    sgemm_abt<<<dim3(8,  32), 256>>>(hidden, wk, qkv + KOFF, HIDN, QKVC);
    sgemm_abt<<<dim3(8,  32), 256>>>(hidden, wv, qkv + VOFF, HIDN, QKVC);

    // RoPE on Q + K heads
    rope_kernel<<<dim3(NNZ, NHEAD + NKVH), 64>>>(qkv, pos);

    // Causal GQA flash attention
    attn_kernel<<<dim3(16, NHEAD, NBATCH), 256, ATT_SMEM_BYTES>>>(qkv, attn);

    // Output projection: d_out = attn @ wo^T
    sgemm_abt<<<dim3(32, 32), 256>>>(attn, wo, outp, HIDN, HIDN);
}

// round 2
// speedup vs baseline: 2.2283x; 2.2283x over previous
#include <cuda_runtime.h>
#include <cuda_bf16.h>
#include <math.h>

// Problem constants (shapes fixed by setup_inputs)
#define NNZ   4096     // B*S tokens
#define HIDN  4096
#define NHEAD 32
#define NKVH  8
#define HDIM  128
#define SEQ   1024
#define NBATCH 4
#define QKVC  6144     // 4096 (Q) + 1024 (K) + 1024 (V)
#define KOFF  4096
#define VOFF  5120

// Scratch (device globals — no allocation allowed)
__device__ float g_qkv[(size_t)NNZ * QKVC];   // ~100 MB
__device__ float g_attn[(size_t)NNZ * HIDN];  // ~64 MB

// ---------------------------------------------------------------------------
// bf16-split tensor-core GEMM: C[i,j] = sum_k A[i,k]*B[j,k]
//   A row-major [M,K] fp32, B row-major [N,K] fp32, C row-major [M,ldc] fp32.
// Each fp32 x is split: hi=bf16(x), lo=bf16(x-hi); product approximated by
// hi*hi + hi*lo + lo*hi accumulated in fp32 (error ~2^-18 per term).
// Block: 128x128 tile, BK=32, 512 threads = 16 warps (4x4), warp tile 32x32.
// Grid: (N/128, M/128). M,N multiples of 128; K multiple of 32.
// ---------------------------------------------------------------------------
#define BK 32
#define SM_STRIDE 40   // bf16 elements per row (32 + 8 pad) -> conflict-free ldmatrix

__device__ __forceinline__ void ldsm_x4(unsigned* r, unsigned addr) {
    asm volatile("ldmatrix.sync.aligned.m8n8.x4.shared.b16 {%0,%1,%2,%3}, [%4];\n"
                 : "=r"(r[0]), "=r"(r[1]), "=r"(r[2]), "=r"(r[3])
                 : "r"(addr));
}

__device__ __forceinline__ void mma_bf16(float* c, const unsigned* a, const unsigned* b) {
    asm volatile(
        "mma.sync.aligned.m16n8k16.row.col.f32.bf16.bf16.f32 "
        "{%0,%1,%2,%3}, {%4,%5,%6,%7}, {%8,%9}, {%0,%1,%2,%3};\n"
        : "+f"(c[0]), "+f"(c[1]), "+f"(c[2]), "+f"(c[3])
        : "r"(a[0]), "r"(a[1]), "r"(a[2]), "r"(a[3]), "r"(b[0]), "r"(b[1]));
}

__device__ __forceinline__ unsigned pk(__nv_bfloat16 a, __nv_bfloat16 b) {
    __nv_bfloat162 t(a, b);
    return *reinterpret_cast<unsigned*>(&t);
}

// Split a float4 and store hi/lo bf16 quads (8B each) at smem byte addrs.
__device__ __forceinline__ void split_store(__nv_bfloat16* hiP, __nv_bfloat16* loP, float4 v) {
    __nv_bfloat16 h0 = __float2bfloat16(v.x);
    __nv_bfloat16 h1 = __float2bfloat16(v.y);
    __nv_bfloat16 h2 = __float2bfloat16(v.z);
    __nv_bfloat16 h3 = __float2bfloat16(v.w);
    __nv_bfloat16 l0 = __float2bfloat16(v.x - __bfloat162float(h0));
    __nv_bfloat16 l1 = __float2bfloat16(v.y - __bfloat162float(h1));
    __nv_bfloat16 l2 = __float2bfloat16(v.z - __bfloat162float(h2));
    __nv_bfloat16 l3 = __float2bfloat16(v.w - __bfloat162float(h3));
    *reinterpret_cast<uint2*>(hiP) = make_uint2(pk(h0, h1), pk(h2, h3));
    *reinterpret_cast<uint2*>(loP) = make_uint2(pk(l0, l1), pk(l2, l3));
}

__global__ void __launch_bounds__(512) gemm_bf16x3(
    const float* __restrict__ A, const float* __restrict__ B,
    float* __restrict__ C, int K, int ldc)
{
    __shared__ __nv_bfloat16 smAhi[128 * SM_STRIDE];
    __shared__ __nv_bfloat16 smAlo[128 * SM_STRIDE];
    __shared__ __nv_bfloat16 smBhi[128 * SM_STRIDE];
    __shared__ __nv_bfloat16 smBlo[128 * SM_STRIDE];

    const int bm = blockIdx.y * 128;
    const int bn = blockIdx.x * 128;
    const int t  = threadIdx.x;
    const int lane = t & 31;
    const int warp = t >> 5;
    const int wm = (warp & 3) * 32;   // warp m-offset in tile
    const int wn = (warp >> 2) * 32;  // warp n-offset in tile

    // global load mapping: 128x32 fp32 tile / 512 threads = 2 float4 each
    const int ldRow = t >> 3;          // 0..63
    const int ldCol = (t & 7) * 4;     // 0..28
    const float* Ag = A + (size_t)(bm + ldRow) * K + ldCol;
    const float* Bg = B + (size_t)(bn + ldRow) * K + ldCol;

    // ldmatrix lane geometry
    const int mat = lane >> 3;
    const int aRow = wm + (lane & 7) + (mat & 1) * 8;
    const int aColAdd = (mat >> 1) * 8;
    const int bRow = wn + (lane & 7) + (mat >> 1) * 8;
    const int bColAdd = (mat & 1) * 8;

    const unsigned baseAhi = (unsigned)__cvta_generic_to_shared(smAhi);
    const unsigned baseAlo = (unsigned)__cvta_generic_to_shared(smAlo);
    const unsigned baseBhi = (unsigned)__cvta_generic_to_shared(smBhi);
    const unsigned baseBlo = (unsigned)__cvta_generic_to_shared(smBlo);

    float acc[2][4][4];
#pragma unroll
    for (int mi = 0; mi < 2; mi++)
#pragma unroll
        for (int nj = 0; nj < 4; nj++)
#pragma unroll
            for (int u = 0; u < 4; u++) acc[mi][nj][u] = 0.0f;

    // preload first tile
    float4 nA0 = *(const float4*)(Ag);
    float4 nA1 = *(const float4*)(Ag + 64 * (size_t)K);
    float4 nB0 = *(const float4*)(Bg);
    float4 nB1 = *(const float4*)(Bg + 64 * (size_t)K);
    {
        int i0 = ldRow * SM_STRIDE + ldCol;
        int i1 = (ldRow + 64) * SM_STRIDE + ldCol;
        split_store(&smAhi[i0], &smAlo[i0], nA0);
        split_store(&smAhi[i1], &smAlo[i1], nA1);
        split_store(&smBhi[i0], &smBlo[i0], nB0);
        split_store(&smBhi[i1], &smBlo[i1], nB1);
    }
    __syncthreads();

    for (int k0 = 0; k0 < K; k0 += BK) {
        const bool hasNext = (k0 + BK) < K;
        if (hasNext) {
            const int kn = k0 + BK;
            nA0 = *(const float4*)(Ag + kn);
            nA1 = *(const float4*)(Ag + 64 * (size_t)K + kn);
            nB0 = *(const float4*)(Bg + kn);
            nB1 = *(const float4*)(Bg + 64 * (size_t)K + kn);
        }

#pragma unroll
        for (int kk = 0; kk < BK; kk += 16) {
            unsigned ahi[2][4], alo[2][4], bhi[8], blo[8];
#pragma unroll
            for (int mi = 0; mi < 2; mi++) {
                unsigned off = (unsigned)((aRow + mi * 16) * SM_STRIDE + kk + aColAdd) * 2u;
                ldsm_x4(ahi[mi], baseAhi + off);
                ldsm_x4(alo[mi], baseAlo + off);
            }
#pragma unroll
            for (int p = 0; p < 2; p++) {
                unsigned off = (unsigned)((bRow + p * 16) * SM_STRIDE + kk + bColAdd) * 2u;
                ldsm_x4(&bhi[p * 4], baseBhi + off);
                ldsm_x4(&blo[p * 4], baseBlo + off);
            }
#pragma unroll
            for (int mi = 0; mi < 2; mi++)
#pragma unroll
                for (int nj = 0; nj < 4; nj++) {
                    const unsigned* bh = &bhi[(nj >> 1) * 4 + (nj & 1) * 2];
                    const unsigned* bl = &blo[(nj >> 1) * 4 + (nj & 1) * 2];
                    mma_bf16(acc[mi][nj], ahi[mi], bh);
                    mma_bf16(acc[mi][nj], ahi[mi], bl);
                    mma_bf16(acc[mi][nj], alo[mi], bh);
                }
        }
        __syncthreads();
        if (hasNext) {
            int i0 = ldRow * SM_STRIDE + ldCol;
            int i1 = (ldRow + 64) * SM_STRIDE + ldCol;
            split_store(&smAhi[i0], &smAlo[i0], nA0);
            split_store(&smAhi[i1], &smAlo[i1], nA1);
            split_store(&smBhi[i0], &smBlo[i0], nB0);
            split_store(&smBhi[i1], &smBlo[i1], nB1);
            __syncthreads();
        }
    }

    // epilogue: mma C layout -> global
    const int g = lane >> 2;
    const int tq = lane & 3;
#pragma unroll
    for (int mi = 0; mi < 2; mi++) {
        const int row0 = bm + wm + mi * 16 + g;
#pragma unroll
        for (int nj = 0; nj < 4; nj++) {
            const int col = bn + wn + nj * 8 + tq * 2;
            *(float2*)(C + (size_t)row0 * ldc + col) =
                make_float2(acc[mi][nj][0], acc[mi][nj][1]);
            *(float2*)(C + (size_t)(row0 + 8) * ldc + col) =
                make_float2(acc[mi][nj][2], acc[mi][nj][3]);
        }
    }
}

// ---------------------------------------------------------------------------
// Llama-3.1 RoPE, in-place on Q heads (cols 0..4095) and K heads (4096..5119).
// ---------------------------------------------------------------------------
__global__ void rope_kernel(float* __restrict__ qkv, const int* __restrict__ pos)
{
    const int tok = blockIdx.x;
    const int h   = blockIdx.y;     // 0..39
    const int d   = threadIdx.x;    // 0..63

    float* base = qkv + (size_t)tok * QKVC + h * HDIM;
    const int p = pos[tok];

    float freq = powf(500000.0f, -(float)d / 64.0f);
    const float wl = 6.283185307179586f / freq;
    float f;
    if (wl < 2048.0f) {
        f = freq;
    } else if (wl > 8192.0f) {
        f = freq * 0.125f;
    } else {
        float smooth = (8192.0f / wl - 1.0f) * (1.0f / 3.0f);
        f = (1.0f - smooth) * freq * 0.125f + smooth * freq;
    }
    const float ang = (float)p * f;
    const float c = cosf(ang), s = sinf(ang);
    const float x1 = base[d], x2 = base[d + 64];
    base[d]      = x1 * c - x2 * s;
    base[d + 64] = x2 * c + x1 * s;
}

// ---------------------------------------------------------------------------
// Flash attention (causal, GQA g=4), fp32. Unchanged from round 1 (correct).
// ---------------------------------------------------------------------------
#define ATT_SMEM_FLOATS (128*68 + 128*68 + 64*132 + 64*68)
#define ATT_SMEM_BYTES  (ATT_SMEM_FLOATS * 4)

__global__ void __launch_bounds__(256) attn_kernel(
    const float* __restrict__ qkv, float* __restrict__ out)
{
    extern __shared__ float sh[];
    float* Qts = sh;
    float* Kts = Qts + 128 * 68;
    float* Vs  = Kts + 128 * 68;
    float* Ps  = Vs + 64 * 132;

    const int qt  = blockIdx.x;
    const int h   = blockIdx.y;
    const int b   = blockIdx.z;
    const int kvh = h >> 2;
    const int tid = threadIdx.x;
    const int tx  = tid & 15;
    const int ty  = tid >> 4;
    const int lane = tid & 31;
    const int qr0 = qt * 64;

    {
        const int lr = tid >> 5;
        const int lc = lane * 4;
        const float scale = 0.08838834764831845f;
        for (int r = lr; r < 64; r += 8) {
            float4 v = *(const float4*)(qkv + (size_t)(b * SEQ + qr0 + r) * QKVC + h * HDIM + lc);
            Qts[(lc + 0) * 68 + r] = v.x * scale;
            Qts[(lc + 1) * 68 + r] = v.y * scale;
            Qts[(lc + 2) * 68 + r] = v.z * scale;
            Qts[(lc + 3) * 68 + r] = v.w * scale;
        }
    }

    float m_i[4], l_i[4];
    float acc[4][2][4];
#pragma unroll
    for (int i = 0; i < 4; i++) {
        m_i[i] = -1e30f;
        l_i[i] = 0.0f;
#pragma unroll
        for (int jj = 0; jj < 2; jj++)
#pragma unroll
            for (int u = 0; u < 4; u++) acc[i][jj][u] = 0.0f;
    }

    for (int kt = 0; kt <= qt; kt++) {
        __syncthreads();

        {
            const int lr = tid >> 5;
            const int lc = lane * 4;
            const int kr0 = kt * 64;
            for (int r = lr; r < 64; r += 8) {
                const size_t krow = (size_t)(b * SEQ + kr0 + r) * QKVC;
                float4 kv = *(const float4*)(qkv + krow + KOFF + kvh * HDIM + lc);
                Kts[(lc + 0) * 68 + r] = kv.x;
                Kts[(lc + 1) * 68 + r] = kv.y;
                Kts[(lc + 2) * 68 + r] = kv.z;
                Kts[(lc + 3) * 68 + r] = kv.w;
                float4 vv = *(const float4*)(qkv + krow + VOFF + kvh * HDIM + lc);
                *(float4*)&Vs[r * 132 + lc] = vv;
            }
        }
        __syncthreads();

        float sc[4][4];
#pragma unroll
        for (int i = 0; i < 4; i++)
#pragma unroll
            for (int j = 0; j < 4; j++) sc[i][j] = 0.0f;

#pragma unroll 4
        for (int d = 0; d < 128; d++) {
            float4 ra = *(const float4*)&Qts[d * 68 + ty * 4];
            float4 rb = *(const float4*)&Kts[d * 68 + tx * 4];
            const float raa[4] = {ra.x, ra.y, ra.z, ra.w};
            const float rbb[4] = {rb.x, rb.y, rb.z, rb.w};
#pragma unroll
            for (int i = 0; i < 4; i++)
#pragma unroll
                for (int j = 0; j < 4; j++) sc[i][j] += raa[i] * rbb[j];
        }

        if (kt == qt) {
#pragma unroll
            for (int i = 0; i < 4; i++)
#pragma unroll
                for (int j = 0; j < 4; j++)
                    if (tx * 4 + j > ty * 4 + i) sc[i][j] = -1e30f;
        }

        float rmax[4], fac[4], rsum[4];
#pragma unroll
        for (int i = 0; i < 4; i++) {
            float m = sc[i][0];
            m = fmaxf(m, sc[i][1]); m = fmaxf(m, sc[i][2]); m = fmaxf(m, sc[i][3]);
            rmax[i] = m;
        }
#pragma unroll
        for (int off = 8; off >= 1; off >>= 1)
#pragma unroll
            for (int i = 0; i < 4; i++)
                rmax[i] = fmaxf(rmax[i], __shfl_xor_sync(0xffffffffu, rmax[i], off));

#pragma unroll
        for (int i = 0; i < 4; i++) {
            float mnew = fmaxf(m_i[i], rmax[i]);
            fac[i] = expf(m_i[i] - mnew);
            m_i[i] = mnew;
            rsum[i] = 0.0f;
        }

#pragma unroll
        for (int i = 0; i < 4; i++) {
#pragma unroll
            for (int j = 0; j < 4; j++) {
                float p = expf(sc[i][j] - m_i[i]);
                Ps[(ty * 4 + i) * 68 + tx * 4 + j] = p;
                rsum[i] += p;
            }
        }
#pragma unroll
        for (int off = 8; off >= 1; off >>= 1)
#pragma unroll
            for (int i = 0; i < 4; i++)
                rsum[i] += __shfl_xor_sync(0xffffffffu, rsum[i], off);

#pragma unroll
        for (int i = 0; i < 4; i++) {
            l_i[i] = l_i[i] * fac[i] + rsum[i];
#pragma unroll
            for (int jj = 0; jj < 2; jj++)
#pragma unroll
                for (int u = 0; u < 4; u++) acc[i][jj][u] *= fac[i];
        }

        __syncthreads();

        for (int c0 = 0; c0 < 64; c0 += 4) {
            float pr[4][4];
#pragma unroll
            for (int i = 0; i < 4; i++) {
                float4 p4 = *(const float4*)&Ps[(ty * 4 + i) * 68 + c0];
                pr[i][0] = p4.x; pr[i][1] = p4.y; pr[i][2] = p4.z; pr[i][3] = p4.w;
            }
#pragma unroll
            for (int cc = 0; cc < 4; cc++) {
                float4 v0 = *(const float4*)&Vs[(c0 + cc) * 132 + tx * 4];
                float4 v1 = *(const float4*)&Vs[(c0 + cc) * 132 + 64 + tx * 4];
                const float v0a[4] = {v0.x, v0.y, v0.z, v0.w};
                const float v1a[4] = {v1.x, v1.y, v1.z, v1.w};
#pragma unroll
                for (int i = 0; i < 4; i++) {
                    const float p = pr[i][cc];
#pragma unroll
                    for (int u = 0; u < 4; u++) {
                        acc[i][0][u] += p * v0a[u];
                        acc[i][1][u] += p * v1a[u];
                    }
                }
            }
        }
    }

#pragma unroll
    for (int i = 0; i < 4; i++) {
        const float inv = 1.0f / l_i[i];
        const int row = b * SEQ + qr0 + ty * 4 + i;
        float* orow = out + (size_t)row * HIDN + h * HDIM;
        float4 o0 = make_float4(acc[i][0][0] * inv, acc[i][0][1] * inv,
                                acc[i][0][2] * inv, acc[i][0][3] * inv);
        float4 o1 = make_float4(acc[i][1][0] * inv, acc[i][1][1] * inv,
                                acc[i][1][2] * inv, acc[i][1][3] * inv);
        *(float4*)(orow + tx * 4) = o0;
        *(float4*)(orow + 64 + tx * 4) = o1;
    }
}

// ---------------------------------------------------------------------------
// Launch: QKV GEMMs (tensor-core bf16x3) -> RoPE -> flash attention -> WO GEMM
// ---------------------------------------------------------------------------
extern "C" void kernel_launch(void* const* d_in, const int* in_sizes, int n_in,
                              void* d_out, int out_size)
{
    const float* hidden = (const float*)d_in[0];
    const float* wq     = (const float*)d_in[1];
    const float* wk     = (const float*)d_in[2];
    const float* wv     = (const float*)d_in[3];
    const float* wo     = (const float*)d_in[4];
    const int*   pos    = (const int*)d_in[6];
    float*       outp   = (float*)d_out;

    float* qkv;  cudaGetSymbolAddress((void**)&qkv,  g_qkv);
    float* attn; cudaGetSymbolAddress((void**)&attn, g_attn);

    cudaFuncSetAttribute(attn_kernel, cudaFuncAttributeMaxDynamicSharedMemorySize,
                         ATT_SMEM_BYTES);

    // Q/K/V projections: out = hidden @ W^T
    gemm_bf16x3<<<dim3(32, 32), 512>>>(hidden, wq, qkv,        HIDN, QKVC);
    gemm_bf16x3<<<dim3(8,  32), 512>>>(hidden, wk, qkv + KOFF, HIDN, QKVC);
    gemm_bf16x3<<<dim3(8,  32), 512>>>(hidden, wv, qkv + VOFF, HIDN, QKVC);

    // RoPE on Q + K heads
    rope_kernel<<<dim3(NNZ, NHEAD + NKVH), 64>>>(qkv, pos);

    // Causal GQA flash attention
    attn_kernel<<<dim3(16, NHEAD, NBATCH), 256, ATT_SMEM_BYTES>>>(qkv, attn);

    // Output projection: d_out = attn @ wo^T
    gemm_bf16x3<<<dim3(32, 32), 512>>>(attn, wo, outp, HIDN, HIDN);
}

// round 3
// speedup vs baseline: 2.7696x; 1.2429x over previous
#include <cuda_runtime.h>
#include <cuda_bf16.h>
#include <math.h>

#define NNZ   4096
#define HIDN  4096
#define NHEAD 32
#define NKVH  8
#define HDIM  128
#define SEQ   1024
#define NBATCH 4
#define QKVC  6144
#define KOFF  4096
#define VOFF  5120

// ---------------- persistent scratch ----------------
__device__ float g_qkv[(size_t)NNZ * QKVC];                 // fp32 QKV (pre-rope)
__device__ __nv_bfloat16 g_qkvh[(size_t)NNZ * QKVC];
__device__ __nv_bfloat16 g_qkvl[(size_t)NNZ * QKVC];
__device__ __nv_bfloat16 g_hidh[(size_t)NNZ * HIDN];
__device__ __nv_bfloat16 g_hidl[(size_t)NNZ * HIDN];
__device__ __nv_bfloat16 g_wqh[(size_t)HIDN * HIDN];
__device__ __nv_bfloat16 g_wql[(size_t)HIDN * HIDN];
__device__ __nv_bfloat16 g_wkh[(size_t)1024 * HIDN];
__device__ __nv_bfloat16 g_wkl[(size_t)1024 * HIDN];
__device__ __nv_bfloat16 g_wvh[(size_t)1024 * HIDN];
__device__ __nv_bfloat16 g_wvl[(size_t)1024 * HIDN];
__device__ __nv_bfloat16 g_woh[(size_t)HIDN * HIDN];
__device__ __nv_bfloat16 g_wol[(size_t)HIDN * HIDN];
__device__ __nv_bfloat16 g_ath[(size_t)NNZ * HIDN];
__device__ __nv_bfloat16 g_atl[(size_t)NNZ * HIDN];

// ---------------- primitives ----------------
__device__ __forceinline__ void ldsm_x4(unsigned* r, unsigned addr) {
    asm volatile("ldmatrix.sync.aligned.m8n8.x4.shared.b16 {%0,%1,%2,%3}, [%4];\n"
                 : "=r"(r[0]), "=r"(r[1]), "=r"(r[2]), "=r"(r[3]) : "r"(addr));
}
__device__ __forceinline__ void ldsm_x4_t(unsigned* r, unsigned addr) {
    asm volatile("ldmatrix.sync.aligned.m8n8.x4.trans.shared.b16 {%0,%1,%2,%3}, [%4];\n"
                 : "=r"(r[0]), "=r"(r[1]), "=r"(r[2]), "=r"(r[3]) : "r"(addr));
}
__device__ __forceinline__ void mma_bf16(float* c, const unsigned* a, const unsigned* b) {
    asm volatile(
        "mma.sync.aligned.m16n8k16.row.col.f32.bf16.bf16.f32 "
        "{%0,%1,%2,%3}, {%4,%5,%6,%7}, {%8,%9}, {%0,%1,%2,%3};\n"
        : "+f"(c[0]), "+f"(c[1]), "+f"(c[2]), "+f"(c[3])
        : "r"(a[0]), "r"(a[1]), "r"(a[2]), "r"(a[3]), "r"(b[0]), "r"(b[1]));
}
__device__ __forceinline__ unsigned pk(__nv_bfloat16 a, __nv_bfloat16 b) {
    __nv_bfloat162 t(a, b);
    return *reinterpret_cast<unsigned*>(&t);
}
__device__ __forceinline__ void cpa16(unsigned dst, const void* src) {
    asm volatile("cp.async.cg.shared.global [%0], [%1], 16;\n" :: "r"(dst), "l"(src));
}
__device__ __forceinline__ void cpa_commit() { asm volatile("cp.async.commit_group;\n"); }

// ---------------- split kernels ----------------
__global__ void split_kernel(const float* __restrict__ src,
                             __nv_bfloat16* __restrict__ hi,
                             __nv_bfloat16* __restrict__ lo, int n)
{
    int i = (blockIdx.x * blockDim.x + threadIdx.x) * 4;
    if (i >= n) return;
    float4 v = *(const float4*)(src + i);
    __nv_bfloat16 h0 = __float2bfloat16(v.x), h1 = __float2bfloat16(v.y);
    __nv_bfloat16 h2 = __float2bfloat16(v.z), h3 = __float2bfloat16(v.w);
    __nv_bfloat16 l0 = __float2bfloat16(v.x - __bfloat162float(h0));
    __nv_bfloat16 l1 = __float2bfloat16(v.y - __bfloat162float(h1));
    __nv_bfloat16 l2 = __float2bfloat16(v.z - __bfloat162float(h2));
    __nv_bfloat16 l3 = __float2bfloat16(v.w - __bfloat162float(h3));
    *(uint2*)(hi + i) = make_uint2(pk(h0, h1), pk(h2, h3));
    *(uint2*)(lo + i) = make_uint2(pk(l0, l1), pk(l2, l3));
}

// RoPE + split for qkv. grid (NNZ, 48), block 64.
// Heads 0..31: Q (rope + 1/sqrt(128) prescale). 32..39: K (rope). 40..47: V (copy).
__global__ void split_rope_kernel(const float* __restrict__ qkv,
                                  const int* __restrict__ pos,
                                  __nv_bfloat16* __restrict__ qh,
                                  __nv_bfloat16* __restrict__ ql)
{
    const int tok = blockIdx.x;
    const int hb  = blockIdx.y;
    const int d   = threadIdx.x;   // 0..63
    const size_t base = (size_t)tok * QKVC + hb * HDIM;
    float x1 = qkv[base + d], x2 = qkv[base + d + 64];

    if (hb < 40) {
        float freq = powf(500000.0f, -(float)d / 64.0f);
        const float wl = 6.283185307179586f / freq;
        float f;
        if (wl < 2048.0f)       f = freq;
        else if (wl > 8192.0f)  f = freq * 0.125f;
        else {
            float smooth = (8192.0f / wl - 1.0f) * (1.0f / 3.0f);
            f = (1.0f - smooth) * freq * 0.125f + smooth * freq;
        }
        const float ang = (float)pos[tok] * f;
        const float c = cosf(ang), s = sinf(ang);
        float y1 = x1 * c - x2 * s;
        float y2 = x2 * c + x1 * s;
        if (hb < 32) { y1 *= 0.08838834764831845f; y2 *= 0.08838834764831845f; }
        x1 = y1; x2 = y2;
    }
    __nv_bfloat16 h1 = __float2bfloat16(x1), h2 = __float2bfloat16(x2);
    qh[base + d]      = h1;
    qh[base + d + 64] = h2;
    ql[base + d]      = __float2bfloat16(x1 - __bfloat162float(h1));
    ql[base + d + 64] = __float2bfloat16(x2 - __bfloat162float(h2));
}

// ---------------------------------------------------------------------------
// Pre-split bf16x3 GEMM: C[i,j] = sum_k A[i,k]*B[j,k], operands bf16 hi/lo.
// 128x128 tile, BK=32, 512 threads, cp.async double-buffered.
// ---------------------------------------------------------------------------
#define GSTRIDE 40
#define G_ARR_BYTES (128 * GSTRIDE * 2)         // 10240
#define G_STAGE_BYTES (4 * G_ARR_BYTES)          // 40960
#define GEMM_SMEM (2 * G_STAGE_BYTES)            // 81920

__global__ void __launch_bounds__(512) gemm_pre(
    const __nv_bfloat16* __restrict__ Ahi, const __nv_bfloat16* __restrict__ Alo,
    const __nv_bfloat16* __restrict__ Bhi, const __nv_bfloat16* __restrict__ Blo,
    float* __restrict__ C, int K, int ldc)
{
    extern __shared__ __nv_bfloat16 dsm[];
    const unsigned smb = (unsigned)__cvta_generic_to_shared(dsm);

    const int bm = blockIdx.y * 128;
    const int bn = blockIdx.x * 128;
    const int t  = threadIdx.x;
    const int lane = t & 31;
    const int warp = t >> 5;
    const int wm = (warp & 3) * 32;
    const int wn = (warp >> 2) * 32;

    // loader: 128 rows x 4 chunks of 8 bf16 (16B) per array
    const int ldRow = t >> 2;
    const int ldCh  = (t & 3) * 8;
    const size_t aOff = (size_t)(bm + ldRow) * K + ldCh;
    const size_t bOff = (size_t)(bn + ldRow) * K + ldCh;
    const unsigned dOff = (unsigned)(ldRow * GSTRIDE + ldCh) * 2u;

    const int mat = lane >> 3;
    const int aRow = wm + (lane & 7) + (mat & 1) * 8;
    const int aColAdd = (mat >> 1) * 8;
    const int bRow = wn + (lane & 7) + (mat >> 1) * 8;
    const int bColAdd = (mat & 1) * 8;

    float acc[2][4][4];
#pragma unroll
    for (int mi = 0; mi < 2; mi++)
#pragma unroll
        for (int nj = 0; nj < 4; nj++)
#pragma unroll
            for (int u = 0; u < 4; u++) acc[mi][nj][u] = 0.0f;

    const int nt = K / 32;

    // prologue: stage 0
    {
        unsigned d0 = smb + dOff;
        cpa16(d0,                     Ahi + aOff);
        cpa16(d0 + G_ARR_BYTES,       Alo + aOff);
        cpa16(d0 + 2 * G_ARR_BYTES,   Bhi + bOff);
        cpa16(d0 + 3 * G_ARR_BYTES,   Blo + bOff);
        cpa_commit();
    }

    for (int i = 0; i < nt; i++) {
        if (i + 1 < nt) {
            unsigned d0 = smb + ((i + 1) & 1) * G_STAGE_BYTES + dOff;
            const int kn = (i + 1) * 32;
            cpa16(d0,                   Ahi + aOff + kn);
            cpa16(d0 + G_ARR_BYTES,     Alo + aOff + kn);
            cpa16(d0 + 2 * G_ARR_BYTES, Bhi + bOff + kn);
            cpa16(d0 + 3 * G_ARR_BYTES, Blo + bOff + kn);
            cpa_commit();
            asm volatile("cp.async.wait_group 1;\n");
        } else {
            asm volatile("cp.async.wait_group 0;\n");
        }
        __syncthreads();

        const unsigned st = smb + (i & 1) * G_STAGE_BYTES;
        const unsigned bAhi = st;
        const unsigned bAlo = st + G_ARR_BYTES;
        const unsigned bBhi = st + 2 * G_ARR_BYTES;
        const unsigned bBlo = st + 3 * G_ARR_BYTES;

#pragma unroll
        for (int kk = 0; kk < 32; kk += 16) {
            unsigned ahi[2][4], alo[2][4], bhi[8], blo[8];
#pragma unroll
            for (int mi = 0; mi < 2; mi++) {
                unsigned off = (unsigned)((aRow + mi * 16) * GSTRIDE + kk + aColAdd) * 2u;
                ldsm_x4(ahi[mi], bAhi + off);
                ldsm_x4(alo[mi], bAlo + off);
            }
#pragma unroll
            for (int p = 0; p < 2; p++) {
                unsigned off = (unsigned)((bRow + p * 16) * GSTRIDE + kk + bColAdd) * 2u;
                ldsm_x4(&bhi[p * 4], bBhi + off);
                ldsm_x4(&blo[p * 4], bBlo + off);
            }
#pragma unroll
            for (int mi = 0; mi < 2; mi++)
#pragma unroll
                for (int nj = 0; nj < 4; nj++) {
                    const unsigned* bh = &bhi[(nj >> 1) * 4 + (nj & 1) * 2];
                    const unsigned* bl = &blo[(nj >> 1) * 4 + (nj & 1) * 2];
                    mma_bf16(acc[mi][nj], ahi[mi], bh);
                    mma_bf16(acc[mi][nj], ahi[mi], bl);
                    mma_bf16(acc[mi][nj], alo[mi], bh);
                }
        }
        __syncthreads();
    }

    const int g = lane >> 2;
    const int tq = lane & 3;
#pragma unroll
    for (int mi = 0; mi < 2; mi++) {
        const int row0 = bm + wm + mi * 16 + g;
#pragma unroll
        for (int nj = 0; nj < 4; nj++) {
            const int col = bn + wn + nj * 8 + tq * 2;
            *(float2*)(C + (size_t)row0 * ldc + col) =
                make_float2(acc[mi][nj][0], acc[mi][nj][1]);
            *(float2*)(C + (size_t)(row0 + 8) * ldc + col) =
                make_float2(acc[mi][nj][2], acc[mi][nj][3]);
        }
    }
}

// ---------------------------------------------------------------------------
// Tensor-core flash attention (causal, GQA g=4), bf16x3 for QK and PV.
// Block: 128 threads (4 warps), tile 64 q-rows x 64 keys, HD=128.
// Warp w owns q rows [w*16, w*16+16). Smem: Q,K,V hi/lo tiles, stride 136.
// ---------------------------------------------------------------------------
#define ASD 136
#define A_ARR (64 * ASD)                    // elems per tile
#define ATT_SMEM (6 * A_ARR * 2)            // 104448 B

__global__ void __launch_bounds__(128) attn_tc(
    const __nv_bfloat16* __restrict__ qh, const __nv_bfloat16* __restrict__ ql,
    __nv_bfloat16* __restrict__ oh, __nv_bfloat16* __restrict__ ol)
{
    extern __shared__ __nv_bfloat16 sm[];
    const unsigned smb = (unsigned)__cvta_generic_to_shared(sm);
    const unsigned OQH = 0, OQL = A_ARR * 2, OKH = 2 * A_ARR * 2, OKL = 3 * A_ARR * 2,
                   OVH = 4 * A_ARR * 2, OVL = 5 * A_ARR * 2;

    const int qt  = (int)gridDim.x - 1 - (int)blockIdx.x;  // heavy tiles first
    const int h   = blockIdx.y;
    const int b   = blockIdx.z;
    const int kvh = h >> 2;
    const int tid = threadIdx.x;
    const int lane = tid & 31;
    const int warp = tid >> 5;
    const int qr0 = qt * 64;
    const int mat = lane >> 3;
    const int lm7 = lane & 7;
    const int g   = lane >> 2;
    const int tq  = lane & 3;

    // stage Q tile (64 x 128, hi+lo)
    for (int j = tid; j < 64 * 16; j += 128) {
        const int r = j >> 4, ch = (j & 15) * 8;
        const size_t gi = (size_t)(b * SEQ + qr0 + r) * QKVC + h * HDIM + ch;
        *(uint4*)&sm[r * ASD + ch]           = *(const uint4*)&qh[gi];
        *(uint4*)&sm[A_ARR + r * ASD + ch]   = *(const uint4*)&ql[gi];
    }

    float o[16][4];
#pragma unroll
    for (int nt = 0; nt < 16; nt++)
#pragma unroll
        for (int u = 0; u < 4; u++) o[nt][u] = 0.0f;
    float m0 = -1e30f, m1 = -1e30f, l0 = 0.0f, l1 = 0.0f;

    for (int kt = 0; kt <= qt; kt++) {
        __syncthreads();
        // stage K,V tiles
        for (int j = tid; j < 64 * 16; j += 128) {
            const int r = j >> 4, ch = (j & 15) * 8;
            const size_t tr = (size_t)(b * SEQ + kt * 64 + r) * QKVC;
            const size_t ki = tr + KOFF + kvh * HDIM + ch;
            const size_t vi = tr + VOFF + kvh * HDIM + ch;
            *(uint4*)&sm[2 * A_ARR + r * ASD + ch] = *(const uint4*)&qh[ki];
            *(uint4*)&sm[3 * A_ARR + r * ASD + ch] = *(const uint4*)&ql[ki];
            *(uint4*)&sm[4 * A_ARR + r * ASD + ch] = *(const uint4*)&qh[vi];
            *(uint4*)&sm[5 * A_ARR + r * ASD + ch] = *(const uint4*)&ql[vi];
        }
        __syncthreads();

        // ---- scores S = Q K^T ----
        float sc[8][4];
#pragma unroll
        for (int nj = 0; nj < 8; nj++)
#pragma unroll
            for (int u = 0; u < 4; u++) sc[nj][u] = 0.0f;

#pragma unroll
        for (int kk = 0; kk < 128; kk += 16) {
            unsigned ah4[4], al4[4], bh[16], bl[16];
            const unsigned aoff =
                (unsigned)((warp * 16 + lm7 + (mat & 1) * 8) * ASD + kk + (mat >> 1) * 8) * 2u;
            ldsm_x4(ah4, smb + OQH + aoff);
            ldsm_x4(al4, smb + OQL + aoff);
#pragma unroll
            for (int p = 0; p < 4; p++) {
                const unsigned boff =
                    (unsigned)((p * 16 + lm7 + (mat >> 1) * 8) * ASD + kk + (mat & 1) * 8) * 2u;
                ldsm_x4(&bh[p * 4], smb + OKH + boff);
                ldsm_x4(&bl[p * 4], smb + OKL + boff);
            }
#pragma unroll
            for (int nj = 0; nj < 8; nj++) {
                const unsigned* b1 = &bh[(nj >> 1) * 4 + (nj & 1) * 2];
                const unsigned* b2 = &bl[(nj >> 1) * 4 + (nj & 1) * 2];
                mma_bf16(sc[nj], ah4, b1);
                mma_bf16(sc[nj], ah4, b2);
                mma_bf16(sc[nj], al4, b1);
            }
        }

        // causal mask (diagonal tile only)
        if (kt == qt) {
            const int r0 = warp * 16 + g, r1 = r0 + 8;
#pragma unroll
            for (int nj = 0; nj < 8; nj++)
#pragma unroll
                for (int e = 0; e < 2; e++) {
                    const int cidx = nj * 8 + tq * 2 + e;
                    if (cidx > r0) sc[nj][e]     = -1e30f;
                    if (cidx > r1) sc[nj][2 + e] = -1e30f;
                }
        }

        // ---- online softmax ----
        float mx0 = -1e30f, mx1 = -1e30f;
#pragma unroll
        for (int nj = 0; nj < 8; nj++) {
            mx0 = fmaxf(mx0, fmaxf(sc[nj][0], sc[nj][1]));
            mx1 = fmaxf(mx1, fmaxf(sc[nj][2], sc[nj][3]));
        }
        mx0 = fmaxf(mx0, __shfl_xor_sync(0xffffffffu, mx0, 1));
        mx0 = fmaxf(mx0, __shfl_xor_sync(0xffffffffu, mx0, 2));
        mx1 = fmaxf(mx1, __shfl_xor_sync(0xffffffffu, mx1, 1));
        mx1 = fmaxf(mx1, __shfl_xor_sync(0xffffffffu, mx1, 2));

        const float mn0 = fmaxf(m0, mx0), mn1 = fmaxf(m1, mx1);
        const float f0 = __expf(m0 - mn0), f1 = __expf(m1 - mn1);
        m0 = mn0; m1 = mn1;

        float s0 = 0.0f, s1 = 0.0f;
        unsigned pah[4][4], pal[4][4];
#pragma unroll
        for (int nj = 0; nj < 8; nj++) {
            const float p0 = __expf(sc[nj][0] - m0);
            const float p1 = __expf(sc[nj][1] - m0);
            const float p2 = __expf(sc[nj][2] - m1);
            const float p3 = __expf(sc[nj][3] - m1);
            s0 += p0 + p1;  s1 += p2 + p3;
            __nv_bfloat16 h0 = __float2bfloat16(p0), h1 = __float2bfloat16(p1);
            __nv_bfloat16 h2 = __float2bfloat16(p2), h3 = __float2bfloat16(p3);
            __nv_bfloat16 e0 = __float2bfloat16(p0 - __bfloat162float(h0));
            __nv_bfloat16 e1 = __float2bfloat16(p1 - __bfloat162float(h1));
            __nv_bfloat16 e2 = __float2bfloat16(p2 - __bfloat162float(h2));
            __nv_bfloat16 e3 = __float2bfloat16(p3 - __bfloat162float(h3));
            const int kb = nj >> 1, hf = (nj & 1) * 2;
            pah[kb][hf + 0] = pk(h0, h1);
            pah[kb][hf + 1] = pk(h2, h3);
            pal[kb][hf + 0] = pk(e0, e1);
            pal[kb][hf + 1] = pk(e2, e3);
        }
        s0 += __shfl_xor_sync(0xffffffffu, s0, 1);
        s0 += __shfl_xor_sync(0xffffffffu, s0, 2);
        s1 += __shfl_xor_sync(0xffffffffu, s1, 1);
        s1 += __shfl_xor_sync(0xffffffffu, s1, 2);
        l0 = l0 * f0 + s0;
        l1 = l1 * f1 + s1;
#pragma unroll
        for (int nt = 0; nt < 16; nt++) {
            o[nt][0] *= f0; o[nt][1] *= f0;
            o[nt][2] *= f1; o[nt][3] *= f1;
        }

        // ---- O += P V ----
#pragma unroll
        for (int kb = 0; kb < 4; kb++) {
#pragma unroll
            for (int ng = 0; ng < 8; ng++) {
                const unsigned voff =
                    (unsigned)((kb * 16 + (mat & 1) * 8 + lm7) * ASD + ng * 16 + (mat >> 1) * 8) * 2u;
                unsigned vh4[4], vl4[4];
                ldsm_x4_t(vh4, smb + OVH + voff);
                ldsm_x4_t(vl4, smb + OVL + voff);
                mma_bf16(o[2 * ng],     pah[kb], vh4);
                mma_bf16(o[2 * ng],     pah[kb], vl4);
                mma_bf16(o[2 * ng],     pal[kb], vh4);
                mma_bf16(o[2 * ng + 1], pah[kb], vh4 + 2);
                mma_bf16(o[2 * ng + 1], pah[kb], vl4 + 2);
                mma_bf16(o[2 * ng + 1], pal[kb], vh4 + 2);
            }
        }
    }

    // ---- epilogue: write bf16 hi/lo ----
    const float i0 = 1.0f / l0, i1 = 1.0f / l1;
    const size_t row0 = (size_t)(b * SEQ + qr0 + warp * 16 + g);
    const size_t row1 = row0 + 8;
#pragma unroll
    for (int nt = 0; nt < 16; nt++) {
        const int col = h * HDIM + nt * 8 + tq * 2;
        const float v0 = o[nt][0] * i0, v1 = o[nt][1] * i0;
        const float v2 = o[nt][2] * i1, v3 = o[nt][3] * i1;
        __nv_bfloat16 h0 = __float2bfloat16(v0), h1 = __float2bfloat16(v1);
        __nv_bfloat16 h2 = __float2bfloat16(v2), h3 = __float2bfloat16(v3);
        *(unsigned*)&oh[row0 * HIDN + col] = pk(h0, h1);
        *(unsigned*)&oh[row1 * HIDN + col] = pk(h2, h3);
        *(unsigned*)&ol[row0 * HIDN + col] =
            pk(__float2bfloat16(v0 - __bfloat162float(h0)),
               __float2bfloat16(v1 - __bfloat162float(h1)));
        *(unsigned*)&ol[row1 * HIDN + col] =
            pk(__float2bfloat16(v2 - __bfloat162float(h2)),
               __float2bfloat16(v3 - __bfloat162float(h3)));
    }
}

// ---------------------------------------------------------------------------
extern "C" void kernel_launch(void* const* d_in, const int* in_sizes, int n_in,
                              void* d_out, int out_size)
{
    const float* hidden = (const float*)d_in[0];
    const float* wq     = (const float*)d_in[1];
    const float* wk     = (const float*)d_in[2];
    const float* wv     = (const float*)d_in[3];
    const float* wo     = (const float*)d_in[4];
    const int*   pos    = (const int*)d_in[6];
    float*       outp   = (float*)d_out;

    float* qkv;  cudaGetSymbolAddress((void**)&qkv,  g_qkv);
    __nv_bfloat16 *qkvh, *qkvl, *hidh, *hidl, *wqh, *wql, *wkh, *wkl,
                  *wvh, *wvl, *woh, *wol, *ath, *atl;
    cudaGetSymbolAddress((void**)&qkvh, g_qkvh);
    cudaGetSymbolAddress((void**)&qkvl, g_qkvl);
    cudaGetSymbolAddress((void**)&hidh, g_hidh);
    cudaGetSymbolAddress((void**)&hidl, g_hidl);
    cudaGetSymbolAddress((void**)&wqh, g_wqh);
    cudaGetSymbolAddress((void**)&wql, g_wql);
    cudaGetSymbolAddress((void**)&wkh, g_wkh);
    cudaGetSymbolAddress((void**)&wkl, g_wkl);
    cudaGetSymbolAddress((void**)&wvh, g_wvh);
    cudaGetSymbolAddress((void**)&wvl, g_wvl);
    cudaGetSymbolAddress((void**)&woh, g_woh);
    cudaGetSymbolAddress((void**)&wol, g_wol);
    cudaGetSymbolAddress((void**)&ath, g_ath);
    cudaGetSymbolAddress((void**)&atl, g_atl);

    cudaFuncSetAttribute(gemm_pre, cudaFuncAttributeMaxDynamicSharedMemorySize, GEMM_SMEM);
    cudaFuncSetAttribute(attn_tc,  cudaFuncAttributeMaxDynamicSharedMemorySize, ATT_SMEM);

    const int nHid = NNZ * HIDN;         // 16.7M
    const int nWqo = HIDN * HIDN;        // 16.7M
    const int nWkv = 1024 * HIDN;        // 4.2M
    split_kernel<<<nHid / 1024, 256>>>(hidden, hidh, hidl, nHid);
    split_kernel<<<nWqo / 1024, 256>>>(wq, wqh, wql, nWqo);
    split_kernel<<<nWkv / 1024, 256>>>(wk, wkh, wkl, nWkv);
    split_kernel<<<nWkv / 1024, 256>>>(wv, wvh, wvl, nWkv);
    split_kernel<<<nWqo / 1024, 256>>>(wo, woh, wol, nWqo);

    // QKV projections -> fp32 qkv buffer
    gemm_pre<<<dim3(32, 32), 512, GEMM_SMEM>>>(hidh, hidl, wqh, wql, qkv,        HIDN, QKVC);
    gemm_pre<<<dim3(8,  32), 512, GEMM_SMEM>>>(hidh, hidl, wkh, wkl, qkv + KOFF, HIDN, QKVC);
    gemm_pre<<<dim3(8,  32), 512, GEMM_SMEM>>>(hidh, hidl, wvh, wvl, qkv + VOFF, HIDN, QKVC);

    // RoPE (+Q prescale) and split to bf16 hi/lo
    split_rope_kernel<<<dim3(NNZ, 48), 64>>>(qkv, pos, qkvh, qkvl);

    // Tensor-core flash attention -> bf16 hi/lo attn
    attn_tc<<<dim3(16, NHEAD, NBATCH), 128, ATT_SMEM>>>(qkvh, qkvl, ath, atl);

    // Output projection
    gemm_pre<<<dim3(32, 32), 512, GEMM_SMEM>>>(ath, atl, woh, wol, outp, HIDN, HIDN);
}

// round 6
// speedup vs baseline: 2.9393x; 1.0613x over previous
#include <cuda_runtime.h>
#include <cuda_bf16.h>
#include <math.h>

#define NNZ   4096
#define HIDN  4096
#define NHEAD 32
#define NKVH  8
#define HDIM  128
#define SEQ   1024
#define NBATCH 4
#define QKVC  6144
#define KOFF  4096
#define VOFF  5120

// ---------------- persistent scratch ----------------
__device__ float g_qkv[(size_t)NNZ * QKVC];
__device__ __nv_bfloat16 g_qkvh[(size_t)NNZ * QKVC];
__device__ __nv_bfloat16 g_qkvl[(size_t)NNZ * QKVC];
__device__ __nv_bfloat16 g_hidh[(size_t)NNZ * HIDN];
__device__ __nv_bfloat16 g_hidl[(size_t)NNZ * HIDN];
__device__ __nv_bfloat16 g_wh[(size_t)QKVC * HIDN];   // fused [wq;wk;wv] hi
__device__ __nv_bfloat16 g_wl[(size_t)QKVC * HIDN];   // fused lo
__device__ __nv_bfloat16 g_woh[(size_t)HIDN * HIDN];
__device__ __nv_bfloat16 g_wol[(size_t)HIDN * HIDN];
__device__ __nv_bfloat16 g_ath[(size_t)NNZ * HIDN];
__device__ __nv_bfloat16 g_atl[(size_t)NNZ * HIDN];

// ---------------- primitives ----------------
__device__ __forceinline__ void ldsm_x4(unsigned* r, unsigned addr) {
    asm volatile("ldmatrix.sync.aligned.m8n8.x4.shared.b16 {%0,%1,%2,%3}, [%4];\n"
                 : "=r"(r[0]), "=r"(r[1]), "=r"(r[2]), "=r"(r[3]) : "r"(addr));
}
__device__ __forceinline__ void ldsm_x4_t(unsigned* r, unsigned addr) {
    asm volatile("ldmatrix.sync.aligned.m8n8.x4.trans.shared.b16 {%0,%1,%2,%3}, [%4];\n"
                 : "=r"(r[0]), "=r"(r[1]), "=r"(r[2]), "=r"(r[3]) : "r"(addr));
}
__device__ __forceinline__ void mma_bf16(float* c, const unsigned* a, const unsigned* b) {
    asm volatile(
        "mma.sync.aligned.m16n8k16.row.col.f32.bf16.bf16.f32 "
        "{%0,%1,%2,%3}, {%4,%5,%6,%7}, {%8,%9}, {%0,%1,%2,%3};\n"
        : "+f"(c[0]), "+f"(c[1]), "+f"(c[2]), "+f"(c[3])
        : "r"(a[0]), "r"(a[1]), "r"(a[2]), "r"(a[3]), "r"(b[0]), "r"(b[1]));
}
__device__ __forceinline__ unsigned pk(__nv_bfloat16 a, __nv_bfloat16 b) {
    __nv_bfloat162 t(a, b);
    return *reinterpret_cast<unsigned*>(&t);
}
__device__ __forceinline__ void cpa16(unsigned dst, const void* src) {
    asm volatile("cp.async.cg.shared.global [%0], [%1], 16;\n" :: "r"(dst), "l"(src));
}
__device__ __forceinline__ void cpa_commit() { asm volatile("cp.async.commit_group;\n"); }

// ---------------- split kernels ----------------
__global__ void split_kernel(const float* __restrict__ src,
                             __nv_bfloat16* __restrict__ hi,
                             __nv_bfloat16* __restrict__ lo, int n)
{
    int i = (blockIdx.x * blockDim.x + threadIdx.x) * 4;
    if (i >= n) return;
    float4 v = *(const float4*)(src + i);
    __nv_bfloat16 h0 = __float2bfloat16(v.x), h1 = __float2bfloat16(v.y);
    __nv_bfloat16 h2 = __float2bfloat16(v.z), h3 = __float2bfloat16(v.w);
    __nv_bfloat16 l0 = __float2bfloat16(v.x - __bfloat162float(h0));
    __nv_bfloat16 l1 = __float2bfloat16(v.y - __bfloat162float(h1));
    __nv_bfloat16 l2 = __float2bfloat16(v.z - __bfloat162float(h2));
    __nv_bfloat16 l3 = __float2bfloat16(v.w - __bfloat162float(h3));
    *(uint2*)(hi + i) = make_uint2(pk(h0, h1), pk(h2, h3));
    *(uint2*)(lo + i) = make_uint2(pk(l0, l1), pk(l2, l3));
}

// RoPE + split for qkv. grid (NNZ, 48), block 64.
// Heads 0..31: Q (rope + prescale). 32..39: K (rope). 40..47: V (copy).
__global__ void split_rope_kernel(const float* __restrict__ qkv,
                                  const int* __restrict__ pos,
                                  __nv_bfloat16* __restrict__ qh,
                                  __nv_bfloat16* __restrict__ ql)
{
    const int tok = blockIdx.x;
    const int hb  = blockIdx.y;
    const int d   = threadIdx.x;
    const size_t base = (size_t)tok * QKVC + hb * HDIM;
    float x1 = qkv[base + d], x2 = qkv[base + d + 64];

    if (hb < 40) {
        float freq = powf(500000.0f, -(float)d / 64.0f);
        const float wl = 6.283185307179586f / freq;
        float f;
        if (wl < 2048.0f)       f = freq;
        else if (wl > 8192.0f)  f = freq * 0.125f;
        else {
            float smooth = (8192.0f / wl - 1.0f) * (1.0f / 3.0f);
            f = (1.0f - smooth) * freq * 0.125f + smooth * freq;
        }
        const float ang = (float)pos[tok] * f;
        const float c = cosf(ang), s = sinf(ang);
        float y1 = x1 * c - x2 * s;
        float y2 = x2 * c + x1 * s;
        if (hb < 32) { y1 *= 0.08838834764831845f; y2 *= 0.08838834764831845f; }
        x1 = y1; x2 = y2;
    }
    __nv_bfloat16 h1 = __float2bfloat16(x1), h2 = __float2bfloat16(x2);
    qh[base + d]      = h1;
    qh[base + d + 64] = h2;
    ql[base + d]      = __float2bfloat16(x1 - __bfloat162float(h1));
    ql[base + d + 64] = __float2bfloat16(x2 - __bfloat162float(h2));
}

// ---------------------------------------------------------------------------
// Pre-split bf16x3 GEMM (mma.sync): C[i,j] = sum_k A[i,k]*B[j,k].
// 128x128 tile, BK=32, 512 threads, 4-stage cp.async pipeline.
// ---------------------------------------------------------------------------
#define GSTRIDE 40
#define G_ARR_BYTES (128 * GSTRIDE * 2)          // 10240
#define G_STAGE_BYTES (4 * G_ARR_BYTES)          // 40960
#define NSTAGE 4
#define GEMM_SMEM (NSTAGE * G_STAGE_BYTES)       // 163840

__global__ void __launch_bounds__(512) gemm_pre(
    const __nv_bfloat16* __restrict__ Ahi, const __nv_bfloat16* __restrict__ Alo,
    const __nv_bfloat16* __restrict__ Bhi, const __nv_bfloat16* __restrict__ Blo,
    float* __restrict__ C, int K, int ldc)
{
    extern __shared__ __nv_bfloat16 dsm[];
    const unsigned smb = (unsigned)__cvta_generic_to_shared(dsm);

    const int bm = blockIdx.y * 128;
    const int bn = blockIdx.x * 128;
    const int t  = threadIdx.x;
    const int lane = t & 31;
    const int warp = t >> 5;
    const int wm = (warp & 3) * 32;
    const int wn = (warp >> 2) * 32;

    // loader: 128 rows x 4 chunks of 8 bf16 (16B); 1 chunk/thread/array
    const int ldRow = t >> 2;
    const int ldCh  = (t & 3) * 8;
    const size_t aOff = (size_t)(bm + ldRow) * K + ldCh;
    const size_t bOff = (size_t)(bn + ldRow) * K + ldCh;
    const unsigned dOff = (unsigned)(ldRow * GSTRIDE + ldCh) * 2u;

    const int mat = lane >> 3;
    const int aRow = wm + (lane & 7) + (mat & 1) * 8;
    const int aColAdd = (mat >> 1) * 8;
    const int bRow = wn + (lane & 7) + (mat >> 1) * 8;
    const int bColAdd = (mat & 1) * 8;

    float acc[2][4][4];
#pragma unroll
    for (int mi = 0; mi < 2; mi++)
#pragma unroll
        for (int nj = 0; nj < 4; nj++)
#pragma unroll
            for (int u = 0; u < 4; u++) acc[mi][nj][u] = 0.0f;

    const int nt = K / 32;

    // prologue: stages 0..2
#pragma unroll
    for (int s = 0; s < NSTAGE - 1; s++) {
        unsigned d0 = smb + s * G_STAGE_BYTES + dOff;
        const int kn = s * 32;
        cpa16(d0,                   Ahi + aOff + kn);
        cpa16(d0 + G_ARR_BYTES,     Alo + aOff + kn);
        cpa16(d0 + 2 * G_ARR_BYTES, Bhi + bOff + kn);
        cpa16(d0 + 3 * G_ARR_BYTES, Blo + bOff + kn);
        cpa_commit();
    }

    for (int i = 0; i < nt; i++) {
        if (i + NSTAGE - 1 < nt) {
            unsigned d0 = smb + ((i + NSTAGE - 1) & (NSTAGE - 1)) * G_STAGE_BYTES + dOff;
            const int kn = (i + NSTAGE - 1) * 32;
            cpa16(d0,                   Ahi + aOff + kn);
            cpa16(d0 + G_ARR_BYTES,     Alo + aOff + kn);
            cpa16(d0 + 2 * G_ARR_BYTES, Bhi + bOff + kn);
            cpa16(d0 + 3 * G_ARR_BYTES, Blo + bOff + kn);
        }
        cpa_commit();                                    // always commit (may be empty)
        asm volatile("cp.async.wait_group %0;\n" :: "n"(NSTAGE - 1));
        __syncthreads();

        const unsigned st = smb + (i & (NSTAGE - 1)) * G_STAGE_BYTES;
        const unsigned bAhi = st;
        const unsigned bAlo = st + G_ARR_BYTES;
        const unsigned bBhi = st + 2 * G_ARR_BYTES;
        const unsigned bBlo = st + 3 * G_ARR_BYTES;

#pragma unroll
        for (int kk = 0; kk < 32; kk += 16) {
            unsigned ahi[2][4], alo[2][4], bhi[8], blo[8];
#pragma unroll
            for (int mi = 0; mi < 2; mi++) {
                unsigned off = (unsigned)((aRow + mi * 16) * GSTRIDE + kk + aColAdd) * 2u;
                ldsm_x4(ahi[mi], bAhi + off);
                ldsm_x4(alo[mi], bAlo + off);
            }
#pragma unroll
            for (int p = 0; p < 2; p++) {
                unsigned off = (unsigned)((bRow + p * 16) * GSTRIDE + kk + bColAdd) * 2u;
                ldsm_x4(&bhi[p * 4], bBhi + off);
                ldsm_x4(&blo[p * 4], bBlo + off);
            }
#pragma unroll
            for (int mi = 0; mi < 2; mi++)
#pragma unroll
                for (int nj = 0; nj < 4; nj++) {
                    const unsigned* bh = &bhi[(nj >> 1) * 4 + (nj & 1) * 2];
                    const unsigned* bl = &blo[(nj >> 1) * 4 + (nj & 1) * 2];
                    mma_bf16(acc[mi][nj], ahi[mi], bh);
                    mma_bf16(acc[mi][nj], ahi[mi], bl);
                    mma_bf16(acc[mi][nj], alo[mi], bh);
                }
        }
        __syncthreads();
    }

    const int g = lane >> 2;
    const int tq = lane & 3;
#pragma unroll
    for (int mi = 0; mi < 2; mi++) {
        const int row0 = bm + wm + mi * 16 + g;
#pragma unroll
        for (int nj = 0; nj < 4; nj++) {
            const int col = bn + wn + nj * 8 + tq * 2;
            *(float2*)(C + (size_t)row0 * ldc + col) =
                make_float2(acc[mi][nj][0], acc[mi][nj][1]);
            *(float2*)(C + (size_t)(row0 + 8) * ldc + col) =
                make_float2(acc[mi][nj][2], acc[mi][nj][3]);
        }
    }
}

// ---------------------------------------------------------------------------
// Tensor-core flash attention (causal, GQA g=4), bf16x3. Unchanged (round 3).
// ---------------------------------------------------------------------------
#define ASD 136
#define A_ARR (64 * ASD)
#define ATT_SMEM (6 * A_ARR * 2)

__global__ void __launch_bounds__(128) attn_tc(
    const __nv_bfloat16* __restrict__ qh, const __nv_bfloat16* __restrict__ ql,
    __nv_bfloat16* __restrict__ oh, __nv_bfloat16* __restrict__ ol)
{
    extern __shared__ __nv_bfloat16 smA[];
    const unsigned smb = (unsigned)__cvta_generic_to_shared(smA);
    const unsigned OQH = 0, OQL = A_ARR * 2, OKH = 2 * A_ARR * 2, OKL = 3 * A_ARR * 2,
                   OVH = 4 * A_ARR * 2, OVL = 5 * A_ARR * 2;

    const int qt  = (int)gridDim.x - 1 - (int)blockIdx.x;
    const int h   = blockIdx.y;
    const int b   = blockIdx.z;
    const int kvh = h >> 2;
    const int tid = threadIdx.x;
    const int lane = tid & 31;
    const int warp = tid >> 5;
    const int qr0 = qt * 64;
    const int mat = lane >> 3;
    const int lm7 = lane & 7;
    const int g   = lane >> 2;
    const int tq  = lane & 3;

    for (int j = tid; j < 64 * 16; j += 128) {
        const int r = j >> 4, ch = (j & 15) * 8;
        const size_t gi = (size_t)(b * SEQ + qr0 + r) * QKVC + h * HDIM + ch;
        *(uint4*)&smA[r * ASD + ch]           = *(const uint4*)&qh[gi];
        *(uint4*)&smA[A_ARR + r * ASD + ch]   = *(const uint4*)&ql[gi];
    }

    float o[16][4];
#pragma unroll
    for (int nt = 0; nt < 16; nt++)
#pragma unroll
        for (int u = 0; u < 4; u++) o[nt][u] = 0.0f;
    float m0 = -1e30f, m1 = -1e30f, l0 = 0.0f, l1 = 0.0f;

    for (int kt = 0; kt <= qt; kt++) {
        __syncthreads();
        for (int j = tid; j < 64 * 16; j += 128) {
            const int r = j >> 4, ch = (j & 15) * 8;
            const size_t tr = (size_t)(b * SEQ + kt * 64 + r) * QKVC;
            const size_t ki = tr + KOFF + kvh * HDIM + ch;
            const size_t vi = tr + VOFF + kvh * HDIM + ch;
            *(uint4*)&smA[2 * A_ARR + r * ASD + ch] = *(const uint4*)&qh[ki];
            *(uint4*)&smA[3 * A_ARR + r * ASD + ch] = *(const uint4*)&ql[ki];
            *(uint4*)&smA[4 * A_ARR + r * ASD + ch] = *(const uint4*)&qh[vi];
            *(uint4*)&smA[5 * A_ARR + r * ASD + ch] = *(const uint4*)&ql[vi];
        }
        __syncthreads();

        float sc[8][4];
#pragma unroll
        for (int nj = 0; nj < 8; nj++)
#pragma unroll
            for (int u = 0; u < 4; u++) sc[nj][u] = 0.0f;

#pragma unroll
        for (int kk = 0; kk < 128; kk += 16) {
            unsigned ah4[4], al4[4], bh[16], bl[16];
            const unsigned aoff =
                (unsigned)((warp * 16 + lm7 + (mat & 1) * 8) * ASD + kk + (mat >> 1) * 8) * 2u;
            ldsm_x4(ah4, smb + OQH + aoff);
            ldsm_x4(al4, smb + OQL + aoff);
#pragma unroll
            for (int p = 0; p < 4; p++) {
                const unsigned boff =
                    (unsigned)((p * 16 + lm7 + (mat >> 1) * 8) * ASD + kk + (mat & 1) * 8) * 2u;
                ldsm_x4(&bh[p * 4], smb + OKH + boff);
                ldsm_x4(&bl[p * 4], smb + OKL + boff);
            }
#pragma unroll
            for (int nj = 0; nj < 8; nj++) {
                const unsigned* b1 = &bh[(nj >> 1) * 4 + (nj & 1) * 2];
                const unsigned* b2 = &bl[(nj >> 1) * 4 + (nj & 1) * 2];
                mma_bf16(sc[nj], ah4, b1);
                mma_bf16(sc[nj], ah4, b2);
                mma_bf16(sc[nj], al4, b1);
            }
        }

        if (kt == qt) {
            const int r0 = warp * 16 + g, r1 = r0 + 8;
#pragma unroll
            for (int nj = 0; nj < 8; nj++)
#pragma unroll
                for (int e = 0; e < 2; e++) {
                    const int cidx = nj * 8 + tq * 2 + e;
                    if (cidx > r0) sc[nj][e]     = -1e30f;
                    if (cidx > r1) sc[nj][2 + e] = -1e30f;
                }
        }

        float mx0 = -1e30f, mx1 = -1e30f;
#pragma unroll
        for (int nj = 0; nj < 8; nj++) {
            mx0 = fmaxf(mx0, fmaxf(sc[nj][0], sc[nj][1]));
            mx1 = fmaxf(mx1, fmaxf(sc[nj][2], sc[nj][3]));
        }
        mx0 = fmaxf(mx0, __shfl_xor_sync(0xffffffffu, mx0, 1));
        mx0 = fmaxf(mx0, __shfl_xor_sync(0xffffffffu, mx0, 2));
        mx1 = fmaxf(mx1, __shfl_xor_sync(0xffffffffu, mx1, 1));
        mx1 = fmaxf(mx1, __shfl_xor_sync(0xffffffffu, mx1, 2));

        const float mn0 = fmaxf(m0, mx0), mn1 = fmaxf(m1, mx1);
        const float f0 = __expf(m0 - mn0), f1 = __expf(m1 - mn1);
        m0 = mn0; m1 = mn1;

        float s0 = 0.0f, s1 = 0.0f;
        unsigned pah[4][4], pal[4][4];
#pragma unroll
        for (int nj = 0; nj < 8; nj++) {
            const float p0 = __expf(sc[nj][0] - m0);
            const float p1 = __expf(sc[nj][1] - m0);
            const float p2 = __expf(sc[nj][2] - m1);
            const float p3 = __expf(sc[nj][3] - m1);
            s0 += p0 + p1;  s1 += p2 + p3;
            __nv_bfloat16 h0 = __float2bfloat16(p0), h1 = __float2bfloat16(p1);
            __nv_bfloat16 h2 = __float2bfloat16(p2), h3 = __float2bfloat16(p3);
            __nv_bfloat16 e0 = __float2bfloat16(p0 - __bfloat162float(h0));
            __nv_bfloat16 e1 = __float2bfloat16(p1 - __bfloat162float(h1));
            __nv_bfloat16 e2 = __float2bfloat16(p2 - __bfloat162float(h2));
            __nv_bfloat16 e3 = __float2bfloat16(p3 - __bfloat162float(h3));
            const int kb = nj >> 1, hf = (nj & 1) * 2;
            pah[kb][hf + 0] = pk(h0, h1);
            pah[kb][hf + 1] = pk(h2, h3);
            pal[kb][hf + 0] = pk(e0, e1);
            pal[kb][hf + 1] = pk(e2, e3);
        }
        s0 += __shfl_xor_sync(0xffffffffu, s0, 1);
        s0 += __shfl_xor_sync(0xffffffffu, s0, 2);
        s1 += __shfl_xor_sync(0xffffffffu, s1, 1);
        s1 += __shfl_xor_sync(0xffffffffu, s1, 2);
        l0 = l0 * f0 + s0;
        l1 = l1 * f1 + s1;
#pragma unroll
        for (int nt = 0; nt < 16; nt++) {
            o[nt][0] *= f0; o[nt][1] *= f0;
            o[nt][2] *= f1; o[nt][3] *= f1;
        }

#pragma unroll
        for (int kb = 0; kb < 4; kb++) {
#pragma unroll
            for (int ng = 0; ng < 8; ng++) {
                const unsigned voff =
                    (unsigned)((kb * 16 + (mat & 1) * 8 + lm7) * ASD + ng * 16 + (mat >> 1) * 8) * 2u;
                unsigned vh4[4], vl4[4];
                ldsm_x4_t(vh4, smb + OVH + voff);
                ldsm_x4_t(vl4, smb + OVL + voff);
                mma_bf16(o[2 * ng],     pah[kb], vh4);
                mma_bf16(o[2 * ng],     pah[kb], vl4);
                mma_bf16(o[2 * ng],     pal[kb], vh4);
                mma_bf16(o[2 * ng + 1], pah[kb], vh4 + 2);
                mma_bf16(o[2 * ng + 1], pah[kb], vl4 + 2);
                mma_bf16(o[2 * ng + 1], pal[kb], vh4 + 2);
            }
        }
    }

    const float i0 = 1.0f / l0, i1 = 1.0f / l1;
    const size_t row0 = (size_t)(b * SEQ + qr0 + warp * 16 + g);
    const size_t row1 = row0 + 8;
#pragma unroll
    for (int nt = 0; nt < 16; nt++) {
        const int col = h * HDIM + nt * 8 + tq * 2;
        const float v0 = o[nt][0] * i0, v1 = o[nt][1] * i0;
        const float v2 = o[nt][2] * i1, v3 = o[nt][3] * i1;
        __nv_bfloat16 h0 = __float2bfloat16(v0), h1 = __float2bfloat16(v1);
        __nv_bfloat16 h2 = __float2bfloat16(v2), h3 = __float2bfloat16(v3);
        *(unsigned*)&oh[row0 * HIDN + col] = pk(h0, h1);
        *(unsigned*)&oh[row1 * HIDN + col] = pk(h2, h3);
        *(unsigned*)&ol[row0 * HIDN + col] =
            pk(__float2bfloat16(v0 - __bfloat162float(h0)),
               __float2bfloat16(v1 - __bfloat162float(h1)));
        *(unsigned*)&ol[row1 * HIDN + col] =
            pk(__float2bfloat16(v2 - __bfloat162float(h2)),
               __float2bfloat16(v3 - __bfloat162float(h3)));
    }
}

// ---------------------------------------------------------------------------
extern "C" void kernel_launch(void* const* d_in, const int* in_sizes, int n_in,
                              void* d_out, int out_size)
{
    const float* hidden = (const float*)d_in[0];
    const float* wq     = (const float*)d_in[1];
    const float* wk     = (const float*)d_in[2];
    const float* wv     = (const float*)d_in[3];
    const float* wo     = (const float*)d_in[4];
    const int*   pos    = (const int*)d_in[6];
    float*       outp   = (float*)d_out;

    float* qkv;  cudaGetSymbolAddress((void**)&qkv,  g_qkv);
    __nv_bfloat16 *qkvh, *qkvl, *hidh, *hidl, *wh, *wl, *woh, *wol, *ath, *atl;
    cudaGetSymbolAddress((void**)&qkvh, g_qkvh);
    cudaGetSymbolAddress((void**)&qkvl, g_qkvl);
    cudaGetSymbolAddress((void**)&hidh, g_hidh);
    cudaGetSymbolAddress((void**)&hidl, g_hidl);
    cudaGetSymbolAddress((void**)&wh,  g_wh);
    cudaGetSymbolAddress((void**)&wl,  g_wl);
    cudaGetSymbolAddress((void**)&woh, g_woh);
    cudaGetSymbolAddress((void**)&wol, g_wol);
    cudaGetSymbolAddress((void**)&ath, g_ath);
    cudaGetSymbolAddress((void**)&atl, g_atl);

    cudaFuncSetAttribute(gemm_pre, cudaFuncAttributeMaxDynamicSharedMemorySize, GEMM_SMEM);
    cudaFuncSetAttribute(attn_tc,  cudaFuncAttributeMaxDynamicSharedMemorySize, ATT_SMEM);

    const int nHid = NNZ * HIDN;
    const int nWqo = HIDN * HIDN;
    const int nWkv = 1024 * HIDN;
    split_kernel<<<nHid / 1024, 256>>>(hidden, hidh, hidl, nHid);
    split_kernel<<<nWqo / 1024, 256>>>(wq, wh,                       wl,                       nWqo);
    split_kernel<<<nWkv / 1024, 256>>>(wk, wh + (size_t)KOFF * HIDN, wl + (size_t)KOFF * HIDN, nWkv);
    split_kernel<<<nWkv / 1024, 256>>>(wv, wh + (size_t)VOFF * HIDN, wl + (size_t)VOFF * HIDN, nWkv);
    split_kernel<<<nWqo / 1024, 256>>>(wo, woh, wol, nWqo);

    // Fused QKV projection: one launch, [4096 x 6144]
    gemm_pre<<<dim3(48, 32), 512, GEMM_SMEM>>>(hidh, hidl, wh, wl, qkv, HIDN, QKVC);

    // RoPE (+Q prescale) and split to bf16 hi/lo
    split_rope_kernel<<<dim3(NNZ, 48), 64>>>(qkv, pos, qkvh, qkvl);

    // Tensor-core flash attention -> bf16 hi/lo attn
    attn_tc<<<dim3(16, NHEAD, NBATCH), 128, ATT_SMEM>>>(qkvh, qkvl, ath, atl);

    // Output projection
    gemm_pre<<<dim3(32, 32), 512, GEMM_SMEM>>>(ath, atl, woh, wol, outp, HIDN, HIDN);
}

// round 7
// speedup vs baseline: 2.9426x; 1.0011x over previous
#include <cuda_runtime.h>
#include <cuda_bf16.h>
#include <math.h>

#define NNZ   4096
#define HIDN  4096
#define NHEAD 32
#define NKVH  8
#define HDIM  128
#define SEQ   1024
#define NBATCH 4
#define QKVC  6144
#define KOFF  4096
#define VOFF  5120

// ---------------- persistent scratch ----------------
__device__ float g_qkv[(size_t)NNZ * QKVC];
__device__ __nv_bfloat16 g_qkvh[(size_t)NNZ * QKVC];
__device__ __nv_bfloat16 g_qkvl[(size_t)NNZ * QKVC];
__device__ __nv_bfloat16 g_hidh[(size_t)NNZ * HIDN];
__device__ __nv_bfloat16 g_hidl[(size_t)NNZ * HIDN];
__device__ __nv_bfloat16 g_wh[(size_t)QKVC * HIDN];   // fused [wq;wk;wv] hi
__device__ __nv_bfloat16 g_wl[(size_t)QKVC * HIDN];   // fused lo
__device__ __nv_bfloat16 g_woh[(size_t)HIDN * HIDN];
__device__ __nv_bfloat16 g_wol[(size_t)HIDN * HIDN];
__device__ __nv_bfloat16 g_ath[(size_t)NNZ * HIDN];
__device__ __nv_bfloat16 g_atl[(size_t)NNZ * HIDN];

// ---------------- primitives ----------------
__device__ __forceinline__ void ldsm_x4(unsigned* r, unsigned addr) {
    asm volatile("ldmatrix.sync.aligned.m8n8.x4.shared.b16 {%0,%1,%2,%3}, [%4];\n"
                 : "=r"(r[0]), "=r"(r[1]), "=r"(r[2]), "=r"(r[3]) : "r"(addr));
}
__device__ __forceinline__ void ldsm_x4_t(unsigned* r, unsigned addr) {
    asm volatile("ldmatrix.sync.aligned.m8n8.x4.trans.shared.b16 {%0,%1,%2,%3}, [%4];\n"
                 : "=r"(r[0]), "=r"(r[1]), "=r"(r[2]), "=r"(r[3]) : "r"(addr));
}
__device__ __forceinline__ void mma_bf16(float* c, const unsigned* a, const unsigned* b) {
    asm volatile(
        "mma.sync.aligned.m16n8k16.row.col.f32.bf16.bf16.f32 "
        "{%0,%1,%2,%3}, {%4,%5,%6,%7}, {%8,%9}, {%0,%1,%2,%3};\n"
        : "+f"(c[0]), "+f"(c[1]), "+f"(c[2]), "+f"(c[3])
        : "r"(a[0]), "r"(a[1]), "r"(a[2]), "r"(a[3]), "r"(b[0]), "r"(b[1]));
}
__device__ __forceinline__ unsigned pk(__nv_bfloat16 a, __nv_bfloat16 b) {
    __nv_bfloat162 t(a, b);
    return *reinterpret_cast<unsigned*>(&t);
}
__device__ __forceinline__ void cpa16(unsigned dst, const void* src) {
    asm volatile("cp.async.cg.shared.global [%0], [%1], 16;\n" :: "r"(dst), "l"(src));
}
__device__ __forceinline__ void cpa_commit() { asm volatile("cp.async.commit_group;\n"); }

// ---------------- split kernels ----------------
__global__ void split_kernel(const float* __restrict__ src,
                             __nv_bfloat16* __restrict__ hi,
                             __nv_bfloat16* __restrict__ lo, int n)
{
    int i = (blockIdx.x * blockDim.x + threadIdx.x) * 4;
    if (i >= n) return;
    float4 v = *(const float4*)(src + i);
    __nv_bfloat16 h0 = __float2bfloat16(v.x), h1 = __float2bfloat16(v.y);
    __nv_bfloat16 h2 = __float2bfloat16(v.z), h3 = __float2bfloat16(v.w);
    __nv_bfloat16 l0 = __float2bfloat16(v.x - __bfloat162float(h0));
    __nv_bfloat16 l1 = __float2bfloat16(v.y - __bfloat162float(h1));
    __nv_bfloat16 l2 = __float2bfloat16(v.z - __bfloat162float(h2));
    __nv_bfloat16 l3 = __float2bfloat16(v.w - __bfloat162float(h3));
    *(uint2*)(hi + i) = make_uint2(pk(h0, h1), pk(h2, h3));
    *(uint2*)(lo + i) = make_uint2(pk(l0, l1), pk(l2, l3));
}

// RoPE + split for qkv. grid (NNZ, 48), block 64.
__global__ void split_rope_kernel(const float* __restrict__ qkv,
                                  const int* __restrict__ pos,
                                  __nv_bfloat16* __restrict__ qh,
                                  __nv_bfloat16* __restrict__ ql)
{
    const int tok = blockIdx.x;
    const int hb  = blockIdx.y;
    const int d   = threadIdx.x;
    const size_t base = (size_t)tok * QKVC + hb * HDIM;
    float x1 = qkv[base + d], x2 = qkv[base + d + 64];

    if (hb < 40) {
        float freq = powf(500000.0f, -(float)d / 64.0f);
        const float wl = 6.283185307179586f / freq;
        float f;
        if (wl < 2048.0f)       f = freq;
        else if (wl > 8192.0f)  f = freq * 0.125f;
        else {
            float smooth = (8192.0f / wl - 1.0f) * (1.0f / 3.0f);
            f = (1.0f - smooth) * freq * 0.125f + smooth * freq;
        }
        const float ang = (float)pos[tok] * f;
        const float c = cosf(ang), s = sinf(ang);
        float y1 = x1 * c - x2 * s;
        float y2 = x2 * c + x1 * s;
        if (hb < 32) { y1 *= 0.08838834764831845f; y2 *= 0.08838834764831845f; }
        x1 = y1; x2 = y2;
    }
    __nv_bfloat16 h1 = __float2bfloat16(x1), h2 = __float2bfloat16(x2);
    qh[base + d]      = h1;
    qh[base + d + 64] = h2;
    ql[base + d]      = __float2bfloat16(x1 - __bfloat162float(h1));
    ql[base + d + 64] = __float2bfloat16(x2 - __bfloat162float(h2));
}

// ---------------------------------------------------------------------------
// Pre-split bf16x3 GEMM (mma.sync). Unchanged from round 6.
// ---------------------------------------------------------------------------
#define GSTRIDE 40
#define G_ARR_BYTES (128 * GSTRIDE * 2)
#define G_STAGE_BYTES (4 * G_ARR_BYTES)
#define NSTAGE 4
#define GEMM_SMEM (NSTAGE * G_STAGE_BYTES)

__global__ void __launch_bounds__(512) gemm_pre(
    const __nv_bfloat16* __restrict__ Ahi, const __nv_bfloat16* __restrict__ Alo,
    const __nv_bfloat16* __restrict__ Bhi, const __nv_bfloat16* __restrict__ Blo,
    float* __restrict__ C, int K, int ldc)
{
    extern __shared__ __nv_bfloat16 dsm[];
    const unsigned smb = (unsigned)__cvta_generic_to_shared(dsm);

    const int bm = blockIdx.y * 128;
    const int bn = blockIdx.x * 128;
    const int t  = threadIdx.x;
    const int lane = t & 31;
    const int warp = t >> 5;
    const int wm = (warp & 3) * 32;
    const int wn = (warp >> 2) * 32;

    const int ldRow = t >> 2;
    const int ldCh  = (t & 3) * 8;
    const size_t aOff = (size_t)(bm + ldRow) * K + ldCh;
    const size_t bOff = (size_t)(bn + ldRow) * K + ldCh;
    const unsigned dOff = (unsigned)(ldRow * GSTRIDE + ldCh) * 2u;

    const int mat = lane >> 3;
    const int aRow = wm + (lane & 7) + (mat & 1) * 8;
    const int aColAdd = (mat >> 1) * 8;
    const int bRow = wn + (lane & 7) + (mat >> 1) * 8;
    const int bColAdd = (mat & 1) * 8;

    float acc[2][4][4];
#pragma unroll
    for (int mi = 0; mi < 2; mi++)
#pragma unroll
        for (int nj = 0; nj < 4; nj++)
#pragma unroll
            for (int u = 0; u < 4; u++) acc[mi][nj][u] = 0.0f;

    const int nt = K / 32;

#pragma unroll
    for (int s = 0; s < NSTAGE - 1; s++) {
        unsigned d0 = smb + s * G_STAGE_BYTES + dOff;
        const int kn = s * 32;
        cpa16(d0,                   Ahi + aOff + kn);
        cpa16(d0 + G_ARR_BYTES,     Alo + aOff + kn);
        cpa16(d0 + 2 * G_ARR_BYTES, Bhi + bOff + kn);
        cpa16(d0 + 3 * G_ARR_BYTES, Blo + bOff + kn);
        cpa_commit();
    }

    for (int i = 0; i < nt; i++) {
        if (i + NSTAGE - 1 < nt) {
            unsigned d0 = smb + ((i + NSTAGE - 1) & (NSTAGE - 1)) * G_STAGE_BYTES + dOff;
            const int kn = (i + NSTAGE - 1) * 32;
            cpa16(d0,                   Ahi + aOff + kn);
            cpa16(d0 + G_ARR_BYTES,     Alo + aOff + kn);
            cpa16(d0 + 2 * G_ARR_BYTES, Bhi + bOff + kn);
            cpa16(d0 + 3 * G_ARR_BYTES, Blo + bOff + kn);
        }
        cpa_commit();
        asm volatile("cp.async.wait_group %0;\n" :: "n"(NSTAGE - 1));
        __syncthreads();

        const unsigned st = smb + (i & (NSTAGE - 1)) * G_STAGE_BYTES;
        const unsigned bAhi = st;
        const unsigned bAlo = st + G_ARR_BYTES;
        const unsigned bBhi = st + 2 * G_ARR_BYTES;
        const unsigned bBlo = st + 3 * G_ARR_BYTES;

#pragma unroll
        for (int kk = 0; kk < 32; kk += 16) {
            unsigned ahi[2][4], alo[2][4], bhi[8], blo[8];
#pragma unroll
            for (int mi = 0; mi < 2; mi++) {
                unsigned off = (unsigned)((aRow + mi * 16) * GSTRIDE + kk + aColAdd) * 2u;
                ldsm_x4(ahi[mi], bAhi + off);
                ldsm_x4(alo[mi], bAlo + off);
            }
#pragma unroll
            for (int p = 0; p < 2; p++) {
                unsigned off = (unsigned)((bRow + p * 16) * GSTRIDE + kk + bColAdd) * 2u;
                ldsm_x4(&bhi[p * 4], bBhi + off);
                ldsm_x4(&blo[p * 4], bBlo + off);
            }
#pragma unroll
            for (int mi = 0; mi < 2; mi++)
#pragma unroll
                for (int nj = 0; nj < 4; nj++) {
                    const unsigned* bh = &bhi[(nj >> 1) * 4 + (nj & 1) * 2];
                    const unsigned* bl = &blo[(nj >> 1) * 4 + (nj & 1) * 2];
                    mma_bf16(acc[mi][nj], ahi[mi], bh);
                    mma_bf16(acc[mi][nj], ahi[mi], bl);
                    mma_bf16(acc[mi][nj], alo[mi], bh);
                }
        }
        __syncthreads();
    }

    const int g = lane >> 2;
    const int tq = lane & 3;
#pragma unroll
    for (int mi = 0; mi < 2; mi++) {
        const int row0 = bm + wm + mi * 16 + g;
#pragma unroll
        for (int nj = 0; nj < 4; nj++) {
            const int col = bn + wn + nj * 8 + tq * 2;
            *(float2*)(C + (size_t)row0 * ldc + col) =
                make_float2(acc[mi][nj][0], acc[mi][nj][1]);
            *(float2*)(C + (size_t)(row0 + 8) * ldc + col) =
                make_float2(acc[mi][nj][2], acc[mi][nj][3]);
        }
    }
}

// ---------------------------------------------------------------------------
// Flash attention v2: Q-tile 128 rows, 256 threads (8 warps, 2/SMSP),
// K/V tiles 64 keys, cp.async double-buffered. bf16x3 QK + PV.
// Smem: Q hi/lo (128x136) + 2 stages of (Khi,Klo,Vhi,Vlo) (64x136 each).
// ---------------------------------------------------------------------------
#define ASD 136
#define QARR (128 * ASD)                    // elems
#define KARR (64 * ASD)
#define KVSTAGE (4 * KARR)
#define ATT_SMEM ((2 * QARR + 2 * KVSTAGE) * 2)   // 208896 B

__device__ __forceinline__ void kv_fill(
    unsigned stage_b, const __nv_bfloat16* qh, const __nv_bfloat16* ql,
    int b, int kt, int kvh, int tid)
{
    for (int j = tid; j < 64 * 16; j += 256) {
        const int r = j >> 4, ch = (j & 15) * 8;
        const size_t tr = (size_t)(b * SEQ + kt * 64 + r) * QKVC;
        const size_t ki = tr + KOFF + kvh * HDIM + ch;
        const size_t vi = tr + VOFF + kvh * HDIM + ch;
        const unsigned dst = stage_b + (unsigned)(r * ASD + ch) * 2u;
        cpa16(dst,                 qh + ki);
        cpa16(dst + KARR * 2,      ql + ki);
        cpa16(dst + 2 * KARR * 2,  qh + vi);
        cpa16(dst + 3 * KARR * 2,  ql + vi);
    }
}

__global__ void __launch_bounds__(256) attn_tc(
    const __nv_bfloat16* __restrict__ qh, const __nv_bfloat16* __restrict__ ql,
    __nv_bfloat16* __restrict__ oh, __nv_bfloat16* __restrict__ ol)
{
    extern __shared__ __nv_bfloat16 smA[];
    const unsigned smb = (unsigned)__cvta_generic_to_shared(smA);

    const int qt  = (int)gridDim.x - 1 - (int)blockIdx.x;  // heavy tiles first
    const int h   = blockIdx.y;
    const int b   = blockIdx.z;
    const int kvh = h >> 2;
    const int tid = threadIdx.x;
    const int lane = tid & 31;
    const int warp = tid >> 5;           // 0..7, owns q rows warp*16..+15
    const int qr0 = qt * 128;
    const int mat = lane >> 3;
    const int lm7 = lane & 7;
    const int g   = lane >> 2;
    const int tq  = lane & 3;

    const int nkt = 2 * qt + 2;

    // prologue: K/V stages 0,1 via cp.async
    kv_fill(smb + 2 * QARR * 2, qh, ql, b, 0, kvh, tid);
    cpa_commit();
    kv_fill(smb + (2 * QARR + KVSTAGE) * 2, qh, ql, b, 1, kvh, tid);
    cpa_commit();

    // stage Q tile (128 x 128, hi+lo) with regular loads (overlaps cp.async)
    for (int j = tid; j < 128 * 16; j += 256) {
        const int r = j >> 4, ch = (j & 15) * 8;
        const size_t gi = (size_t)(b * SEQ + qr0 + r) * QKVC + h * HDIM + ch;
        *(uint4*)&smA[r * ASD + ch]        = *(const uint4*)&qh[gi];
        *(uint4*)&smA[QARR + r * ASD + ch] = *(const uint4*)&ql[gi];
    }

    float o[16][4];
#pragma unroll
    for (int nt = 0; nt < 16; nt++)
#pragma unroll
        for (int u = 0; u < 4; u++) o[nt][u] = 0.0f;
    float m0 = -1e30f, m1 = -1e30f, l0 = 0.0f, l1 = 0.0f;

    for (int kt = 0; kt < nkt; kt++) {
        const int s = kt & 1;
        if (kt + 1 < nkt) asm volatile("cp.async.wait_group 1;\n" ::: "memory");
        else              asm volatile("cp.async.wait_group 0;\n" ::: "memory");
        __syncthreads();

        const unsigned OKH = (unsigned)(2 * QARR + s * KVSTAGE) * 2u;
        const unsigned OKL = OKH + KARR * 2;
        const unsigned OVH = OKH + 2 * KARR * 2;
        const unsigned OVL = OKH + 3 * KARR * 2;

        // ---- scores S = Q K^T (rows warp*16..+15, cols 0..63) ----
        float sc[8][4];
#pragma unroll
        for (int nj = 0; nj < 8; nj++)
#pragma unroll
            for (int u = 0; u < 4; u++) sc[nj][u] = 0.0f;

#pragma unroll
        for (int kk = 0; kk < 128; kk += 16) {
            unsigned ah4[4], al4[4], bh[16], bl[16];
            const unsigned aoff =
                (unsigned)((warp * 16 + lm7 + (mat & 1) * 8) * ASD + kk + (mat >> 1) * 8) * 2u;
            ldsm_x4(ah4, smb + aoff);
            ldsm_x4(al4, smb + QARR * 2 + aoff);
#pragma unroll
            for (int p = 0; p < 4; p++) {
                const unsigned boff =
                    (unsigned)((p * 16 + lm7 + (mat >> 1) * 8) * ASD + kk + (mat & 1) * 8) * 2u;
                ldsm_x4(&bh[p * 4], OKH + smb + boff);
                ldsm_x4(&bl[p * 4], OKL + smb + boff);
            }
#pragma unroll
            for (int nj = 0; nj < 8; nj++) {
                const unsigned* b1 = &bh[(nj >> 1) * 4 + (nj & 1) * 2];
                const unsigned* b2 = &bl[(nj >> 1) * 4 + (nj & 1) * 2];
                mma_bf16(sc[nj], ah4, b1);
                mma_bf16(sc[nj], ah4, b2);
                mma_bf16(sc[nj], al4, b1);
            }
        }

        // causal mask: key kt*64+cidx > q row qr0 + warp*16 + g(+8)
        if (kt >= 2 * qt) {
            const int koff = kt * 64 - qr0;                  // 0 or 64
            const int r0 = warp * 16 + g, r1 = r0 + 8;
#pragma unroll
            for (int nj = 0; nj < 8; nj++)
#pragma unroll
                for (int e = 0; e < 2; e++) {
                    const int cidx = nj * 8 + tq * 2 + e + koff;
                    if (cidx > r0) sc[nj][e]     = -1e30f;
                    if (cidx > r1) sc[nj][2 + e] = -1e30f;
                }
        }

        // ---- online softmax ----
        float mx0 = -1e30f, mx1 = -1e30f;
#pragma unroll
        for (int nj = 0; nj < 8; nj++) {
            mx0 = fmaxf(mx0, fmaxf(sc[nj][0], sc[nj][1]));
            mx1 = fmaxf(mx1, fmaxf(sc[nj][2], sc[nj][3]));
        }
        mx0 = fmaxf(mx0, __shfl_xor_sync(0xffffffffu, mx0, 1));
        mx0 = fmaxf(mx0, __shfl_xor_sync(0xffffffffu, mx0, 2));
        mx1 = fmaxf(mx1, __shfl_xor_sync(0xffffffffu, mx1, 1));
        mx1 = fmaxf(mx1, __shfl_xor_sync(0xffffffffu, mx1, 2));

        const float mn0 = fmaxf(m0, mx0), mn1 = fmaxf(m1, mx1);
        const float f0 = __expf(m0 - mn0), f1 = __expf(m1 - mn1);
        m0 = mn0; m1 = mn1;

        float s0 = 0.0f, s1 = 0.0f;
        unsigned pah[4][4], pal[4][4];
#pragma unroll
        for (int nj = 0; nj < 8; nj++) {
            const float p0 = __expf(sc[nj][0] - m0);
            const float p1 = __expf(sc[nj][1] - m0);
            const float p2 = __expf(sc[nj][2] - m1);
            const float p3 = __expf(sc[nj][3] - m1);
            s0 += p0 + p1;  s1 += p2 + p3;
            __nv_bfloat16 h0 = __float2bfloat16(p0), h1 = __float2bfloat16(p1);
            __nv_bfloat16 h2 = __float2bfloat16(p2), h3 = __float2bfloat16(p3);
            __nv_bfloat16 e0 = __float2bfloat16(p0 - __bfloat162float(h0));
            __nv_bfloat16 e1 = __float2bfloat16(p1 - __bfloat162float(h1));
            __nv_bfloat16 e2 = __float2bfloat16(p2 - __bfloat162float(h2));
            __nv_bfloat16 e3 = __float2bfloat16(p3 - __bfloat162float(h3));
            const int kb = nj >> 1, hf = (nj & 1) * 2;
            pah[kb][hf + 0] = pk(h0, h1);
            pah[kb][hf + 1] = pk(h2, h3);
            pal[kb][hf + 0] = pk(e0, e1);
            pal[kb][hf + 1] = pk(e2, e3);
        }
        s0 += __shfl_xor_sync(0xffffffffu, s0, 1);
        s0 += __shfl_xor_sync(0xffffffffu, s0, 2);
        s1 += __shfl_xor_sync(0xffffffffu, s1, 1);
        s1 += __shfl_xor_sync(0xffffffffu, s1, 2);
        l0 = l0 * f0 + s0;
        l1 = l1 * f1 + s1;
#pragma unroll
        for (int nt = 0; nt < 16; nt++) {
            o[nt][0] *= f0; o[nt][1] *= f0;
            o[nt][2] *= f1; o[nt][3] *= f1;
        }

        // ---- O += P V ----
#pragma unroll
        for (int kb = 0; kb < 4; kb++) {
#pragma unroll
            for (int ng = 0; ng < 8; ng++) {
                const unsigned voff =
                    (unsigned)((kb * 16 + (mat & 1) * 8 + lm7) * ASD + ng * 16 + (mat >> 1) * 8) * 2u;
                unsigned vh4[4], vl4[4];
                ldsm_x4_t(vh4, OVH + smb + voff);
                ldsm_x4_t(vl4, OVL + smb + voff);
                mma_bf16(o[2 * ng],     pah[kb], vh4);
                mma_bf16(o[2 * ng],     pah[kb], vl4);
                mma_bf16(o[2 * ng],     pal[kb], vh4);
                mma_bf16(o[2 * ng + 1], pah[kb], vh4 + 2);
                mma_bf16(o[2 * ng + 1], pah[kb], vl4 + 2);
                mma_bf16(o[2 * ng + 1], pal[kb], vh4 + 2);
            }
        }

        __syncthreads();                    // all warps done reading stage s
        if (kt + 2 < nkt) {
            kv_fill(smb + (2 * QARR + s * KVSTAGE) * 2, qh, ql, b, kt + 2, kvh, tid);
        }
        cpa_commit();                       // uniform group count across iters
    }

    // ---- epilogue: write bf16 hi/lo ----
    const float i0 = 1.0f / l0, i1 = 1.0f / l1;
    const size_t row0 = (size_t)(b * SEQ + qr0 + warp * 16 + g);
    const size_t row1 = row0 + 8;
#pragma unroll
    for (int nt = 0; nt < 16; nt++) {
        const int col = h * HDIM + nt * 8 + tq * 2;
        const float v0 = o[nt][0] * i0, v1 = o[nt][1] * i0;
        const float v2 = o[nt][2] * i1, v3 = o[nt][3] * i1;
        __nv_bfloat16 h0 = __float2bfloat16(v0), h1 = __float2bfloat16(v1);
        __nv_bfloat16 h2 = __float2bfloat16(v2), h3 = __float2bfloat16(v3);
        *(unsigned*)&oh[row0 * HIDN + col] = pk(h0, h1);
        *(unsigned*)&oh[row1 * HIDN + col] = pk(h2, h3);
        *(unsigned*)&ol[row0 * HIDN + col] =
            pk(__float2bfloat16(v0 - __bfloat162float(h0)),
               __float2bfloat16(v1 - __bfloat162float(h1)));
        *(unsigned*)&ol[row1 * HIDN + col] =
            pk(__float2bfloat16(v2 - __bfloat162float(h2)),
               __float2bfloat16(v3 - __bfloat162float(h3)));
    }
}

// ---------------------------------------------------------------------------
extern "C" void kernel_launch(void* const* d_in, const int* in_sizes, int n_in,
                              void* d_out, int out_size)
{
    const float* hidden = (const float*)d_in[0];
    const float* wq     = (const float*)d_in[1];
    const float* wk     = (const float*)d_in[2];
    const float* wv     = (const float*)d_in[3];
    const float* wo     = (const float*)d_in[4];
    const int*   pos    = (const int*)d_in[6];
    float*       outp   = (float*)d_out;

    float* qkv;  cudaGetSymbolAddress((void**)&qkv,  g_qkv);
    __nv_bfloat16 *qkvh, *qkvl, *hidh, *hidl, *wh, *wl, *woh, *wol, *ath, *atl;
    cudaGetSymbolAddress((void**)&qkvh, g_qkvh);
    cudaGetSymbolAddress((void**)&qkvl, g_qkvl);
    cudaGetSymbolAddress((void**)&hidh, g_hidh);
    cudaGetSymbolAddress((void**)&hidl, g_hidl);
    cudaGetSymbolAddress((void**)&wh,  g_wh);
    cudaGetSymbolAddress((void**)&wl,  g_wl);
    cudaGetSymbolAddress((void**)&woh, g_woh);
    cudaGetSymbolAddress((void**)&wol, g_wol);
    cudaGetSymbolAddress((void**)&ath, g_ath);
    cudaGetSymbolAddress((void**)&atl, g_atl);

    cudaFuncSetAttribute(gemm_pre, cudaFuncAttributeMaxDynamicSharedMemorySize, GEMM_SMEM);
    cudaFuncSetAttribute(attn_tc,  cudaFuncAttributeMaxDynamicSharedMemorySize, ATT_SMEM);

    const int nHid = NNZ * HIDN;
    const int nWqo = HIDN * HIDN;
    const int nWkv = 1024 * HIDN;
    split_kernel<<<nHid / 1024, 256>>>(hidden, hidh, hidl, nHid);
    split_kernel<<<nWqo / 1024, 256>>>(wq, wh,                       wl,                       nWqo);
    split_kernel<<<nWkv / 1024, 256>>>(wk, wh + (size_t)KOFF * HIDN, wl + (size_t)KOFF * HIDN, nWkv);
    split_kernel<<<nWkv / 1024, 256>>>(wv, wh + (size_t)VOFF * HIDN, wl + (size_t)VOFF * HIDN, nWkv);
    split_kernel<<<nWqo / 1024, 256>>>(wo, woh, wol, nWqo);

    // Fused QKV projection: one launch, [4096 x 6144]
    gemm_pre<<<dim3(48, 32), 512, GEMM_SMEM>>>(hidh, hidl, wh, wl, qkv, HIDN, QKVC);

    // RoPE (+Q prescale) and split to bf16 hi/lo
    split_rope_kernel<<<dim3(NNZ, 48), 64>>>(qkv, pos, qkvh, qkvl);

    // Flash attention: 8 q-tiles of 128 rows
    attn_tc<<<dim3(SEQ / 128, NHEAD, NBATCH), 256, ATT_SMEM>>>(qkvh, qkvl, ath, atl);

    // Output projection
    gemm_pre<<<dim3(32, 32), 512, GEMM_SMEM>>>(ath, atl, woh, wol, outp, HIDN, HIDN);
}

// round 8
// speedup vs baseline: 3.7326x; 1.2685x over previous
#include <cuda_runtime.h>
#include <cuda_bf16.h>
#include <cuda_fp16.h>
#include <math.h>

#define NNZ   4096
#define HIDN  4096
#define NHEAD 32
#define NKVH  8
#define HDIM  128
#define SEQ   1024
#define NBATCH 4
#define QKVC  6144
#define KOFF  4096
#define VOFF  5120

// ---------------- persistent scratch ----------------
__device__ float g_qkv[(size_t)NNZ * QKVC];
__device__ __nv_bfloat16 g_qkvh[(size_t)NNZ * QKVC];
__device__ __nv_bfloat16 g_qkvl[(size_t)NNZ * QKVC];
__device__ __nv_bfloat16 g_hidh[(size_t)NNZ * HIDN];
__device__ __nv_bfloat16 g_hidl[(size_t)NNZ * HIDN];
__device__ __nv_bfloat16 g_wh[(size_t)QKVC * HIDN];   // fused [wq;wk;wv] hi
__device__ __nv_bfloat16 g_wl[(size_t)QKVC * HIDN];   // fused lo
__device__ __half g_woh[(size_t)HIDN * HIDN];         // wo, fp16 single
__device__ __half g_ath[(size_t)NNZ * HIDN];          // attention out, fp16

// ---------------- primitives ----------------
__device__ __forceinline__ void ldsm_x4(unsigned* r, unsigned addr) {
    asm volatile("ldmatrix.sync.aligned.m8n8.x4.shared.b16 {%0,%1,%2,%3}, [%4];\n"
                 : "=r"(r[0]), "=r"(r[1]), "=r"(r[2]), "=r"(r[3]) : "r"(addr));
}
__device__ __forceinline__ void ldsm_x4_t(unsigned* r, unsigned addr) {
    asm volatile("ldmatrix.sync.aligned.m8n8.x4.trans.shared.b16 {%0,%1,%2,%3}, [%4];\n"
                 : "=r"(r[0]), "=r"(r[1]), "=r"(r[2]), "=r"(r[3]) : "r"(addr));
}
__device__ __forceinline__ void mma_bf16(float* c, const unsigned* a, const unsigned* b) {
    asm volatile(
        "mma.sync.aligned.m16n8k16.row.col.f32.bf16.bf16.f32 "
        "{%0,%1,%2,%3}, {%4,%5,%6,%7}, {%8,%9}, {%0,%1,%2,%3};\n"
        : "+f"(c[0]), "+f"(c[1]), "+f"(c[2]), "+f"(c[3])
        : "r"(a[0]), "r"(a[1]), "r"(a[2]), "r"(a[3]), "r"(b[0]), "r"(b[1]));
}
__device__ __forceinline__ void mma_f16(float* c, const unsigned* a, const unsigned* b) {
    asm volatile(
        "mma.sync.aligned.m16n8k16.row.col.f32.f16.f16.f32 "
        "{%0,%1,%2,%3}, {%4,%5,%6,%7}, {%8,%9}, {%0,%1,%2,%3};\n"
        : "+f"(c[0]), "+f"(c[1]), "+f"(c[2]), "+f"(c[3])
        : "r"(a[0]), "r"(a[1]), "r"(a[2]), "r"(a[3]), "r"(b[0]), "r"(b[1]));
}
__device__ __forceinline__ unsigned pk(__nv_bfloat16 a, __nv_bfloat16 b) {
    __nv_bfloat162 t(a, b);
    return *reinterpret_cast<unsigned*>(&t);
}
__device__ __forceinline__ void cpa16(unsigned dst, const void* src) {
    asm volatile("cp.async.cg.shared.global [%0], [%1], 16;\n" :: "r"(dst), "l"(src));
}
__device__ __forceinline__ void cpa_commit() { asm volatile("cp.async.commit_group;\n"); }

// ---------------- conversion kernels ----------------
__global__ void split_kernel(const float* __restrict__ src,
                             __nv_bfloat16* __restrict__ hi,
                             __nv_bfloat16* __restrict__ lo, int n)
{
    int i = (blockIdx.x * blockDim.x + threadIdx.x) * 4;
    if (i >= n) return;
    float4 v = *(const float4*)(src + i);
    __nv_bfloat16 h0 = __float2bfloat16(v.x), h1 = __float2bfloat16(v.y);
    __nv_bfloat16 h2 = __float2bfloat16(v.z), h3 = __float2bfloat16(v.w);
    __nv_bfloat16 l0 = __float2bfloat16(v.x - __bfloat162float(h0));
    __nv_bfloat16 l1 = __float2bfloat16(v.y - __bfloat162float(h1));
    __nv_bfloat16 l2 = __float2bfloat16(v.z - __bfloat162float(h2));
    __nv_bfloat16 l3 = __float2bfloat16(v.w - __bfloat162float(h3));
    *(uint2*)(hi + i) = make_uint2(pk(h0, h1), pk(h2, h3));
    *(uint2*)(lo + i) = make_uint2(pk(l0, l1), pk(l2, l3));
}

__global__ void half_kernel(const float* __restrict__ src,
                            __half* __restrict__ dst, int n)
{
    int i = (blockIdx.x * blockDim.x + threadIdx.x) * 4;
    if (i >= n) return;
    float4 v = *(const float4*)(src + i);
    __half2 a = __floats2half2_rn(v.x, v.y);
    __half2 b = __floats2half2_rn(v.z, v.w);
    *(uint2*)(dst + i) = make_uint2(*(unsigned*)&a, *(unsigned*)&b);
}

// RoPE + split for qkv. grid (NNZ, 48), block 64.
__global__ void split_rope_kernel(const float* __restrict__ qkv,
                                  const int* __restrict__ pos,
                                  __nv_bfloat16* __restrict__ qh,
                                  __nv_bfloat16* __restrict__ ql)
{
    const int tok = blockIdx.x;
    const int hb  = blockIdx.y;
    const int d   = threadIdx.x;
    const size_t base = (size_t)tok * QKVC + hb * HDIM;
    float x1 = qkv[base + d], x2 = qkv[base + d + 64];

    if (hb < 40) {
        float freq = powf(500000.0f, -(float)d / 64.0f);
        const float wl = 6.283185307179586f / freq;
        float f;
        if (wl < 2048.0f)       f = freq;
        else if (wl > 8192.0f)  f = freq * 0.125f;
        else {
            float smooth = (8192.0f / wl - 1.0f) * (1.0f / 3.0f);
            f = (1.0f - smooth) * freq * 0.125f + smooth * freq;
        }
        const float ang = (float)pos[tok] * f;
        const float c = cosf(ang), s = sinf(ang);
        float y1 = x1 * c - x2 * s;
        float y2 = x2 * c + x1 * s;
        if (hb < 32) { y1 *= 0.08838834764831845f; y2 *= 0.08838834764831845f; }
        x1 = y1; x2 = y2;
    }
    __nv_bfloat16 h1 = __float2bfloat16(x1), h2 = __float2bfloat16(x2);
    qh[base + d]      = h1;
    qh[base + d + 64] = h2;
    ql[base + d]      = __float2bfloat16(x1 - __bfloat162float(h1));
    ql[base + d + 64] = __float2bfloat16(x2 - __bfloat162float(h2));
}

// ---------------------------------------------------------------------------
// Pre-split bf16x3 GEMM (mma.sync). Unchanged from round 6. QKV only.
// ---------------------------------------------------------------------------
#define GSTRIDE 40
#define G_ARR_BYTES (128 * GSTRIDE * 2)
#define G_STAGE_BYTES (4 * G_ARR_BYTES)
#define NSTAGE 4
#define GEMM_SMEM (NSTAGE * G_STAGE_BYTES)

__global__ void __launch_bounds__(512) gemm_pre(
    const __nv_bfloat16* __restrict__ Ahi, const __nv_bfloat16* __restrict__ Alo,
    const __nv_bfloat16* __restrict__ Bhi, const __nv_bfloat16* __restrict__ Blo,
    float* __restrict__ C, int K, int ldc)
{
    extern __shared__ __nv_bfloat16 dsm[];
    const unsigned smb = (unsigned)__cvta_generic_to_shared(dsm);

    const int bm = blockIdx.y * 128;
    const int bn = blockIdx.x * 128;
    const int t  = threadIdx.x;
    const int lane = t & 31;
    const int warp = t >> 5;
    const int wm = (warp & 3) * 32;
    const int wn = (warp >> 2) * 32;

    const int ldRow = t >> 2;
    const int ldCh  = (t & 3) * 8;
    const size_t aOff = (size_t)(bm + ldRow) * K + ldCh;
    const size_t bOff = (size_t)(bn + ldRow) * K + ldCh;
    const unsigned dOff = (unsigned)(ldRow * GSTRIDE + ldCh) * 2u;

    const int mat = lane >> 3;
    const int aRow = wm + (lane & 7) + (mat & 1) * 8;
    const int aColAdd = (mat >> 1) * 8;
    const int bRow = wn + (lane & 7) + (mat >> 1) * 8;
    const int bColAdd = (mat & 1) * 8;

    float acc[2][4][4];
#pragma unroll
    for (int mi = 0; mi < 2; mi++)
#pragma unroll
        for (int nj = 0; nj < 4; nj++)
#pragma unroll
            for (int u = 0; u < 4; u++) acc[mi][nj][u] = 0.0f;

    const int nt = K / 32;

#pragma unroll
    for (int s = 0; s < NSTAGE - 1; s++) {
        unsigned d0 = smb + s * G_STAGE_BYTES + dOff;
        const int kn = s * 32;
        cpa16(d0,                   Ahi + aOff + kn);
        cpa16(d0 + G_ARR_BYTES,     Alo + aOff + kn);
        cpa16(d0 + 2 * G_ARR_BYTES, Bhi + bOff + kn);
        cpa16(d0 + 3 * G_ARR_BYTES, Blo + bOff + kn);
        cpa_commit();
    }

    for (int i = 0; i < nt; i++) {
        if (i + NSTAGE - 1 < nt) {
            unsigned d0 = smb + ((i + NSTAGE - 1) & (NSTAGE - 1)) * G_STAGE_BYTES + dOff;
            const int kn = (i + NSTAGE - 1) * 32;
            cpa16(d0,                   Ahi + aOff + kn);
            cpa16(d0 + G_ARR_BYTES,     Alo + aOff + kn);
            cpa16(d0 + 2 * G_ARR_BYTES, Bhi + bOff + kn);
            cpa16(d0 + 3 * G_ARR_BYTES, Blo + bOff + kn);
        }
        cpa_commit();
        asm volatile("cp.async.wait_group %0;\n" :: "n"(NSTAGE - 1));
        __syncthreads();

        const unsigned st = smb + (i & (NSTAGE - 1)) * G_STAGE_BYTES;
        const unsigned bAhi = st;
        const unsigned bAlo = st + G_ARR_BYTES;
        const unsigned bBhi = st + 2 * G_ARR_BYTES;
        const unsigned bBlo = st + 3 * G_ARR_BYTES;

#pragma unroll
        for (int kk = 0; kk < 32; kk += 16) {
            unsigned ahi[2][4], alo[2][4], bhi[8], blo[8];
#pragma unroll
            for (int mi = 0; mi < 2; mi++) {
                unsigned off = (unsigned)((aRow + mi * 16) * GSTRIDE + kk + aColAdd) * 2u;
                ldsm_x4(ahi[mi], bAhi + off);
                ldsm_x4(alo[mi], bAlo + off);
            }
#pragma unroll
            for (int p = 0; p < 2; p++) {
                unsigned off = (unsigned)((bRow + p * 16) * GSTRIDE + kk + bColAdd) * 2u;
                ldsm_x4(&bhi[p * 4], bBhi + off);
                ldsm_x4(&blo[p * 4], bBlo + off);
            }
#pragma unroll
            for (int mi = 0; mi < 2; mi++)
#pragma unroll
                for (int nj = 0; nj < 4; nj++) {
                    const unsigned* bh = &bhi[(nj >> 1) * 4 + (nj & 1) * 2];
                    const unsigned* bl = &blo[(nj >> 1) * 4 + (nj & 1) * 2];
                    mma_bf16(acc[mi][nj], ahi[mi], bh);
                    mma_bf16(acc[mi][nj], ahi[mi], bl);
                    mma_bf16(acc[mi][nj], alo[mi], bh);
                }
        }
        __syncthreads();
    }

    const int g = lane >> 2;
    const int tq = lane & 3;
#pragma unroll
    for (int mi = 0; mi < 2; mi++) {
        const int row0 = bm + wm + mi * 16 + g;
#pragma unroll
        for (int nj = 0; nj < 4; nj++) {
            const int col = bn + wn + nj * 8 + tq * 2;
            *(float2*)(C + (size_t)row0 * ldc + col) =
                make_float2(acc[mi][nj][0], acc[mi][nj][1]);
            *(float2*)(C + (size_t)(row0 + 8) * ldc + col) =
                make_float2(acc[mi][nj][2], acc[mi][nj][3]);
        }
    }
}

// ---------------------------------------------------------------------------
// Single-term fp16 GEMM (mma.sync): C = A B^T, A/B fp16. 1/3 the mma count of
// bf16x3. Used for the WO projection (no exp-amplification of its errors).
// 128x128 tile, BK=32, 512 threads, 4-stage cp.async.
// ---------------------------------------------------------------------------
#define H_STAGE_BYTES (2 * G_ARR_BYTES)          // 20480
#define GEMMH_SMEM (NSTAGE * H_STAGE_BYTES)      // 81920

__global__ void __launch_bounds__(512) gemm_f16(
    const __half* __restrict__ A, const __half* __restrict__ B,
    float* __restrict__ C, int K, int ldc)
{
    extern __shared__ __half hsm[];
    const unsigned smb = (unsigned)__cvta_generic_to_shared(hsm);

    const int bm = blockIdx.y * 128;
    const int bn = blockIdx.x * 128;
    const int t  = threadIdx.x;
    const int lane = t & 31;
    const int warp = t >> 5;
    const int wm = (warp & 3) * 32;
    const int wn = (warp >> 2) * 32;

    const int ldRow = t >> 2;
    const int ldCh  = (t & 3) * 8;
    const size_t aOff = (size_t)(bm + ldRow) * K + ldCh;
    const size_t bOff = (size_t)(bn + ldRow) * K + ldCh;
    const unsigned dOff = (unsigned)(ldRow * GSTRIDE + ldCh) * 2u;

    const int mat = lane >> 3;
    const int aRow = wm + (lane & 7) + (mat & 1) * 8;
    const int aColAdd = (mat >> 1) * 8;
    const int bRow = wn + (lane & 7) + (mat >> 1) * 8;
    const int bColAdd = (mat & 1) * 8;

    float acc[2][4][4];
#pragma unroll
    for (int mi = 0; mi < 2; mi++)
#pragma unroll
        for (int nj = 0; nj < 4; nj++)
#pragma unroll
            for (int u = 0; u < 4; u++) acc[mi][nj][u] = 0.0f;

    const int nt = K / 32;

#pragma unroll
    for (int s = 0; s < NSTAGE - 1; s++) {
        unsigned d0 = smb + s * H_STAGE_BYTES + dOff;
        const int kn = s * 32;
        cpa16(d0,               A + aOff + kn);
        cpa16(d0 + G_ARR_BYTES, B + bOff + kn);
        cpa_commit();
    }

    for (int i = 0; i < nt; i++) {
        if (i + NSTAGE - 1 < nt) {
            unsigned d0 = smb + ((i + NSTAGE - 1) & (NSTAGE - 1)) * H_STAGE_BYTES + dOff;
            const int kn = (i + NSTAGE - 1) * 32;
            cpa16(d0,               A + aOff + kn);
            cpa16(d0 + G_ARR_BYTES, B + bOff + kn);
        }
        cpa_commit();
        asm volatile("cp.async.wait_group %0;\n" :: "n"(NSTAGE - 1));
        __syncthreads();

        const unsigned st = smb + (i & (NSTAGE - 1)) * H_STAGE_BYTES;
        const unsigned bA = st;
        const unsigned bB = st + G_ARR_BYTES;

#pragma unroll
        for (int kk = 0; kk < 32; kk += 16) {
            unsigned a4[2][4], b4[8];
#pragma unroll
            for (int mi = 0; mi < 2; mi++) {
                unsigned off = (unsigned)((aRow + mi * 16) * GSTRIDE + kk + aColAdd) * 2u;
                ldsm_x4(a4[mi], bA + off);
            }
#pragma unroll
            for (int p = 0; p < 2; p++) {
                unsigned off = (unsigned)((bRow + p * 16) * GSTRIDE + kk + bColAdd) * 2u;
                ldsm_x4(&b4[p * 4], bB + off);
            }
#pragma unroll
            for (int mi = 0; mi < 2; mi++)
#pragma unroll
                for (int nj = 0; nj < 4; nj++)
                    mma_f16(acc[mi][nj], a4[mi], &b4[(nj >> 1) * 4 + (nj & 1) * 2]);
        }
        __syncthreads();
    }

    const int g = lane >> 2;
    const int tq = lane & 3;
#pragma unroll
    for (int mi = 0; mi < 2; mi++) {
        const int row0 = bm + wm + mi * 16 + g;
#pragma unroll
        for (int nj = 0; nj < 4; nj++) {
            const int col = bn + wn + nj * 8 + tq * 2;
            *(float2*)(C + (size_t)row0 * ldc + col) =
                make_float2(acc[mi][nj][0], acc[mi][nj][1]);
            *(float2*)(C + (size_t)(row0 + 8) * ldc + col) =
                make_float2(acc[mi][nj][2], acc[mi][nj][3]);
        }
    }
}

// ---------------------------------------------------------------------------
// Flash attention (round 7 structure), epilogue now writes fp16 directly.
// ---------------------------------------------------------------------------
#define ASD 136
#define QARR (128 * ASD)
#define KARR (64 * ASD)
#define KVSTAGE (4 * KARR)
#define ATT_SMEM ((2 * QARR + 2 * KVSTAGE) * 2)   // 208896 B

__device__ __forceinline__ void kv_fill(
    unsigned stage_b, const __nv_bfloat16* qh, const __nv_bfloat16* ql,
    int b, int kt, int kvh, int tid)
{
    for (int j = tid; j < 64 * 16; j += 256) {
        const int r = j >> 4, ch = (j & 15) * 8;
        const size_t tr = (size_t)(b * SEQ + kt * 64 + r) * QKVC;
        const size_t ki = tr + KOFF + kvh * HDIM + ch;
        const size_t vi = tr + VOFF + kvh * HDIM + ch;
        const unsigned dst = stage_b + (unsigned)(r * ASD + ch) * 2u;
        cpa16(dst,                 qh + ki);
        cpa16(dst + KARR * 2,      ql + ki);
        cpa16(dst + 2 * KARR * 2,  qh + vi);
        cpa16(dst + 3 * KARR * 2,  ql + vi);
    }
}

__global__ void __launch_bounds__(256) attn_tc(
    const __nv_bfloat16* __restrict__ qh, const __nv_bfloat16* __restrict__ ql,
    __half* __restrict__ oh)
{
    extern __shared__ __nv_bfloat16 smA[];
    const unsigned smb = (unsigned)__cvta_generic_to_shared(smA);

    const int qt  = (int)gridDim.x - 1 - (int)blockIdx.x;
    const int h   = blockIdx.y;
    const int b   = blockIdx.z;
    const int kvh = h >> 2;
    const int tid = threadIdx.x;
    const int lane = tid & 31;
    const int warp = tid >> 5;
    const int qr0 = qt * 128;
    const int mat = lane >> 3;
    const int lm7 = lane & 7;
    const int g   = lane >> 2;
    const int tq  = lane & 3;

    const int nkt = 2 * qt + 2;

    kv_fill(smb + 2 * QARR * 2, qh, ql, b, 0, kvh, tid);
    cpa_commit();
    kv_fill(smb + (2 * QARR + KVSTAGE) * 2, qh, ql, b, 1, kvh, tid);
    cpa_commit();

    for (int j = tid; j < 128 * 16; j += 256) {
        const int r = j >> 4, ch = (j & 15) * 8;
        const size_t gi = (size_t)(b * SEQ + qr0 + r) * QKVC + h * HDIM + ch;
        *(uint4*)&smA[r * ASD + ch]        = *(const uint4*)&qh[gi];
        *(uint4*)&smA[QARR + r * ASD + ch] = *(const uint4*)&ql[gi];
    }

    float o[16][4];
#pragma unroll
    for (int nt = 0; nt < 16; nt++)
#pragma unroll
        for (int u = 0; u < 4; u++) o[nt][u] = 0.0f;
    float m0 = -1e30f, m1 = -1e30f, l0 = 0.0f, l1 = 0.0f;

    for (int kt = 0; kt < nkt; kt++) {
        const int s = kt & 1;
        if (kt + 1 < nkt) asm volatile("cp.async.wait_group 1;\n" ::: "memory");
        else              asm volatile("cp.async.wait_group 0;\n" ::: "memory");
        __syncthreads();

        const unsigned OKH = (unsigned)(2 * QARR + s * KVSTAGE) * 2u;
        const unsigned OKL = OKH + KARR * 2;
        const unsigned OVH = OKH + 2 * KARR * 2;
        const unsigned OVL = OKH + 3 * KARR * 2;

        float sc[8][4];
#pragma unroll
        for (int nj = 0; nj < 8; nj++)
#pragma unroll
            for (int u = 0; u < 4; u++) sc[nj][u] = 0.0f;

#pragma unroll
        for (int kk = 0; kk < 128; kk += 16) {
            unsigned ah4[4], al4[4], bh[16], bl[16];
            const unsigned aoff =
                (unsigned)((warp * 16 + lm7 + (mat & 1) * 8) * ASD + kk + (mat >> 1) * 8) * 2u;
            ldsm_x4(ah4, smb + aoff);
            ldsm_x4(al4, smb + QARR * 2 + aoff);
#pragma unroll
            for (int p = 0; p < 4; p++) {
                const unsigned boff =
                    (unsigned)((p * 16 + lm7 + (mat >> 1) * 8) * ASD + kk + (mat & 1) * 8) * 2u;
                ldsm_x4(&bh[p * 4], OKH + smb + boff);
                ldsm_x4(&bl[p * 4], OKL + smb + boff);
            }
#pragma unroll
            for (int nj = 0; nj < 8; nj++) {
                const unsigned* b1 = &bh[(nj >> 1) * 4 + (nj & 1) * 2];
                const unsigned* b2 = &bl[(nj >> 1) * 4 + (nj & 1) * 2];
                mma_bf16(sc[nj], ah4, b1);
                mma_bf16(sc[nj], ah4, b2);
                mma_bf16(sc[nj], al4, b1);
            }
        }

        if (kt >= 2 * qt) {
            const int koff = kt * 64 - qr0;
            const int r0 = warp * 16 + g, r1 = r0 + 8;
#pragma unroll
            for (int nj = 0; nj < 8; nj++)
#pragma unroll
                for (int e = 0; e < 2; e++) {
                    const int cidx = nj * 8 + tq * 2 + e + koff;
                    if (cidx > r0) sc[nj][e]     = -1e30f;
                    if (cidx > r1) sc[nj][2 + e] = -1e30f;
                }
        }

        float mx0 = -1e30f, mx1 = -1e30f;
#pragma unroll
        for (int nj = 0; nj < 8; nj++) {
            mx0 = fmaxf(mx0, fmaxf(sc[nj][0], sc[nj][1]));
            mx1 = fmaxf(mx1, fmaxf(sc[nj][2], sc[nj][3]));
        }
        mx0 = fmaxf(mx0, __shfl_xor_sync(0xffffffffu, mx0, 1));
        mx0 = fmaxf(mx0, __shfl_xor_sync(0xffffffffu, mx0, 2));
        mx1 = fmaxf(mx1, __shfl_xor_sync(0xffffffffu, mx1, 1));
        mx1 = fmaxf(mx1, __shfl_xor_sync(0xffffffffu, mx1, 2));

        const float mn0 = fmaxf(m0, mx0), mn1 = fmaxf(m1, mx1);
        const float f0 = __expf(m0 - mn0), f1 = __expf(m1 - mn1);
        m0 = mn0; m1 = mn1;

        float s0 = 0.0f, s1 = 0.0f;
        unsigned pah[4][4], pal[4][4];
#pragma unroll
        for (int nj = 0; nj < 8; nj++) {
            const float p0 = __expf(sc[nj][0] - m0);
            const float p1 = __expf(sc[nj][1] - m0);
            const float p2 = __expf(sc[nj][2] - m1);
            const float p3 = __expf(sc[nj][3] - m1);
            s0 += p0 + p1;  s1 += p2 + p3;
            __nv_bfloat16 h0 = __float2bfloat16(p0), h1 = __float2bfloat16(p1);
            __nv_bfloat16 h2 = __float2bfloat16(p2), h3 = __float2bfloat16(p3);
            __nv_bfloat16 e0 = __float2bfloat16(p0 - __bfloat162float(h0));
            __nv_bfloat16 e1 = __float2bfloat16(p1 - __bfloat162float(h1));
            __nv_bfloat16 e2 = __float2bfloat16(p2 - __bfloat162float(h2));
            __nv_bfloat16 e3 = __float2bfloat16(p3 - __bfloat162float(h3));
            const int kb = nj >> 1, hf = (nj & 1) * 2;
            pah[kb][hf + 0] = pk(h0, h1);
            pah[kb][hf + 1] = pk(h2, h3);
            pal[kb][hf + 0] = pk(e0, e1);
            pal[kb][hf + 1] = pk(e2, e3);
        }
        s0 += __shfl_xor_sync(0xffffffffu, s0, 1);
        s0 += __shfl_xor_sync(0xffffffffu, s0, 2);
        s1 += __shfl_xor_sync(0xffffffffu, s1, 1);
        s1 += __shfl_xor_sync(0xffffffffu, s1, 2);
        l0 = l0 * f0 + s0;
        l1 = l1 * f1 + s1;
#pragma unroll
        for (int nt = 0; nt < 16; nt++) {
            o[nt][0] *= f0; o[nt][1] *= f0;
            o[nt][2] *= f1; o[nt][3] *= f1;
        }

#pragma unroll
        for (int kb = 0; kb < 4; kb++) {
#pragma unroll
            for (int ng = 0; ng < 8; ng++) {
                const unsigned voff =
                    (unsigned)((kb * 16 + (mat & 1) * 8 + lm7) * ASD + ng * 16 + (mat >> 1) * 8) * 2u;
                unsigned vh4[4], vl4[4];
                ldsm_x4_t(vh4, OVH + smb + voff);
                ldsm_x4_t(vl4, OVL + smb + voff);
                mma_bf16(o[2 * ng],     pah[kb], vh4);
                mma_bf16(o[2 * ng],     pah[kb], vl4);
                mma_bf16(o[2 * ng],     pal[kb], vh4);
                mma_bf16(o[2 * ng + 1], pah[kb], vh4 + 2);
                mma_bf16(o[2 * ng + 1], pah[kb], vl4 + 2);
                mma_bf16(o[2 * ng + 1], pal[kb], vh4 + 2);
            }
        }

        __syncthreads();
        if (kt + 2 < nkt) {
            kv_fill(smb + (2 * QARR + s * KVSTAGE) * 2, qh, ql, b, kt + 2, kvh, tid);
        }
        cpa_commit();
    }

    // ---- epilogue: write fp16 ----
    const float i0 = 1.0f / l0, i1 = 1.0f / l1;
    const size_t row0 = (size_t)(b * SEQ + qr0 + warp * 16 + g);
    const size_t row1 = row0 + 8;
#pragma unroll
    for (int nt = 0; nt < 16; nt++) {
        const int col = h * HDIM + nt * 8 + tq * 2;
        __half2 v01 = __floats2half2_rn(o[nt][0] * i0, o[nt][1] * i0);
        __half2 v23 = __floats2half2_rn(o[nt][2] * i1, o[nt][3] * i1);
        *(unsigned*)&oh[row0 * HIDN + col] = *(unsigned*)&v01;
        *(unsigned*)&oh[row1 * HIDN + col] = *(unsigned*)&v23;
    }
}

// ---------------------------------------------------------------------------
extern "C" void kernel_launch(void* const* d_in, const int* in_sizes, int n_in,
                              void* d_out, int out_size)
{
    const float* hidden = (const float*)d_in[0];
    const float* wq     = (const float*)d_in[1];
    const float* wk     = (const float*)d_in[2];
    const float* wv     = (const float*)d_in[3];
    const float* wo     = (const float*)d_in[4];
    const int*   pos    = (const int*)d_in[6];
    float*       outp   = (float*)d_out;

    float* qkv;  cudaGetSymbolAddress((void**)&qkv,  g_qkv);
    __nv_bfloat16 *qkvh, *qkvl, *hidh, *hidl, *wh, *wl;
    __half *woh, *ath;
    cudaGetSymbolAddress((void**)&qkvh, g_qkvh);
    cudaGetSymbolAddress((void**)&qkvl, g_qkvl);
    cudaGetSymbolAddress((void**)&hidh, g_hidh);
    cudaGetSymbolAddress((void**)&hidl, g_hidl);
    cudaGetSymbolAddress((void**)&wh,  g_wh);
    cudaGetSymbolAddress((void**)&wl,  g_wl);
    cudaGetSymbolAddress((void**)&woh, g_woh);
    cudaGetSymbolAddress((void**)&ath, g_ath);

    cudaFuncSetAttribute(gemm_pre, cudaFuncAttributeMaxDynamicSharedMemorySize, GEMM_SMEM);
    cudaFuncSetAttribute(gemm_f16, cudaFuncAttributeMaxDynamicSharedMemorySize, GEMMH_SMEM);
    cudaFuncSetAttribute(attn_tc,  cudaFuncAttributeMaxDynamicSharedMemorySize, ATT_SMEM);

    const int nHid = NNZ * HIDN;
    const int nWqo = HIDN * HIDN;
    const int nWkv = 1024 * HIDN;
    split_kernel<<<nHid / 1024, 256>>>(hidden, hidh, hidl, nHid);
    split_kernel<<<nWqo / 1024, 256>>>(wq, wh,                       wl,                       nWqo);
    split_kernel<<<nWkv / 1024, 256>>>(wk, wh + (size_t)KOFF * HIDN, wl + (size_t)KOFF * HIDN, nWkv);
    split_kernel<<<nWkv / 1024, 256>>>(wv, wh + (size_t)VOFF * HIDN, wl + (size_t)VOFF * HIDN, nWkv);
    half_kernel<<<nWqo / 1024, 256>>>(wo, woh, nWqo);

    // Fused QKV projection (bf16x3): one launch, [4096 x 6144]
    gemm_pre<<<dim3(48, 32), 512, GEMM_SMEM>>>(hidh, hidl, wh, wl, qkv, HIDN, QKVC);

    // RoPE (+Q prescale) and split to bf16 hi/lo
    split_rope_kernel<<<dim3(NNZ, 48), 64>>>(qkv, pos, qkvh, qkvl);

    // Flash attention -> fp16 output
    attn_tc<<<dim3(SEQ / 128, NHEAD, NBATCH), 256, ATT_SMEM>>>(qkvh, qkvl, ath);

    // Output projection: fp16 single-term
    gemm_f16<<<dim3(32, 32), 512, GEMMH_SMEM>>>(ath, woh, outp, HIDN, HIDN);
}

// round 9
// speedup vs baseline: 3.9254x; 1.0517x over previous
#include <cuda_runtime.h>
#include <cuda_bf16.h>
#include <cuda_fp16.h>
#include <math.h>

#define NNZ   4096
#define HIDN  4096
#define NHEAD 32
#define NKVH  8
#define HDIM  128
#define SEQ   1024
#define NBATCH 4
#define QKVC  6144
#define KOFF  4096
#define VOFF  5120
#define VCOLS 1024

// ---------------- persistent scratch ----------------
__device__ float g_qkv[(size_t)NNZ * QKVC];
__device__ __nv_bfloat16 g_qkvh[(size_t)NNZ * QKVC];
__device__ __nv_bfloat16 g_qkvl[(size_t)NNZ * QKVC];
__device__ __half g_vf[(size_t)NNZ * VCOLS];          // V post-proj, fp16
__device__ __nv_bfloat16 g_hidh[(size_t)NNZ * HIDN];
__device__ __nv_bfloat16 g_hidl[(size_t)NNZ * HIDN];
__device__ __nv_bfloat16 g_wh[(size_t)QKVC * HIDN];   // fused [wq;wk;wv] hi
__device__ __nv_bfloat16 g_wl[(size_t)QKVC * HIDN];   // fused lo
__device__ __half g_woh[(size_t)HIDN * HIDN];         // wo, fp16 single
__device__ __half g_ath[(size_t)NNZ * HIDN];          // attention out, fp16

// ---------------- primitives ----------------
__device__ __forceinline__ void ldsm_x4(unsigned* r, unsigned addr) {
    asm volatile("ldmatrix.sync.aligned.m8n8.x4.shared.b16 {%0,%1,%2,%3}, [%4];\n"
                 : "=r"(r[0]), "=r"(r[1]), "=r"(r[2]), "=r"(r[3]) : "r"(addr));
}
__device__ __forceinline__ void ldsm_x4_t(unsigned* r, unsigned addr) {
    asm volatile("ldmatrix.sync.aligned.m8n8.x4.trans.shared.b16 {%0,%1,%2,%3}, [%4];\n"
                 : "=r"(r[0]), "=r"(r[1]), "=r"(r[2]), "=r"(r[3]) : "r"(addr));
}
__device__ __forceinline__ void mma_bf16(float* c, const unsigned* a, const unsigned* b) {
    asm volatile(
        "mma.sync.aligned.m16n8k16.row.col.f32.bf16.bf16.f32 "
        "{%0,%1,%2,%3}, {%4,%5,%6,%7}, {%8,%9}, {%0,%1,%2,%3};\n"
        : "+f"(c[0]), "+f"(c[1]), "+f"(c[2]), "+f"(c[3])
        : "r"(a[0]), "r"(a[1]), "r"(a[2]), "r"(a[3]), "r"(b[0]), "r"(b[1]));
}
__device__ __forceinline__ void mma_f16(float* c, const unsigned* a, const unsigned* b) {
    asm volatile(
        "mma.sync.aligned.m16n8k16.row.col.f32.f16.f16.f32 "
        "{%0,%1,%2,%3}, {%4,%5,%6,%7}, {%8,%9}, {%0,%1,%2,%3};\n"
        : "+f"(c[0]), "+f"(c[1]), "+f"(c[2]), "+f"(c[3])
        : "r"(a[0]), "r"(a[1]), "r"(a[2]), "r"(a[3]), "r"(b[0]), "r"(b[1]));
}
__device__ __forceinline__ unsigned pk(__nv_bfloat16 a, __nv_bfloat16 b) {
    __nv_bfloat162 t(a, b);
    return *reinterpret_cast<unsigned*>(&t);
}
__device__ __forceinline__ void cpa16(unsigned dst, const void* src) {
    asm volatile("cp.async.cg.shared.global [%0], [%1], 16;\n" :: "r"(dst), "l"(src));
}
__device__ __forceinline__ void cpa_commit() { asm volatile("cp.async.commit_group;\n"); }

// ---------------- conversion kernels ----------------
__global__ void split_kernel(const float* __restrict__ src,
                             __nv_bfloat16* __restrict__ hi,
                             __nv_bfloat16* __restrict__ lo, int n)
{
    int i = (blockIdx.x * blockDim.x + threadIdx.x) * 4;
    if (i >= n) return;
    float4 v = *(const float4*)(src + i);
    __nv_bfloat16 h0 = __float2bfloat16(v.x), h1 = __float2bfloat16(v.y);
    __nv_bfloat16 h2 = __float2bfloat16(v.z), h3 = __float2bfloat16(v.w);
    __nv_bfloat16 l0 = __float2bfloat16(v.x - __bfloat162float(h0));
    __nv_bfloat16 l1 = __float2bfloat16(v.y - __bfloat162float(h1));
    __nv_bfloat16 l2 = __float2bfloat16(v.z - __bfloat162float(h2));
    __nv_bfloat16 l3 = __float2bfloat16(v.w - __bfloat162float(h3));
    *(uint2*)(hi + i) = make_uint2(pk(h0, h1), pk(h2, h3));
    *(uint2*)(lo + i) = make_uint2(pk(l0, l1), pk(l2, l3));
}

__global__ void half_kernel(const float* __restrict__ src,
                            __half* __restrict__ dst, int n)
{
    int i = (blockIdx.x * blockDim.x + threadIdx.x) * 4;
    if (i >= n) return;
    float4 v = *(const float4*)(src + i);
    __half2 a = __floats2half2_rn(v.x, v.y);
    __half2 b = __floats2half2_rn(v.z, v.w);
    *(uint2*)(dst + i) = make_uint2(*(unsigned*)&a, *(unsigned*)&b);
}

// RoPE + split for qkv. grid (NNZ, 48), block 64.
// hb 0..31: Q (rope + prescale, bf16 hi/lo). 32..39: K (rope, bf16 hi/lo).
// 40..47: V (straight fp16 store into g_vf).
__global__ void split_rope_kernel(const float* __restrict__ qkv,
                                  const int* __restrict__ pos,
                                  __nv_bfloat16* __restrict__ qh,
                                  __nv_bfloat16* __restrict__ ql,
                                  __half* __restrict__ vf)
{
    const int tok = blockIdx.x;
    const int hb  = blockIdx.y;
    const int d   = threadIdx.x;
    const size_t base = (size_t)tok * QKVC + hb * HDIM;
    float x1 = qkv[base + d], x2 = qkv[base + d + 64];

    if (hb >= 40) {
        const size_t vb = (size_t)tok * VCOLS + (hb - 40) * HDIM;
        vf[vb + d]      = __float2half_rn(x1);
        vf[vb + d + 64] = __float2half_rn(x2);
        return;
    }

    // freq = 500000^(-d/64) = 2^(-d * log2(5e5)/64)
    float freq = exp2f(-0.29580575860567744f * (float)d);
    const float wl = 6.283185307179586f / freq;
    float f;
    if (wl < 2048.0f)       f = freq;
    else if (wl > 8192.0f)  f = freq * 0.125f;
    else {
        float smooth = (8192.0f / wl - 1.0f) * (1.0f / 3.0f);
        f = (1.0f - smooth) * freq * 0.125f + smooth * freq;
    }
    const float ang = (float)pos[tok] * f;
    const float c = cosf(ang), s = sinf(ang);
    float y1 = x1 * c - x2 * s;
    float y2 = x2 * c + x1 * s;
    if (hb < 32) { y1 *= 0.08838834764831845f; y2 *= 0.08838834764831845f; }

    __nv_bfloat16 h1 = __float2bfloat16(y1), h2 = __float2bfloat16(y2);
    qh[base + d]      = h1;
    qh[base + d + 64] = h2;
    ql[base + d]      = __float2bfloat16(y1 - __bfloat162float(h1));
    ql[base + d + 64] = __float2bfloat16(y2 - __bfloat162float(h2));
}

// ---------------------------------------------------------------------------
// Pre-split bf16x3 GEMM (mma.sync). 4-stage cp.async, ONE barrier per iter.
// ---------------------------------------------------------------------------
#define GSTRIDE 40
#define G_ARR_BYTES (128 * GSTRIDE * 2)
#define G_STAGE_BYTES (4 * G_ARR_BYTES)
#define NSTAGE 4
#define GEMM_SMEM (NSTAGE * G_STAGE_BYTES)

__global__ void __launch_bounds__(512) gemm_pre(
    const __nv_bfloat16* __restrict__ Ahi, const __nv_bfloat16* __restrict__ Alo,
    const __nv_bfloat16* __restrict__ Bhi, const __nv_bfloat16* __restrict__ Blo,
    float* __restrict__ C, int K, int ldc)
{
    extern __shared__ __nv_bfloat16 dsm[];
    const unsigned smb = (unsigned)__cvta_generic_to_shared(dsm);

    const int bm = blockIdx.y * 128;
    const int bn = blockIdx.x * 128;
    const int t  = threadIdx.x;
    const int lane = t & 31;
    const int warp = t >> 5;
    const int wm = (warp & 3) * 32;
    const int wn = (warp >> 2) * 32;

    const int ldRow = t >> 2;
    const int ldCh  = (t & 3) * 8;
    const size_t aOff = (size_t)(bm + ldRow) * K + ldCh;
    const size_t bOff = (size_t)(bn + ldRow) * K + ldCh;
    const unsigned dOff = (unsigned)(ldRow * GSTRIDE + ldCh) * 2u;

    const int mat = lane >> 3;
    const int aRow = wm + (lane & 7) + (mat & 1) * 8;
    const int aColAdd = (mat >> 1) * 8;
    const int bRow = wn + (lane & 7) + (mat >> 1) * 8;
    const int bColAdd = (mat & 1) * 8;

    float acc[2][4][4];
#pragma unroll
    for (int mi = 0; mi < 2; mi++)
#pragma unroll
        for (int nj = 0; nj < 4; nj++)
#pragma unroll
            for (int u = 0; u < 4; u++) acc[mi][nj][u] = 0.0f;

    const int nt = K / 32;

#pragma unroll
    for (int s = 0; s < NSTAGE - 1; s++) {
        unsigned d0 = smb + s * G_STAGE_BYTES + dOff;
        const int kn = s * 32;
        cpa16(d0,                   Ahi + aOff + kn);
        cpa16(d0 + G_ARR_BYTES,     Alo + aOff + kn);
        cpa16(d0 + 2 * G_ARR_BYTES, Bhi + bOff + kn);
        cpa16(d0 + 3 * G_ARR_BYTES, Blo + bOff + kn);
        cpa_commit();
    }

    for (int i = 0; i < nt; i++) {
        asm volatile("cp.async.wait_group %0;\n" :: "n"(NSTAGE - 2));
        __syncthreads();   // stage i visible; all warps done with stage i-1

        const unsigned st = smb + (i & (NSTAGE - 1)) * G_STAGE_BYTES;
        const unsigned bAhi = st;
        const unsigned bAlo = st + G_ARR_BYTES;
        const unsigned bBhi = st + 2 * G_ARR_BYTES;
        const unsigned bBlo = st + 3 * G_ARR_BYTES;

#pragma unroll
        for (int kk = 0; kk < 32; kk += 16) {
            unsigned ahi[2][4], alo[2][4], bhi[8], blo[8];
#pragma unroll
            for (int mi = 0; mi < 2; mi++) {
                unsigned off = (unsigned)((aRow + mi * 16) * GSTRIDE + kk + aColAdd) * 2u;
                ldsm_x4(ahi[mi], bAhi + off);
                ldsm_x4(alo[mi], bAlo + off);
            }
#pragma unroll
            for (int p = 0; p < 2; p++) {
                unsigned off = (unsigned)((bRow + p * 16) * GSTRIDE + kk + bColAdd) * 2u;
                ldsm_x4(&bhi[p * 4], bBhi + off);
                ldsm_x4(&blo[p * 4], bBlo + off);
            }
#pragma unroll
            for (int mi = 0; mi < 2; mi++)
#pragma unroll
                for (int nj = 0; nj < 4; nj++) {
                    const unsigned* bh = &bhi[(nj >> 1) * 4 + (nj & 1) * 2];
                    const unsigned* bl = &blo[(nj >> 1) * 4 + (nj & 1) * 2];
                    mma_bf16(acc[mi][nj], ahi[mi], bh);
                    mma_bf16(acc[mi][nj], ahi[mi], bl);
                    mma_bf16(acc[mi][nj], alo[mi], bh);
                }
        }

        if (i + NSTAGE - 1 < nt) {
            // writes stage (i-1)&3 — safe: barrier above certified all warps
            // finished compute(i-1)
            unsigned d0 = smb + ((i + NSTAGE - 1) & (NSTAGE - 1)) * G_STAGE_BYTES + dOff;
            const int kn = (i + NSTAGE - 1) * 32;
            cpa16(d0,                   Ahi + aOff + kn);
            cpa16(d0 + G_ARR_BYTES,     Alo + aOff + kn);
            cpa16(d0 + 2 * G_ARR_BYTES, Bhi + bOff + kn);
            cpa16(d0 + 3 * G_ARR_BYTES, Blo + bOff + kn);
        }
        cpa_commit();
    }

    const int g = lane >> 2;
    const int tq = lane & 3;
#pragma unroll
    for (int mi = 0; mi < 2; mi++) {
        const int row0 = bm + wm + mi * 16 + g;
#pragma unroll
        for (int nj = 0; nj < 4; nj++) {
            const int col = bn + wn + nj * 8 + tq * 2;
            *(float2*)(C + (size_t)row0 * ldc + col) =
                make_float2(acc[mi][nj][0], acc[mi][nj][1]);
            *(float2*)(C + (size_t)(row0 + 8) * ldc + col) =
                make_float2(acc[mi][nj][2], acc[mi][nj][3]);
        }
    }
}

// ---------------------------------------------------------------------------
// Single-term fp16 GEMM (WO). 4-stage cp.async, one barrier per iter.
// ---------------------------------------------------------------------------
#define H_STAGE_BYTES (2 * G_ARR_BYTES)
#define GEMMH_SMEM (NSTAGE * H_STAGE_BYTES)

__global__ void __launch_bounds__(512) gemm_f16(
    const __half* __restrict__ A, const __half* __restrict__ B,
    float* __restrict__ C, int K, int ldc)
{
    extern __shared__ __half hsm[];
    const unsigned smb = (unsigned)__cvta_generic_to_shared(hsm);

    const int bm = blockIdx.y * 128;
    const int bn = blockIdx.x * 128;
    const int t  = threadIdx.x;
    const int lane = t & 31;
    const int warp = t >> 5;
    const int wm = (warp & 3) * 32;
    const int wn = (warp >> 2) * 32;

    const int ldRow = t >> 2;
    const int ldCh  = (t & 3) * 8;
    const size_t aOff = (size_t)(bm + ldRow) * K + ldCh;
    const size_t bOff = (size_t)(bn + ldRow) * K + ldCh;
    const unsigned dOff = (unsigned)(ldRow * GSTRIDE + ldCh) * 2u;

    const int mat = lane >> 3;
    const int aRow = wm + (lane & 7) + (mat & 1) * 8;
    const int aColAdd = (mat >> 1) * 8;
    const int bRow = wn + (lane & 7) + (mat >> 1) * 8;
    const int bColAdd = (mat & 1) * 8;

    float acc[2][4][4];
#pragma unroll
    for (int mi = 0; mi < 2; mi++)
#pragma unroll
        for (int nj = 0; nj < 4; nj++)
#pragma unroll
            for (int u = 0; u < 4; u++) acc[mi][nj][u] = 0.0f;

    const int nt = K / 32;

#pragma unroll
    for (int s = 0; s < NSTAGE - 1; s++) {
        unsigned d0 = smb + s * H_STAGE_BYTES + dOff;
        const int kn = s * 32;
        cpa16(d0,               A + aOff + kn);
        cpa16(d0 + G_ARR_BYTES, B + bOff + kn);
        cpa_commit();
    }

    for (int i = 0; i < nt; i++) {
        asm volatile("cp.async.wait_group %0;\n" :: "n"(NSTAGE - 2));
        __syncthreads();

        const unsigned st = smb + (i & (NSTAGE - 1)) * H_STAGE_BYTES;
        const unsigned bA = st;
        const unsigned bB = st + G_ARR_BYTES;

#pragma unroll
        for (int kk = 0; kk < 32; kk += 16) {
            unsigned a4[2][4], b4[8];
#pragma unroll
            for (int mi = 0; mi < 2; mi++) {
                unsigned off = (unsigned)((aRow + mi * 16) * GSTRIDE + kk + aColAdd) * 2u;
                ldsm_x4(a4[mi], bA + off);
            }
#pragma unroll
            for (int p = 0; p < 2; p++) {
                unsigned off = (unsigned)((bRow + p * 16) * GSTRIDE + kk + bColAdd) * 2u;
                ldsm_x4(&b4[p * 4], bB + off);
            }
#pragma unroll
            for (int mi = 0; mi < 2; mi++)
#pragma unroll
                for (int nj = 0; nj < 4; nj++)
                    mma_f16(acc[mi][nj], a4[mi], &b4[(nj >> 1) * 4 + (nj & 1) * 2]);
        }

        if (i + NSTAGE - 1 < nt) {
            unsigned d0 = smb + ((i + NSTAGE - 1) & (NSTAGE - 1)) * H_STAGE_BYTES + dOff;
            const int kn = (i + NSTAGE - 1) * 32;
            cpa16(d0,               A + aOff + kn);
            cpa16(d0 + G_ARR_BYTES, B + bOff + kn);
        }
        cpa_commit();
    }

    const int g = lane >> 2;
    const int tq = lane & 3;
#pragma unroll
    for (int mi = 0; mi < 2; mi++) {
        const int row0 = bm + wm + mi * 16 + g;
#pragma unroll
        for (int nj = 0; nj < 4; nj++) {
            const int col = bn + wn + nj * 8 + tq * 2;
            *(float2*)(C + (size_t)row0 * ldc + col) =
                make_float2(acc[mi][nj][0], acc[mi][nj][1]);
            *(float2*)(C + (size_t)(row0 + 8) * ldc + col) =
                make_float2(acc[mi][nj][2], acc[mi][nj][3]);
        }
    }
}

// ---------------------------------------------------------------------------
// Flash attention: QK bf16x3, PV fp16 single x single.
// Q-tile 128 rows, 256 threads, K/V stages: (Khi, Klo bf16; V fp16).
// ---------------------------------------------------------------------------
#define ASD 136
#define QARR_B (128 * ASD * 2)              // 34816 B per Q array
#define KARR_B (64 * ASD * 2)               // 17408 B per K/V array
#define KVSTAGE_B (3 * KARR_B)              // 52224 B (Khi, Klo, Vf16)
#define ATT_SMEM (2 * QARR_B + 2 * KVSTAGE_B)   // 174080 B

__device__ __forceinline__ void kv_fill(
    unsigned stage_b, const __nv_bfloat16* qh, const __nv_bfloat16* ql,
    const __half* vf, int b, int kt, int kvh, int tid)
{
    for (int j = tid; j < 64 * 16; j += 256) {
        const int r = j >> 4, ch = (j & 15) * 8;
        const int ktok = b * SEQ + kt * 64 + r;
        const size_t ki = (size_t)ktok * QKVC + KOFF + kvh * HDIM + ch;
        const size_t vi = (size_t)ktok * VCOLS + kvh * HDIM + ch;
        const unsigned dst = stage_b + (unsigned)(r * ASD + ch) * 2u;
        cpa16(dst,              qh + ki);
        cpa16(dst + KARR_B,     ql + ki);
        cpa16(dst + 2 * KARR_B, vf + vi);
    }
}

__global__ void __launch_bounds__(256) attn_tc(
    const __nv_bfloat16* __restrict__ qh, const __nv_bfloat16* __restrict__ ql,
    const __half* __restrict__ vf, __half* __restrict__ oh)
{
    extern __shared__ __nv_bfloat16 smA[];
    const unsigned smb = (unsigned)__cvta_generic_to_shared(smA);

    const int qt  = (int)gridDim.x - 1 - (int)blockIdx.x;
    const int h   = blockIdx.y;
    const int b   = blockIdx.z;
    const int kvh = h >> 2;
    const int tid = threadIdx.x;
    const int lane = tid & 31;
    const int warp = tid >> 5;
    const int qr0 = qt * 128;
    const int mat = lane >> 3;
    const int lm7 = lane & 7;
    const int g   = lane >> 2;
    const int tq  = lane & 3;

    const int nkt = 2 * qt + 2;

    kv_fill(smb + 2 * QARR_B, qh, ql, vf, b, 0, kvh, tid);
    cpa_commit();
    kv_fill(smb + 2 * QARR_B + KVSTAGE_B, qh, ql, vf, b, 1, kvh, tid);
    cpa_commit();

    for (int j = tid; j < 128 * 16; j += 256) {
        const int r = j >> 4, ch = (j & 15) * 8;
        const size_t gi = (size_t)(b * SEQ + qr0 + r) * QKVC + h * HDIM + ch;
        *(uint4*)&smA[r * ASD + ch]              = *(const uint4*)&qh[gi];
        *(uint4*)&smA[128 * ASD + r * ASD + ch]  = *(const uint4*)&ql[gi];
    }

    float o[16][4];
#pragma unroll
    for (int nt = 0; nt < 16; nt++)
#pragma unroll
        for (int u = 0; u < 4; u++) o[nt][u] = 0.0f;
    float m0 = -1e30f, m1 = -1e30f, l0 = 0.0f, l1 = 0.0f;

    for (int kt = 0; kt < nkt; kt++) {
        const int s = kt & 1;
        if (kt + 1 < nkt) asm volatile("cp.async.wait_group 1;\n" ::: "memory");
        else              asm volatile("cp.async.wait_group 0;\n" ::: "memory");
        __syncthreads();

        const unsigned OKH = (unsigned)(2 * QARR_B + s * KVSTAGE_B);
        const unsigned OKL = OKH + KARR_B;
        const unsigned OVF = OKH + 2 * KARR_B;

        float sc[8][4];
#pragma unroll
        for (int nj = 0; nj < 8; nj++)
#pragma unroll
            for (int u = 0; u < 4; u++) sc[nj][u] = 0.0f;

#pragma unroll
        for (int kk = 0; kk < 128; kk += 16) {
            unsigned ah4[4], al4[4], bh[16], bl[16];
            const unsigned aoff =
                (unsigned)((warp * 16 + lm7 + (mat & 1) * 8) * ASD + kk + (mat >> 1) * 8) * 2u;
            ldsm_x4(ah4, smb + aoff);
            ldsm_x4(al4, smb + QARR_B + aoff);
#pragma unroll
            for (int p = 0; p < 4; p++) {
                const unsigned boff =
                    (unsigned)((p * 16 + lm7 + (mat >> 1) * 8) * ASD + kk + (mat & 1) * 8) * 2u;
                ldsm_x4(&bh[p * 4], OKH + smb + boff);
                ldsm_x4(&bl[p * 4], OKL + smb + boff);
            }
#pragma unroll
            for (int nj = 0; nj < 8; nj++) {
                const unsigned* b1 = &bh[(nj >> 1) * 4 + (nj & 1) * 2];
                const unsigned* b2 = &bl[(nj >> 1) * 4 + (nj & 1) * 2];
                mma_bf16(sc[nj], ah4, b1);
                mma_bf16(sc[nj], ah4, b2);
                mma_bf16(sc[nj], al4, b1);
            }
        }

        if (kt >= 2 * qt) {
            const int koff = kt * 64 - qr0;
            const int r0 = warp * 16 + g, r1 = r0 + 8;
#pragma unroll
            for (int nj = 0; nj < 8; nj++)
#pragma unroll
                for (int e = 0; e < 2; e++) {
                    const int cidx = nj * 8 + tq * 2 + e + koff;
                    if (cidx > r0) sc[nj][e]     = -1e30f;
                    if (cidx > r1) sc[nj][2 + e] = -1e30f;
                }
        }

        float mx0 = -1e30f, mx1 = -1e30f;
#pragma unroll
        for (int nj = 0; nj < 8; nj++) {
            mx0 = fmaxf(mx0, fmaxf(sc[nj][0], sc[nj][1]));
            mx1 = fmaxf(mx1, fmaxf(sc[nj][2], sc[nj][3]));
        }
        mx0 = fmaxf(mx0, __shfl_xor_sync(0xffffffffu, mx0, 1));
        mx0 = fmaxf(mx0, __shfl_xor_sync(0xffffffffu, mx0, 2));
        mx1 = fmaxf(mx1, __shfl_xor_sync(0xffffffffu, mx1, 1));
        mx1 = fmaxf(mx1, __shfl_xor_sync(0xffffffffu, mx1, 2));

        const float mn0 = fmaxf(m0, mx0), mn1 = fmaxf(m1, mx1);
        const float f0 = __expf(m0 - mn0), f1 = __expf(m1 - mn1);
        m0 = mn0; m1 = mn1;

        float s0 = 0.0f, s1 = 0.0f;
        unsigned pa[4][4];            // P as fp16 A-fragments
#pragma unroll
        for (int nj = 0; nj < 8; nj++) {
            const float p0 = __expf(sc[nj][0] - m0);
            const float p1 = __expf(sc[nj][1] - m0);
            const float p2 = __expf(sc[nj][2] - m1);
            const float p3 = __expf(sc[nj][3] - m1);
            s0 += p0 + p1;  s1 += p2 + p3;
            __half2 a01 = __floats2half2_rn(p0, p1);
            __half2 a23 = __floats2half2_rn(p2, p3);
            const int kb = nj >> 1, hf = (nj & 1) * 2;
            pa[kb][hf + 0] = *(unsigned*)&a01;
            pa[kb][hf + 1] = *(unsigned*)&a23;
        }
        s0 += __shfl_xor_sync(0xffffffffu, s0, 1);
        s0 += __shfl_xor_sync(0xffffffffu, s0, 2);
        s1 += __shfl_xor_sync(0xffffffffu, s1, 1);
        s1 += __shfl_xor_sync(0xffffffffu, s1, 2);
        l0 = l0 * f0 + s0;
        l1 = l1 * f1 + s1;
#pragma unroll
        for (int nt = 0; nt < 16; nt++) {
            o[nt][0] *= f0; o[nt][1] *= f0;
            o[nt][2] *= f1; o[nt][3] *= f1;
        }

        // ---- O += P V (fp16 single x single) ----
#pragma unroll
        for (int kb = 0; kb < 4; kb++) {
#pragma unroll
            for (int ng = 0; ng < 8; ng++) {
                const unsigned voff =
                    (unsigned)((kb * 16 + (mat & 1) * 8 + lm7) * ASD + ng * 16 + (mat >> 1) * 8) * 2u;
                unsigned v4[4];
                ldsm_x4_t(v4, OVF + smb + voff);
                mma_f16(o[2 * ng],     pa[kb], v4);
                mma_f16(o[2 * ng + 1], pa[kb], v4 + 2);
            }
        }

        __syncthreads();
        if (kt + 2 < nkt) {
            kv_fill(smb + 2 * QARR_B + s * KVSTAGE_B, qh, ql, vf, b, kt + 2, kvh, tid);
        }
        cpa_commit();
    }

    const float i0 = 1.0f / l0, i1 = 1.0f / l1;
    const size_t row0 = (size_t)(b * SEQ + qr0 + warp * 16 + g);
    const size_t row1 = row0 + 8;
#pragma unroll
    for (int nt = 0; nt < 16; nt++) {
        const int col = h * HDIM + nt * 8 + tq * 2;
        __half2 v01 = __floats2half2_rn(o[nt][0] * i0, o[nt][1] * i0);
        __half2 v23 = __floats2half2_rn(o[nt][2] * i1, o[nt][3] * i1);
        *(unsigned*)&oh[row0 * HIDN + col] = *(unsigned*)&v01;
        *(unsigned*)&oh[row1 * HIDN + col] = *(unsigned*)&v23;
    }
}

// ---------------------------------------------------------------------------
extern "C" void kernel_launch(void* const* d_in, const int* in_sizes, int n_in,
                              void* d_out, int out_size)
{
    const float* hidden = (const float*)d_in[0];
    const float* wq     = (const float*)d_in[1];
    const float* wk     = (const float*)d_in[2];
    const float* wv     = (const float*)d_in[3];
    const float* wo     = (const float*)d_in[4];
    const int*   pos    = (const int*)d_in[6];
    float*       outp   = (float*)d_out;

    float* qkv;  cudaGetSymbolAddress((void**)&qkv,  g_qkv);
    __nv_bfloat16 *qkvh, *qkvl, *hidh, *hidl, *wh, *wl;
    __half *woh, *ath, *vfp;
    cudaGetSymbolAddress((void**)&qkvh, g_qkvh);
    cudaGetSymbolAddress((void**)&qkvl, g_qkvl);
    cudaGetSymbolAddress((void**)&hidh, g_hidh);
    cudaGetSymbolAddress((void**)&hidl, g_hidl);
    cudaGetSymbolAddress((void**)&wh,  g_wh);
    cudaGetSymbolAddress((void**)&wl,  g_wl);
    cudaGetSymbolAddress((void**)&woh, g_woh);
    cudaGetSymbolAddress((void**)&ath, g_ath);
    cudaGetSymbolAddress((void**)&vfp, g_vf);

    cudaFuncSetAttribute(gemm_pre, cudaFuncAttributeMaxDynamicSharedMemorySize, GEMM_SMEM);
    cudaFuncSetAttribute(gemm_f16, cudaFuncAttributeMaxDynamicSharedMemorySize, GEMMH_SMEM);
    cudaFuncSetAttribute(attn_tc,  cudaFuncAttributeMaxDynamicSharedMemorySize, ATT_SMEM);

    const int nHid = NNZ * HIDN;
    const int nWqo = HIDN * HIDN;
    const int nWkv = 1024 * HIDN;
    split_kernel<<<nHid / 1024, 256>>>(hidden, hidh, hidl, nHid);
    split_kernel<<<nWqo / 1024, 256>>>(wq, wh,                       wl,                       nWqo);
    split_kernel<<<nWkv / 1024, 256>>>(wk, wh + (size_t)KOFF * HIDN, wl + (size_t)KOFF * HIDN, nWkv);
    split_kernel<<<nWkv / 1024, 256>>>(wv, wh + (size_t)VOFF * HIDN, wl + (size_t)VOFF * HIDN, nWkv);
    half_kernel<<<nWqo / 1024, 256>>>(wo, woh, nWqo);

    // Fused QKV projection (bf16x3): one launch, [4096 x 6144]
    gemm_pre<<<dim3(48, 32), 512, GEMM_SMEM>>>(hidh, hidl, wh, wl, qkv, HIDN, QKVC);

    // RoPE (+Q prescale) -> bf16 hi/lo; V -> fp16
    split_rope_kernel<<<dim3(NNZ, 48), 64>>>(qkv, pos, qkvh, qkvl, vfp);

    // Flash attention -> fp16 output
    attn_tc<<<dim3(SEQ / 128, NHEAD, NBATCH), 256, ATT_SMEM>>>(qkvh, qkvl, vfp, ath);

    // Output projection: fp16 single-term
    gemm_f16<<<dim3(32, 32), 512, GEMMH_SMEM>>>(ath, woh, outp, HIDN, HIDN);
}

// round 11
// speedup vs baseline: 5.0929x; 1.2974x over previous
#include <cuda_runtime.h>
#include <cuda_bf16.h>
#include <cuda_fp16.h>
#include <math.h>

#define NNZ   4096
#define HIDN  4096
#define NHEAD 32
#define NKVH  8
#define HDIM  128
#define SEQ   1024
#define NBATCH 4
#define QKVC  6144
#define KOFF  4096
#define VOFF  5120
#define VCOLS 1024

// ---------------- persistent scratch ----------------
__device__ float g_qkv[(size_t)NNZ * QKVC];
__device__ __nv_bfloat16 g_qkvh[(size_t)NNZ * QKVC];
__device__ __nv_bfloat16 g_qkvl[(size_t)NNZ * QKVC];
__device__ __half g_vf[(size_t)NNZ * VCOLS];          // V post-rope-pass, fp16
__device__ __half g_hidf[(size_t)NNZ * HIDN];         // hidden, fp16 single
__device__ __half g_wfh[(size_t)QKVC * HIDN];         // fused [wq;wk;wv] fp16 hi
__device__ __half g_wfl[(size_t)QKVC * HIDN];         // fused fp16 lo (residual)
__device__ __half g_woh[(size_t)HIDN * HIDN];         // wo, fp16 single
__device__ __half g_ath[(size_t)NNZ * HIDN];          // attention out, fp16

// ---------------- primitives ----------------
__device__ __forceinline__ void ldsm_x4(unsigned* r, unsigned addr) {
    asm volatile("ldmatrix.sync.aligned.m8n8.x4.shared.b16 {%0,%1,%2,%3}, [%4];\n"
                 : "=r"(r[0]), "=r"(r[1]), "=r"(r[2]), "=r"(r[3]) : "r"(addr));
}
__device__ __forceinline__ void ldsm_x4_t(unsigned* r, unsigned addr) {
    asm volatile("ldmatrix.sync.aligned.m8n8.x4.trans.shared.b16 {%0,%1,%2,%3}, [%4];\n"
                 : "=r"(r[0]), "=r"(r[1]), "=r"(r[2]), "=r"(r[3]) : "r"(addr));
}
__device__ __forceinline__ void mma_bf16(float* c, const unsigned* a, const unsigned* b) {
    asm volatile(
        "mma.sync.aligned.m16n8k16.row.col.f32.bf16.bf16.f32 "
        "{%0,%1,%2,%3}, {%4,%5,%6,%7}, {%8,%9}, {%0,%1,%2,%3};\n"
        : "+f"(c[0]), "+f"(c[1]), "+f"(c[2]), "+f"(c[3])
        : "r"(a[0]), "r"(a[1]), "r"(a[2]), "r"(a[3]), "r"(b[0]), "r"(b[1]));
}
__device__ __forceinline__ void mma_f16(float* c, const unsigned* a, const unsigned* b) {
    asm volatile(
        "mma.sync.aligned.m16n8k16.row.col.f32.f16.f16.f32 "
        "{%0,%1,%2,%3}, {%4,%5,%6,%7}, {%8,%9}, {%0,%1,%2,%3};\n"
        : "+f"(c[0]), "+f"(c[1]), "+f"(c[2]), "+f"(c[3])
        : "r"(a[0]), "r"(a[1]), "r"(a[2]), "r"(a[3]), "r"(b[0]), "r"(b[1]));
}
__device__ __forceinline__ unsigned pk(__nv_bfloat16 a, __nv_bfloat16 b) {
    __nv_bfloat162 t(a, b);
    return *reinterpret_cast<unsigned*>(&t);
}
__device__ __forceinline__ void cpa16(unsigned dst, const void* src) {
    asm volatile("cp.async.cg.shared.global [%0], [%1], 16;\n" :: "r"(dst), "l"(src));
}
__device__ __forceinline__ void cpa_commit() { asm volatile("cp.async.commit_group;\n"); }

// ---------------- conversion kernels ----------------
__global__ void half_kernel(const float* __restrict__ src,
                            __half* __restrict__ dst, int n)
{
    int i = (blockIdx.x * blockDim.x + threadIdx.x) * 4;
    if (i >= n) return;
    float4 v = *(const float4*)(src + i);
    __half2 a = __floats2half2_rn(v.x, v.y);
    __half2 b = __floats2half2_rn(v.z, v.w);
    *(uint2*)(dst + i) = make_uint2(*(unsigned*)&a, *(unsigned*)&b);
}

// fp16 hi/lo split: hi = fp16(x), lo = fp16(x - hi). Residual error ~2^-22.
__global__ void split16_kernel(const float* __restrict__ src,
                               __half* __restrict__ hi,
                               __half* __restrict__ lo, int n)
{
    int i = (blockIdx.x * blockDim.x + threadIdx.x) * 4;
    if (i >= n) return;
    float4 v = *(const float4*)(src + i);
    __half h0 = __float2half_rn(v.x), h1 = __float2half_rn(v.y);
    __half h2 = __float2half_rn(v.z), h3 = __float2half_rn(v.w);
    __half l0 = __float2half_rn(v.x - __half2float(h0));
    __half l1 = __float2half_rn(v.y - __half2float(h1));
    __half l2 = __float2half_rn(v.z - __half2float(h2));
    __half l3 = __float2half_rn(v.w - __half2float(h3));
    __half2 hh0(h0, h1), hh1(h2, h3), ll0(l0, l1), ll1(l2, l3);
    *(uint2*)(hi + i) = make_uint2(*(unsigned*)&hh0, *(unsigned*)&hh1);
    *(uint2*)(lo + i) = make_uint2(*(unsigned*)&ll0, *(unsigned*)&ll1);
}

// RoPE + split for qkv. grid (NNZ, 48), block 64.
// hb 0..31: Q (rope + prescale, bf16 hi/lo). 32..39: K (rope, bf16 hi/lo).
// 40..47: V (straight fp16 store into g_vf).
__global__ void split_rope_kernel(const float* __restrict__ qkv,
                                  const int* __restrict__ pos,
                                  __nv_bfloat16* __restrict__ qh,
                                  __nv_bfloat16* __restrict__ ql,
                                  __half* __restrict__ vf)
{
    const int tok = blockIdx.x;
    const int hb  = blockIdx.y;
    const int d   = threadIdx.x;
    const size_t base = (size_t)tok * QKVC + hb * HDIM;
    float x1 = qkv[base + d], x2 = qkv[base + d + 64];

    if (hb >= 40) {
        const size_t vb = (size_t)tok * VCOLS + (hb - 40) * HDIM;
        vf[vb + d]      = __float2half_rn(x1);
        vf[vb + d + 64] = __float2half_rn(x2);
        return;
    }

    // freq = 500000^(-d/64) = 2^(-d * log2(5e5)/64)
    float freq = exp2f(-0.29580575860567744f * (float)d);
    const float wl = 6.283185307179586f / freq;
    float f;
    if (wl < 2048.0f)       f = freq;
    else if (wl > 8192.0f)  f = freq * 0.125f;
    else {
        float smooth = (8192.0f / wl - 1.0f) * (1.0f / 3.0f);
        f = (1.0f - smooth) * freq * 0.125f + smooth * freq;
    }
    const float ang = (float)pos[tok] * f;
    const float c = cosf(ang), s = sinf(ang);
    float y1 = x1 * c - x2 * s;
    float y2 = x2 * c + x1 * s;
    if (hb < 32) { y1 *= 0.08838834764831845f; y2 *= 0.08838834764831845f; }

    __nv_bfloat16 h1 = __float2bfloat16(y1), h2 = __float2bfloat16(y2);
    qh[base + d]      = h1;
    qh[base + d + 64] = h2;
    ql[base + d]      = __float2bfloat16(y1 - __bfloat162float(h1));
    ql[base + d + 64] = __float2bfloat16(y2 - __bfloat162float(h2));
}

// ---------------------------------------------------------------------------
// QKV GEMM, fp16 2-term: C = A (Bh + Bl)^T. A fp16 single (hidden),
// Bh/Bl fp16 split (weights, effectively exact). 128x128 tile, BK=32,
// 512 threads, 4-stage cp.async, one barrier per iteration.
// ---------------------------------------------------------------------------
#define GSTRIDE 40
#define G_ARR_BYTES (128 * GSTRIDE * 2)
#define NSTAGE 4
#define Q_STAGE_BYTES (3 * G_ARR_BYTES)          // 30720
#define GEMMQ_SMEM (NSTAGE * Q_STAGE_BYTES)      // 122880

__global__ void __launch_bounds__(512) gemm_qkv(
    const __half* __restrict__ A,
    const __half* __restrict__ Bh, const __half* __restrict__ Bl,
    float* __restrict__ C, int K, int ldc)
{
    extern __shared__ __half qsm[];
    const unsigned smb = (unsigned)__cvta_generic_to_shared(qsm);

    const int bm = blockIdx.y * 128;
    const int bn = blockIdx.x * 128;
    const int t  = threadIdx.x;
    const int lane = t & 31;
    const int warp = t >> 5;
    const int wm = (warp & 3) * 32;
    const int wn = (warp >> 2) * 32;

    const int ldRow = t >> 2;
    const int ldCh  = (t & 3) * 8;
    const size_t aOff = (size_t)(bm + ldRow) * K + ldCh;
    const size_t bOff = (size_t)(bn + ldRow) * K + ldCh;
    const unsigned dOff = (unsigned)(ldRow * GSTRIDE + ldCh) * 2u;

    const int mat = lane >> 3;
    const int aRow = wm + (lane & 7) + (mat & 1) * 8;
    const int aColAdd = (mat >> 1) * 8;
    const int bRow = wn + (lane & 7) + (mat >> 1) * 8;
    const int bColAdd = (mat & 1) * 8;

    float acc[2][4][4];
#pragma unroll
    for (int mi = 0; mi < 2; mi++)
#pragma unroll
        for (int nj = 0; nj < 4; nj++)
#pragma unroll
            for (int u = 0; u < 4; u++) acc[mi][nj][u] = 0.0f;

    const int nt = K / 32;

#pragma unroll
    for (int s = 0; s < NSTAGE - 1; s++) {
        unsigned d0 = smb + s * Q_STAGE_BYTES + dOff;
        const int kn = s * 32;
        cpa16(d0,                   A  + aOff + kn);
        cpa16(d0 + G_ARR_BYTES,     Bh + bOff + kn);
        cpa16(d0 + 2 * G_ARR_BYTES, Bl + bOff + kn);
        cpa_commit();
    }

    for (int i = 0; i < nt; i++) {
        asm volatile("cp.async.wait_group %0;\n" :: "n"(NSTAGE - 2));
        __syncthreads();

        const unsigned st = smb + (i & (NSTAGE - 1)) * Q_STAGE_BYTES;
        const unsigned bA  = st;
        const unsigned bBh = st + G_ARR_BYTES;
        const unsigned bBl = st + 2 * G_ARR_BYTES;

#pragma unroll
        for (int kk = 0; kk < 32; kk += 16) {
            unsigned a4[2][4], bh[8], bl[8];
#pragma unroll
            for (int mi = 0; mi < 2; mi++) {
                unsigned off = (unsigned)((aRow + mi * 16) * GSTRIDE + kk + aColAdd) * 2u;
                ldsm_x4(a4[mi], bA + off);
            }
#pragma unroll
            for (int p = 0; p < 2; p++) {
                unsigned off = (unsigned)((bRow + p * 16) * GSTRIDE + kk + bColAdd) * 2u;
                ldsm_x4(&bh[p * 4], bBh + off);
                ldsm_x4(&bl[p * 4], bBl + off);
            }
#pragma unroll
            for (int mi = 0; mi < 2; mi++)
#pragma unroll
                for (int nj = 0; nj < 4; nj++) {
                    const unsigned* b1 = &bh[(nj >> 1) * 4 + (nj & 1) * 2];
                    const unsigned* b2 = &bl[(nj >> 1) * 4 + (nj & 1) * 2];
                    mma_f16(acc[mi][nj], a4[mi], b1);
                    mma_f16(acc[mi][nj], a4[mi], b2);
                }
        }

        if (i + NSTAGE - 1 < nt) {
            unsigned d0 = smb + ((i + NSTAGE - 1) & (NSTAGE - 1)) * Q_STAGE_BYTES + dOff;
            const int kn = (i + NSTAGE - 1) * 32;
            cpa16(d0,                   A  + aOff + kn);
            cpa16(d0 + G_ARR_BYTES,     Bh + bOff + kn);
            cpa16(d0 + 2 * G_ARR_BYTES, Bl + bOff + kn);
        }
        cpa_commit();
    }

    const int g = lane >> 2;
    const int tq = lane & 3;
#pragma unroll
    for (int mi = 0; mi < 2; mi++) {
        const int row0 = bm + wm + mi * 16 + g;
#pragma unroll
        for (int nj = 0; nj < 4; nj++) {
            const int col = bn + wn + nj * 8 + tq * 2;
            *(float2*)(C + (size_t)row0 * ldc + col) =
                make_float2(acc[mi][nj][0], acc[mi][nj][1]);
            *(float2*)(C + (size_t)(row0 + 8) * ldc + col) =
                make_float2(acc[mi][nj][2], acc[mi][nj][3]);
        }
    }
}

// ---------------------------------------------------------------------------
// Single-term fp16 GEMM (WO). 4-stage cp.async, one barrier per iter.
// ---------------------------------------------------------------------------
#define H_STAGE_BYTES (2 * G_ARR_BYTES)
#define GEMMH_SMEM (NSTAGE * H_STAGE_BYTES)

__global__ void __launch_bounds__(512) gemm_f16(
    const __half* __restrict__ A, const __half* __restrict__ B,
    float* __restrict__ C, int K, int ldc)
{
    extern __shared__ __half hsm[];
    const unsigned smb = (unsigned)__cvta_generic_to_shared(hsm);

    const int bm = blockIdx.y * 128;
    const int bn = blockIdx.x * 128;
    const int t  = threadIdx.x;
    const int lane = t & 31;
    const int warp = t >> 5;
    const int wm = (warp & 3) * 32;
    const int wn = (warp >> 2) * 32;

    const int ldRow = t >> 2;
    const int ldCh  = (t & 3) * 8;
    const size_t aOff = (size_t)(bm + ldRow) * K + ldCh;
    const size_t bOff = (size_t)(bn + ldRow) * K + ldCh;
    const unsigned dOff = (unsigned)(ldRow * GSTRIDE + ldCh) * 2u;

    const int mat = lane >> 3;
    const int aRow = wm + (lane & 7) + (mat & 1) * 8;
    const int aColAdd = (mat >> 1) * 8;
    const int bRow = wn + (lane & 7) + (mat >> 1) * 8;
    const int bColAdd = (mat & 1) * 8;

    float acc[2][4][4];
#pragma unroll
    for (int mi = 0; mi < 2; mi++)
#pragma unroll
        for (int nj = 0; nj < 4; nj++)
#pragma unroll
            for (int u = 0; u < 4; u++) acc[mi][nj][u] = 0.0f;

    const int nt = K / 32;

#pragma unroll
    for (int s = 0; s < NSTAGE - 1; s++) {
        unsigned d0 = smb + s * H_STAGE_BYTES + dOff;
        const int kn = s * 32;
        cpa16(d0,               A + aOff + kn);
        cpa16(d0 + G_ARR_BYTES, B + bOff + kn);
        cpa_commit();
    }

    for (int i = 0; i < nt; i++) {
        asm volatile("cp.async.wait_group %0;\n" :: "n"(NSTAGE - 2));
        __syncthreads();

        const unsigned st = smb + (i & (NSTAGE - 1)) * H_STAGE_BYTES;
        const unsigned bA = st;
        const unsigned bB = st + G_ARR_BYTES;

#pragma unroll
        for (int kk = 0; kk < 32; kk += 16) {
            unsigned a4[2][4], b4[8];
#pragma unroll
            for (int mi = 0; mi < 2; mi++) {
                unsigned off = (unsigned)((aRow + mi * 16) * GSTRIDE + kk + aColAdd) * 2u;
                ldsm_x4(a4[mi], bA + off);
            }
#pragma unroll
            for (int p = 0; p < 2; p++) {
                unsigned off = (unsigned)((bRow + p * 16) * GSTRIDE + kk + bColAdd) * 2u;
                ldsm_x4(&b4[p * 4], bB + off);
            }
#pragma unroll
            for (int mi = 0; mi < 2; mi++)
#pragma unroll
                for (int nj = 0; nj < 4; nj++)
                    mma_f16(acc[mi][nj], a4[mi], &b4[(nj >> 1) * 4 + (nj & 1) * 2]);
        }

        if (i + NSTAGE - 1 < nt) {
            unsigned d0 = smb + ((i + NSTAGE - 1) & (NSTAGE - 1)) * H_STAGE_BYTES + dOff;
            const int kn = (i + NSTAGE - 1) * 32;
            cpa16(d0,               A + aOff + kn);
            cpa16(d0 + G_ARR_BYTES, B + bOff + kn);
        }
        cpa_commit();
    }

    const int g = lane >> 2;
    const int tq = lane & 3;
#pragma unroll
    for (int mi = 0; mi < 2; mi++) {
        const int row0 = bm + wm + mi * 16 + g;
#pragma unroll
        for (int nj = 0; nj < 4; nj++) {
            const int col = bn + wn + nj * 8 + tq * 2;
            *(float2*)(C + (size_t)row0 * ldc + col) =
                make_float2(acc[mi][nj][0], acc[mi][nj][1]);
            *(float2*)(C + (size_t)(row0 + 8) * ldc + col) =
                make_float2(acc[mi][nj][2], acc[mi][nj][3]);
        }
    }
}

// ---------------------------------------------------------------------------
// Flash attention: QK bf16x3, PV fp16 single x single. Unchanged (round 9).
// ---------------------------------------------------------------------------
#define ASD 136
#define QARR_B (128 * ASD * 2)
#define KARR_B (64 * ASD * 2)
#define KVSTAGE_B (3 * KARR_B)
#define ATT_SMEM (2 * QARR_B + 2 * KVSTAGE_B)   // 174080 B

__device__ __forceinline__ void kv_fill(
    unsigned stage_b, const __nv_bfloat16* qh, const __nv_bfloat16* ql,
    const __half* vf, int b, int kt, int kvh, int tid)
{
    for (int j = tid; j < 64 * 16; j += 256) {
        const int r = j >> 4, ch = (j & 15) * 8;
        const int ktok = b * SEQ + kt * 64 + r;
        const size_t ki = (size_t)ktok * QKVC + KOFF + kvh * HDIM + ch;
        const size_t vi = (size_t)ktok * VCOLS + kvh * HDIM + ch;
        const unsigned dst = stage_b + (unsigned)(r * ASD + ch) * 2u;
        cpa16(dst,              qh + ki);
        cpa16(dst + KARR_B,     ql + ki);
        cpa16(dst + 2 * KARR_B, vf + vi);
    }
}

__global__ void __launch_bounds__(256) attn_tc(
    const __nv_bfloat16* __restrict__ qh, const __nv_bfloat16* __restrict__ ql,
    const __half* __restrict__ vf, __half* __restrict__ oh)
{
    extern __shared__ __nv_bfloat16 smA[];
    const unsigned smb = (unsigned)__cvta_generic_to_shared(smA);

    const int qt  = (int)gridDim.x - 1 - (int)blockIdx.x;
    const int h   = blockIdx.y;
    const int b   = blockIdx.z;
    const int kvh = h >> 2;
    const int tid = threadIdx.x;
    const int lane = tid & 31;
    const int warp = tid >> 5;
    const int qr0 = qt * 128;
    const int mat = lane >> 3;
    const int lm7 = lane & 7;
    const int g   = lane >> 2;
    const int tq  = lane & 3;

    const int nkt = 2 * qt + 2;

    kv_fill(smb + 2 * QARR_B, qh, ql, vf, b, 0, kvh, tid);
    cpa_commit();
    kv_fill(smb + 2 * QARR_B + KVSTAGE_B, qh, ql, vf, b, 1, kvh, tid);
    cpa_commit();

    for (int j = tid; j < 128 * 16; j += 256) {
        const int r = j >> 4, ch = (j & 15) * 8;
        const size_t gi = (size_t)(b * SEQ + qr0 + r) * QKVC + h * HDIM + ch;
        *(uint4*)&smA[r * ASD + ch]              = *(const uint4*)&qh[gi];
        *(uint4*)&smA[128 * ASD + r * ASD + ch]  = *(const uint4*)&ql[gi];
    }

    float o[16][4];
#pragma unroll
    for (int nt = 0; nt < 16; nt++)
#pragma unroll
        for (int u = 0; u < 4; u++) o[nt][u] = 0.0f;
    float m0 = -1e30f, m1 = -1e30f, l0 = 0.0f, l1 = 0.0f;

    for (int kt = 0; kt < nkt; kt++) {
        const int s = kt & 1;
        if (kt + 1 < nkt) asm volatile("cp.async.wait_group 1;\n" ::: "memory");
        else              asm volatile("cp.async.wait_group 0;\n" ::: "memory");
        __syncthreads();

        const unsigned OKH = (unsigned)(2 * QARR_B + s * KVSTAGE_B);
        const unsigned OKL = OKH + KARR_B;
        const unsigned OVF = OKH + 2 * KARR_B;

        float sc[8][4];
#pragma unroll
        for (int nj = 0; nj < 8; nj++)
#pragma unroll
            for (int u = 0; u < 4; u++) sc[nj][u] = 0.0f;

#pragma unroll
        for (int kk = 0; kk < 128; kk += 16) {
            unsigned ah4[4], al4[4], bh[16], bl[16];
            const unsigned aoff =
                (unsigned)((warp * 16 + lm7 + (mat & 1) * 8) * ASD + kk + (mat >> 1) * 8) * 2u;
            ldsm_x4(ah4, smb + aoff);
            ldsm_x4(al4, smb + QARR_B + aoff);
#pragma unroll
            for (int p = 0; p < 4; p++) {
                const unsigned boff =
                    (unsigned)((p * 16 + lm7 + (mat >> 1) * 8) * ASD + kk + (mat & 1) * 8) * 2u;
                ldsm_x4(&bh[p * 4], OKH + smb + boff);
                ldsm_x4(&bl[p * 4], OKL + smb + boff);
            }
#pragma unroll
            for (int nj = 0; nj < 8; nj++) {
                const unsigned* b1 = &bh[(nj >> 1) * 4 + (nj & 1) * 2];
                const unsigned* b2 = &bl[(nj >> 1) * 4 + (nj & 1) * 2];
                mma_bf16(sc[nj], ah4, b1);
                mma_bf16(sc[nj], ah4, b2);
                mma_bf16(sc[nj], al4, b1);
            }
        }

        if (kt >= 2 * qt) {
            const int koff = kt * 64 - qr0;
            const int r0 = warp * 16 + g, r1 = r0 + 8;
#pragma unroll
            for (int nj = 0; nj < 8; nj++)
#pragma unroll
                for (int e = 0; e < 2; e++) {
                    const int cidx = nj * 8 + tq * 2 + e + koff;
                    if (cidx > r0) sc[nj][e]     = -1e30f;
                    if (cidx > r1) sc[nj][2 + e] = -1e30f;
                }
        }

        float mx0 = -1e30f, mx1 = -1e30f;
#pragma unroll
        for (int nj = 0; nj < 8; nj++) {
            mx0 = fmaxf(mx0, fmaxf(sc[nj][0], sc[nj][1]));
            mx1 = fmaxf(mx1, fmaxf(sc[nj][2], sc[nj][3]));
        }
        mx0 = fmaxf(mx0, __shfl_xor_sync(0xffffffffu, mx0, 1));
        mx0 = fmaxf(mx0, __shfl_xor_sync(0xffffffffu, mx0, 2));
        mx1 = fmaxf(mx1, __shfl_xor_sync(0xffffffffu, mx1, 1));
        mx1 = fmaxf(mx1, __shfl_xor_sync(0xffffffffu, mx1, 2));

        const float mn0 = fmaxf(m0, mx0), mn1 = fmaxf(m1, mx1);
        const float f0 = __expf(m0 - mn0), f1 = __expf(m1 - mn1);
        m0 = mn0; m1 = mn1;

        float s0 = 0.0f, s1 = 0.0f;
        unsigned pa[4][4];
#pragma unroll
        for (int nj = 0; nj < 8; nj++) {
            const float p0 = __expf(sc[nj][0] - m0);
            const float p1 = __expf(sc[nj][1] - m0);
            const float p2 = __expf(sc[nj][2] - m1);
            const float p3 = __expf(sc[nj][3] - m1);
            s0 += p0 + p1;  s1 += p2 + p3;
            __half2 a01 = __floats2half2_rn(p0, p1);
            __half2 a23 = __floats2half2_rn(p2, p3);
            const int kb = nj >> 1, hf = (nj & 1) * 2;
            pa[kb][hf + 0] = *(unsigned*)&a01;
            pa[kb][hf + 1] = *(unsigned*)&a23;
        }
        s0 += __shfl_xor_sync(0xffffffffu, s0, 1);
        s0 += __shfl_xor_sync(0xffffffffu, s0, 2);
        s1 += __shfl_xor_sync(0xffffffffu, s1, 1);
        s1 += __shfl_xor_sync(0xffffffffu, s1, 2);
        l0 = l0 * f0 + s0;
        l1 = l1 * f1 + s1;
#pragma unroll
        for (int nt = 0; nt < 16; nt++) {
            o[nt][0] *= f0; o[nt][1] *= f0;
            o[nt][2] *= f1; o[nt][3] *= f1;
        }

#pragma unroll
        for (int kb = 0; kb < 4; kb++) {
#pragma unroll
            for (int ng = 0; ng < 8; ng++) {
                const unsigned voff =
                    (unsigned)((kb * 16 + (mat & 1) * 8 + lm7) * ASD + ng * 16 + (mat >> 1) * 8) * 2u;
                unsigned v4[4];
                ldsm_x4_t(v4, OVF + smb + voff);
                mma_f16(o[2 * ng],     pa[kb], v4);
                mma_f16(o[2 * ng + 1], pa[kb], v4 + 2);
            }
        }

        __syncthreads();
        if (kt + 2 < nkt) {
            kv_fill(smb + 2 * QARR_B + s * KVSTAGE_B, qh, ql, vf, b, kt + 2, kvh, tid);
        }
        cpa_commit();
    }

    const float i0 = 1.0f / l0, i1 = 1.0f / l1;
    const size_t row0 = (size_t)(b * SEQ + qr0 + warp * 16 + g);
    const size_t row1 = row0 + 8;
#pragma unroll
    for (int nt = 0; nt < 16; nt++) {
        const int col = h * HDIM + nt * 8 + tq * 2;
        __half2 v01 = __floats2half2_rn(o[nt][0] * i0, o[nt][1] * i0);
        __half2 v23 = __floats2half2_rn(o[nt][2] * i1, o[nt][3] * i1);
        *(unsigned*)&oh[row0 * HIDN + col] = *(unsigned*)&v01;
        *(unsigned*)&oh[row1 * HIDN + col] = *(unsigned*)&v23;
    }
}

// ---------------------------------------------------------------------------
extern "C" void kernel_launch(void* const* d_in, const int* in_sizes, int n_in,
                              void* d_out, int out_size)
{
    const float* hidden = (const float*)d_in[0];
    const float* wq     = (const float*)d_in[1];
    const float* wk     = (const float*)d_in[2];
    const float* wv     = (const float*)d_in[3];
    const float* wo     = (const float*)d_in[4];
    const int*   pos    = (const int*)d_in[6];
    float*       outp   = (float*)d_out;

    float* qkv;  cudaGetSymbolAddress((void**)&qkv,  g_qkv);
    __nv_bfloat16 *qkvh, *qkvl;
    __half *hidf, *wfh, *wfl, *woh, *ath, *vfp;
    cudaGetSymbolAddress((void**)&qkvh, g_qkvh);
    cudaGetSymbolAddress((void**)&qkvl, g_qkvl);
    cudaGetSymbolAddress((void**)&hidf, g_hidf);
    cudaGetSymbolAddress((void**)&wfh, g_wfh);
    cudaGetSymbolAddress((void**)&wfl, g_wfl);
    cudaGetSymbolAddress((void**)&woh, g_woh);
    cudaGetSymbolAddress((void**)&ath, g_ath);
    cudaGetSymbolAddress((void**)&vfp, g_vf);

    cudaFuncSetAttribute(gemm_qkv, cudaFuncAttributeMaxDynamicSharedMemorySize, GEMMQ_SMEM);
    cudaFuncSetAttribute(gemm_f16, cudaFuncAttributeMaxDynamicSharedMemorySize, GEMMH_SMEM);
    cudaFuncSetAttribute(attn_tc,  cudaFuncAttributeMaxDynamicSharedMemorySize, ATT_SMEM);

    const int nHid = NNZ * HIDN;
    const int nWqo = HIDN * HIDN;
    const int nWkv = 1024 * HIDN;
    half_kernel<<<nHid / 1024, 256>>>(hidden, hidf, nHid);
    split16_kernel<<<nWqo / 1024, 256>>>(wq, wfh,                        wfl,                        nWqo);
    split16_kernel<<<nWkv / 1024, 256>>>(wk, wfh + (size_t)KOFF * HIDN,  wfl + (size_t)KOFF * HIDN,  nWkv);
    split16_kernel<<<nWkv / 1024, 256>>>(wv, wfh + (size_t)VOFF * HIDN,  wfl + (size_t)VOFF * HIDN,  nWkv);
    half_kernel<<<nWqo / 1024, 256>>>(wo, woh, nWqo);

    // Fused QKV projection (fp16 2-term): one launch, [4096 x 6144]
    gemm_qkv<<<dim3(48, 32), 512, GEMMQ_SMEM>>>(hidf, wfh, wfl, qkv, HIDN, QKVC);

    // RoPE (+Q prescale) -> bf16 hi/lo; V -> fp16
    split_rope_kernel<<<dim3(NNZ, 48), 64>>>(qkv, pos, qkvh, qkvl, vfp);

    // Flash attention -> fp16 output
    attn_tc<<<dim3(SEQ / 128, NHEAD, NBATCH), 256, ATT_SMEM>>>(qkvh, qkvl, vfp, ath);

    // Output projection: fp16 single-term
    gemm_f16<<<dim3(32, 32), 512, GEMMH_SMEM>>>(ath, woh, outp, HIDN, HIDN);
}

// round 14
// speedup vs baseline: 7.0243x; 1.3792x over previous
#include <cuda_runtime.h>
#include <cuda_bf16.h>
#include <cuda_fp16.h>
#include <math.h>

#define NNZ   4096
#define HIDN  4096
#define NHEAD 32
#define NKVH  8
#define HDIM  128
#define SEQ   1024
#define NBATCH 4
#define QKVC  6144
#define KOFF  4096
#define VOFF  5120
#define VCOLS 1024

// ---------------- persistent scratch ----------------
__device__ float g_qkv[(size_t)NNZ * QKVC];
__device__ __nv_bfloat16 g_qkvh[(size_t)NNZ * QKVC];
__device__ __nv_bfloat16 g_qkvl[(size_t)NNZ * QKVC];
__device__ __half g_vf[(size_t)NNZ * VCOLS];          // V post-rope-pass, fp16
__device__ __half g_hidf[(size_t)NNZ * HIDN];         // hidden, fp16 single
__device__ __half g_wf[(size_t)QKVC * HIDN];          // fused [wq;wk;wv] fp16
__device__ __half g_woh[(size_t)HIDN * HIDN];         // wo, fp16 single
__device__ __half g_ath[(size_t)NNZ * HIDN];          // attention out, fp16

// ---------------- primitives ----------------
__device__ __forceinline__ void ldsm_x4(unsigned* r, unsigned addr) {
    asm volatile("ldmatrix.sync.aligned.m8n8.x4.shared.b16 {%0,%1,%2,%3}, [%4];\n"
                 : "=r"(r[0]), "=r"(r[1]), "=r"(r[2]), "=r"(r[3]) : "r"(addr));
}
__device__ __forceinline__ void ldsm_x4_t(unsigned* r, unsigned addr) {
    asm volatile("ldmatrix.sync.aligned.m8n8.x4.trans.shared.b16 {%0,%1,%2,%3}, [%4];\n"
                 : "=r"(r[0]), "=r"(r[1]), "=r"(r[2]), "=r"(r[3]) : "r"(addr));
}
__device__ __forceinline__ void mma_bf16(float* c, const unsigned* a, const unsigned* b) {
    asm volatile(
        "mma.sync.aligned.m16n8k16.row.col.f32.bf16.bf16.f32 "
        "{%0,%1,%2,%3}, {%4,%5,%6,%7}, {%8,%9}, {%0,%1,%2,%3};\n"
        : "+f"(c[0]), "+f"(c[1]), "+f"(c[2]), "+f"(c[3])
        : "r"(a[0]), "r"(a[1]), "r"(a[2]), "r"(a[3]), "r"(b[0]), "r"(b[1]));
}
__device__ __forceinline__ void mma_f16(float* c, const unsigned* a, const unsigned* b) {
    asm volatile(
        "mma.sync.aligned.m16n8k16.row.col.f32.f16.f16.f32 "
        "{%0,%1,%2,%3}, {%4,%5,%6,%7}, {%8,%9}, {%0,%1,%2,%3};\n"
        : "+f"(c[0]), "+f"(c[1]), "+f"(c[2]), "+f"(c[3])
        : "r"(a[0]), "r"(a[1]), "r"(a[2]), "r"(a[3]), "r"(b[0]), "r"(b[1]));
}
__device__ __forceinline__ unsigned pk(__nv_bfloat16 a, __nv_bfloat16 b) {
    __nv_bfloat162 t(a, b);
    return *reinterpret_cast<unsigned*>(&t);
}
__device__ __forceinline__ void cpa16(unsigned dst, const void* src) {
    asm volatile("cp.async.cg.shared.global [%0], [%1], 16;\n" :: "r"(dst), "l"(src));
}
__device__ __forceinline__ void cpa_commit() { asm volatile("cp.async.commit_group;\n"); }

// ---------------- conversion kernels ----------------
__global__ void half_kernel(const float* __restrict__ src,
                            __half* __restrict__ dst, int n)
{
    int i = (blockIdx.x * blockDim.x + threadIdx.x) * 4;
    if (i >= n) return;
    float4 v = *(const float4*)(src + i);
    __half2 a = __floats2half2_rn(v.x, v.y);
    __half2 b = __floats2half2_rn(v.z, v.w);
    *(uint2*)(dst + i) = make_uint2(*(unsigned*)&a, *(unsigned*)&b);
}

// RoPE + split for qkv. grid (NNZ, 48), block 64.
// hb 0..31: Q (rope + prescale, bf16 hi/lo). 32..39: K (rope, bf16 hi/lo).
// 40..47: V (straight fp16 store into g_vf).
__global__ void split_rope_kernel(const float* __restrict__ qkv,
                                  const int* __restrict__ pos,
                                  __nv_bfloat16* __restrict__ qh,
                                  __nv_bfloat16* __restrict__ ql,
                                  __half* __restrict__ vf)
{
    const int tok = blockIdx.x;
    const int hb  = blockIdx.y;
    const int d   = threadIdx.x;
    const size_t base = (size_t)tok * QKVC + hb * HDIM;
    float x1 = qkv[base + d], x2 = qkv[base + d + 64];

    if (hb >= 40) {
        const size_t vb = (size_t)tok * VCOLS + (hb - 40) * HDIM;
        vf[vb + d]      = __float2half_rn(x1);
        vf[vb + d + 64] = __float2half_rn(x2);
        return;
    }

    // freq = 500000^(-d/64) = 2^(-d * log2(5e5)/64)
    float freq = exp2f(-0.29580575860567744f * (float)d);
    const float wl = 6.283185307179586f / freq;
    float f;
    if (wl < 2048.0f)       f = freq;
    else if (wl > 8192.0f)  f = freq * 0.125f;
    else {
        float smooth = (8192.0f / wl - 1.0f) * (1.0f / 3.0f);
        f = (1.0f - smooth) * freq * 0.125f + smooth * freq;
    }
    const float ang = (float)pos[tok] * f;
    const float c = cosf(ang), s = sinf(ang);
    float y1 = x1 * c - x2 * s;
    float y2 = x2 * c + x1 * s;
    if (hb < 32) { y1 *= 0.08838834764831845f; y2 *= 0.08838834764831845f; }

    __nv_bfloat16 h1 = __float2bfloat16(y1), h2 = __float2bfloat16(y2);
    qh[base + d]      = h1;
    qh[base + d + 64] = h2;
    ql[base + d]      = __float2bfloat16(y1 - __bfloat162float(h1));
    ql[base + d + 64] = __float2bfloat16(y2 - __bfloat162float(h2));
}

// ---------------------------------------------------------------------------
// Single-term fp16 GEMM: C = A B^T, used for BOTH QKV and WO projections.
// 128x128 tile, BK=32, 512 threads, 4-stage cp.async, one barrier per iter.
// ---------------------------------------------------------------------------
#define GSTRIDE 40
#define G_ARR_BYTES (128 * GSTRIDE * 2)
#define NSTAGE 4
#define H_STAGE_BYTES (2 * G_ARR_BYTES)
#define GEMMH_SMEM (NSTAGE * H_STAGE_BYTES)      // 81920

__global__ void __launch_bounds__(512) gemm_f16(
    const __half* __restrict__ A, const __half* __restrict__ B,
    float* __restrict__ C, int K, int ldc)
{
    extern __shared__ __half hsm[];
    const unsigned smb = (unsigned)__cvta_generic_to_shared(hsm);

    const int bm = blockIdx.y * 128;
    const int bn = blockIdx.x * 128;
    const int t  = threadIdx.x;
    const int lane = t & 31;
    const int warp = t >> 5;
    const int wm = (warp & 3) * 32;
    const int wn = (warp >> 2) * 32;

    const int ldRow = t >> 2;
    const int ldCh  = (t & 3) * 8;
    const size_t aOff = (size_t)(bm + ldRow) * K + ldCh;
    const size_t bOff = (size_t)(bn + ldRow) * K + ldCh;
    const unsigned dOff = (unsigned)(ldRow * GSTRIDE + ldCh) * 2u;

    const int mat = lane >> 3;
    const int aRow = wm + (lane & 7) + (mat & 1) * 8;
    const int aColAdd = (mat >> 1) * 8;
    const int bRow = wn + (lane & 7) + (mat >> 1) * 8;
    const int bColAdd = (mat & 1) * 8;

    float acc[2][4][4];
#pragma unroll
    for (int mi = 0; mi < 2; mi++)
#pragma unroll
        for (int nj = 0; nj < 4; nj++)
#pragma unroll
            for (int u = 0; u < 4; u++) acc[mi][nj][u] = 0.0f;

    const int nt = K / 32;

#pragma unroll
    for (int s = 0; s < NSTAGE - 1; s++) {
        unsigned d0 = smb + s * H_STAGE_BYTES + dOff;
        const int kn = s * 32;
        cpa16(d0,               A + aOff + kn);
        cpa16(d0 + G_ARR_BYTES, B + bOff + kn);
        cpa_commit();
    }

    for (int i = 0; i < nt; i++) {
        asm volatile("cp.async.wait_group %0;\n" :: "n"(NSTAGE - 2));
        __syncthreads();

        const unsigned st = smb + (i & (NSTAGE - 1)) * H_STAGE_BYTES;
        const unsigned bA = st;
        const unsigned bB = st + G_ARR_BYTES;

#pragma unroll
        for (int kk = 0; kk < 32; kk += 16) {
            unsigned a4[2][4], b4[8];
#pragma unroll
            for (int mi = 0; mi < 2; mi++) {
                unsigned off = (unsigned)((aRow + mi * 16) * GSTRIDE + kk + aColAdd) * 2u;
                ldsm_x4(a4[mi], bA + off);
            }
#pragma unroll
            for (int p = 0; p < 2; p++) {
                unsigned off = (unsigned)((bRow + p * 16) * GSTRIDE + kk + bColAdd) * 2u;
                ldsm_x4(&b4[p * 4], bB + off);
            }
#pragma unroll
            for (int mi = 0; mi < 2; mi++)
#pragma unroll
                for (int nj = 0; nj < 4; nj++)
                    mma_f16(acc[mi][nj], a4[mi], &b4[(nj >> 1) * 4 + (nj & 1) * 2]);
        }

        if (i + NSTAGE - 1 < nt) {
            unsigned d0 = smb + ((i + NSTAGE - 1) & (NSTAGE - 1)) * H_STAGE_BYTES + dOff;
            const int kn = (i + NSTAGE - 1) * 32;
            cpa16(d0,               A + aOff + kn);
            cpa16(d0 + G_ARR_BYTES, B + bOff + kn);
        }
        cpa_commit();
    }

    const int g = lane >> 2;
    const int tq = lane & 3;
#pragma unroll
    for (int mi = 0; mi < 2; mi++) {
        const int row0 = bm + wm + mi * 16 + g;
#pragma unroll
        for (int nj = 0; nj < 4; nj++) {
            const int col = bn + wn + nj * 8 + tq * 2;
            *(float2*)(C + (size_t)row0 * ldc + col) =
                make_float2(acc[mi][nj][0], acc[mi][nj][1]);
            *(float2*)(C + (size_t)(row0 + 8) * ldc + col) =
                make_float2(acc[mi][nj][2], acc[mi][nj][3]);
        }
    }
}

// ---------------------------------------------------------------------------
// Flash attention: QK bf16x3, PV fp16 single x single. Unchanged (round 9).
// ---------------------------------------------------------------------------
#define ASD 136
#define QARR_B (128 * ASD * 2)
#define KARR_B (64 * ASD * 2)
#define KVSTAGE_B (3 * KARR_B)
#define ATT_SMEM (2 * QARR_B + 2 * KVSTAGE_B)   // 174080 B

__device__ __forceinline__ void kv_fill(
    unsigned stage_b, const __nv_bfloat16* qh, const __nv_bfloat16* ql,
    const __half* vf, int b, int kt, int kvh, int tid)
{
    for (int j = tid; j < 64 * 16; j += 256) {
        const int r = j >> 4, ch = (j & 15) * 8;
        const int ktok = b * SEQ + kt * 64 + r;
        const size_t ki = (size_t)ktok * QKVC + KOFF + kvh * HDIM + ch;
        const size_t vi = (size_t)ktok * VCOLS + kvh * HDIM + ch;
        const unsigned dst = stage_b + (unsigned)(r * ASD + ch) * 2u;
        cpa16(dst,              qh + ki);
        cpa16(dst + KARR_B,     ql + ki);
        cpa16(dst + 2 * KARR_B, vf + vi);
    }
}

__global__ void __launch_bounds__(256) attn_tc(
    const __nv_bfloat16* __restrict__ qh, const __nv_bfloat16* __restrict__ ql,
    const __half* __restrict__ vf, __half* __restrict__ oh)
{
    extern __shared__ __nv_bfloat16 smA[];
    const unsigned smb = (unsigned)__cvta_generic_to_shared(smA);

    const int qt  = (int)gridDim.x - 1 - (int)blockIdx.x;
    const int h   = blockIdx.y;
    const int b   = blockIdx.z;
    const int kvh = h >> 2;
    const int tid = threadIdx.x;
    const int lane = tid & 31;
    const int warp = tid >> 5;
    const int qr0 = qt * 128;
    const int mat = lane >> 3;
    const int lm7 = lane & 7;
    const int g   = lane >> 2;
    const int tq  = lane & 3;

    const int nkt = 2 * qt + 2;

    kv_fill(smb + 2 * QARR_B, qh, ql, vf, b, 0, kvh, tid);
    cpa_commit();
    kv_fill(smb + 2 * QARR_B + KVSTAGE_B, qh, ql, vf, b, 1, kvh, tid);
    cpa_commit();

    for (int j = tid; j < 128 * 16; j += 256) {
        const int r = j >> 4, ch = (j & 15) * 8;
        const size_t gi = (size_t)(b * SEQ + qr0 + r) * QKVC + h * HDIM + ch;
        *(uint4*)&smA[r * ASD + ch]              = *(const uint4*)&qh[gi];
        *(uint4*)&smA[128 * ASD + r * ASD + ch]  = *(const uint4*)&ql[gi];
    }

    float o[16][4];
#pragma unroll
    for (int nt = 0; nt < 16; nt++)
#pragma unroll
        for (int u = 0; u < 4; u++) o[nt][u] = 0.0f;
    float m0 = -1e30f, m1 = -1e30f, l0 = 0.0f, l1 = 0.0f;

    for (int kt = 0; kt < nkt; kt++) {
        const int s = kt & 1;
        if (kt + 1 < nkt) asm volatile("cp.async.wait_group 1;\n" ::: "memory");
        else              asm volatile("cp.async.wait_group 0;\n" ::: "memory");
        __syncthreads();

        const unsigned OKH = (unsigned)(2 * QARR_B + s * KVSTAGE_B);
        const unsigned OKL = OKH + KARR_B;
        const unsigned OVF = OKH + 2 * KARR_B;

        float sc[8][4];
#pragma unroll
        for (int nj = 0; nj < 8; nj++)
#pragma unroll
            for (int u = 0; u < 4; u++) sc[nj][u] = 0.0f;

#pragma unroll
        for (int kk = 0; kk < 128; kk += 16) {
            unsigned ah4[4], al4[4], bh[16], bl[16];
            const unsigned aoff =
                (unsigned)((warp * 16 + lm7 + (mat & 1) * 8) * ASD + kk + (mat >> 1) * 8) * 2u;
            ldsm_x4(ah4, smb + aoff);
            ldsm_x4(al4, smb + QARR_B + aoff);
#pragma unroll
            for (int p = 0; p < 4; p++) {
                const unsigned boff =
                    (unsigned)((p * 16 + lm7 + (mat >> 1) * 8) * ASD + kk + (mat & 1) * 8) * 2u;
                ldsm_x4(&bh[p * 4], OKH + smb + boff);
                ldsm_x4(&bl[p * 4], OKL + smb + boff);
            }
#pragma unroll
            for (int nj = 0; nj < 8; nj++) {
                const unsigned* b1 = &bh[(nj >> 1) * 4 + (nj & 1) * 2];
                const unsigned* b2 = &bl[(nj >> 1) * 4 + (nj & 1) * 2];
                mma_bf16(sc[nj], ah4, b1);
                mma_bf16(sc[nj], ah4, b2);
                mma_bf16(sc[nj], al4, b1);
            }
        }

        if (kt >= 2 * qt) {
            const int koff = kt * 64 - qr0;
            const int r0 = warp * 16 + g, r1 = r0 + 8;
#pragma unroll
            for (int nj = 0; nj < 8; nj++)
#pragma unroll
                for (int e = 0; e < 2; e++) {
                    const int cidx = nj * 8 + tq * 2 + e + koff;
                    if (cidx > r0) sc[nj][e]     = -1e30f;
                    if (cidx > r1) sc[nj][2 + e] = -1e30f;
                }
        }

        float mx0 = -1e30f, mx1 = -1e30f;
#pragma unroll
        for (int nj = 0; nj < 8; nj++) {
            mx0 = fmaxf(mx0, fmaxf(sc[nj][0], sc[nj][1]));
            mx1 = fmaxf(mx1, fmaxf(sc[nj][2], sc[nj][3]));
        }
        mx0 = fmaxf(mx0, __shfl_xor_sync(0xffffffffu, mx0, 1));
        mx0 = fmaxf(mx0, __shfl_xor_sync(0xffffffffu, mx0, 2));
        mx1 = fmaxf(mx1, __shfl_xor_sync(0xffffffffu, mx1, 1));
        mx1 = fmaxf(mx1, __shfl_xor_sync(0xffffffffu, mx1, 2));

        const float mn0 = fmaxf(m0, mx0), mn1 = fmaxf(m1, mx1);
        const float f0 = __expf(m0 - mn0), f1 = __expf(m1 - mn1);
        m0 = mn0; m1 = mn1;

        float s0 = 0.0f, s1 = 0.0f;
        unsigned pa[4][4];
#pragma unroll
        for (int nj = 0; nj < 8; nj++) {
            const float p0 = __expf(sc[nj][0] - m0);
            const float p1 = __expf(sc[nj][1] - m0);
            const float p2 = __expf(sc[nj][2] - m1);
            const float p3 = __expf(sc[nj][3] - m1);
            s0 += p0 + p1;  s1 += p2 + p3;
            __half2 a01 = __floats2half2_rn(p0, p1);
            __half2 a23 = __floats2half2_rn(p2, p3);
            const int kb = nj >> 1, hf = (nj & 1) * 2;
            pa[kb][hf + 0] = *(unsigned*)&a01;
            pa[kb][hf + 1] = *(unsigned*)&a23;
        }
        s0 += __shfl_xor_sync(0xffffffffu, s0, 1);
        s0 += __shfl_xor_sync(0xffffffffu, s0, 2);
        s1 += __shfl_xor_sync(0xffffffffu, s1, 1);
        s1 += __shfl_xor_sync(0xffffffffu, s1, 2);
        l0 = l0 * f0 + s0;
        l1 = l1 * f1 + s1;
#pragma unroll
        for (int nt = 0; nt < 16; nt++) {
            o[nt][0] *= f0; o[nt][1] *= f0;
            o[nt][2] *= f1; o[nt][3] *= f1;
        }

#pragma unroll
        for (int kb = 0; kb < 4; kb++) {
#pragma unroll
            for (int ng = 0; ng < 8; ng++) {
                const unsigned voff =
                    (unsigned)((kb * 16 + (mat & 1) * 8 + lm7) * ASD + ng * 16 + (mat >> 1) * 8) * 2u;
                unsigned v4[4];
                ldsm_x4_t(v4, OVF + smb + voff);
                mma_f16(o[2 * ng],     pa[kb], v4);
                mma_f16(o[2 * ng + 1], pa[kb], v4 + 2);
            }
        }

        __syncthreads();
        if (kt + 2 < nkt) {
            kv_fill(smb + 2 * QARR_B + s * KVSTAGE_B, qh, ql, vf, b, kt + 2, kvh, tid);
        }
        cpa_commit();
    }

    const float i0 = 1.0f / l0, i1 = 1.0f / l1;
    const size_t row0 = (size_t)(b * SEQ + qr0 + warp * 16 + g);
    const size_t row1 = row0 + 8;
#pragma unroll
    for (int nt = 0; nt < 16; nt++) {
        const int col = h * HDIM + nt * 8 + tq * 2;
        __half2 v01 = __floats2half2_rn(o[nt][0] * i0, o[nt][1] * i0);
        __half2 v23 = __floats2half2_rn(o[nt][2] * i1, o[nt][3] * i1);
        *(unsigned*)&oh[row0 * HIDN + col] = *(unsigned*)&v01;
        *(unsigned*)&oh[row1 * HIDN + col] = *(unsigned*)&v23;
    }
}

// ---------------------------------------------------------------------------
extern "C" void kernel_launch(void* const* d_in, const int* in_sizes, int n_in,
                              void* d_out, int out_size)
{
    const float* hidden = (const float*)d_in[0];
    const float* wq     = (const float*)d_in[1];
    const float* wk     = (const float*)d_in[2];
    const float* wv     = (const float*)d_in[3];
    const float* wo     = (const float*)d_in[4];
    const int*   pos    = (const int*)d_in[6];
    float*       outp   = (float*)d_out;

    float* qkv;  cudaGetSymbolAddress((void**)&qkv,  g_qkv);
    __nv_bfloat16 *qkvh, *qkvl;
    __half *hidf, *wf, *woh, *ath, *vfp;
    cudaGetSymbolAddress((void**)&qkvh, g_qkvh);
    cudaGetSymbolAddress((void**)&qkvl, g_qkvl);
    cudaGetSymbolAddress((void**)&hidf, g_hidf);
    cudaGetSymbolAddress((void**)&wf,  g_wf);
    cudaGetSymbolAddress((void**)&woh, g_woh);
    cudaGetSymbolAddress((void**)&ath, g_ath);
    cudaGetSymbolAddress((void**)&vfp, g_vf);

    cudaFuncSetAttribute(gemm_f16, cudaFuncAttributeMaxDynamicSharedMemorySize, GEMMH_SMEM);
    cudaFuncSetAttribute(attn_tc,  cudaFuncAttributeMaxDynamicSharedMemorySize, ATT_SMEM);

    const int nHid = NNZ * HIDN;
    const int nWqo = HIDN * HIDN;
    const int nWkv = 1024 * HIDN;
    half_kernel<<<nHid / 1024, 256>>>(hidden, hidf, nHid);
    half_kernel<<<nWqo / 1024, 256>>>(wq, wf,                       nWqo);
    half_kernel<<<nWkv / 1024, 256>>>(wk, wf + (size_t)KOFF * HIDN, nWkv);
    half_kernel<<<nWkv / 1024, 256>>>(wv, wf + (size_t)VOFF * HIDN, nWkv);
    half_kernel<<<nWqo / 1024, 256>>>(wo, woh, nWqo);

    // Fused QKV projection (fp16 single-term): one launch, [4096 x 6144]
    gemm_f16<<<dim3(48, 32), 512, GEMMH_SMEM>>>(hidf, wf, qkv, HIDN, QKVC);

    // RoPE (+Q prescale) -> bf16 hi/lo; V -> fp16
    split_rope_kernel<<<dim3(NNZ, 48), 64>>>(qkv, pos, qkvh, qkvl, vfp);

    // Flash attention -> fp16 output
    attn_tc<<<dim3(SEQ / 128, NHEAD, NBATCH), 256, ATT_SMEM>>>(qkvh, qkvl, vfp, ath);

    // Output projection: fp16 single-term
    gemm_f16<<<dim3(32, 32), 512, GEMMH_SMEM>>>(ath, woh, outp, HIDN, HIDN);
}